// round 7
// baseline (speedup 1.0000x reference)
#include <cuda_runtime.h>
#include <cuda_bf16.h>
#include <cstdint>

// Dims: B=2, N=2048, M=1024, C=1024, H=16, D=64, HID=4096
// TQ = 4096 (B*N), TKV = 2048 (B*M)

// ---------------- scratch ----------------
__device__ __nv_bfloat16 g_w_hi[16777216];
__device__ __nv_bfloat16 g_w_lo[16777216];
__device__ __nv_bfloat16 g_lnh[4096u * 1024u], g_lnl[4096u * 1024u];
__device__ __nv_bfloat16 g_ath[4096u * 1024u], g_atl[4096u * 1024u];
__device__ __nv_bfloat16 g_cxh[2048u * 1024u], g_cxl[2048u * 1024u];
__device__ __nv_bfloat16 g_mdh[4096u * 4096u], g_mdl[4096u * 4096u];
__device__ __nv_bfloat16 g_qkv[4096u * 3072u];
__device__ __nv_bfloat16 g_q  [4096u * 1024u];
__device__ __nv_bfloat16 g_kv [2048u * 2048u];
__device__ float g_x1[4096u * 1024u];
__device__ float g_x2[4096u * 1024u];

// weight offsets (elements)
#define OFF_QKV 0
#define OFF_OS  3145728
#define OFF_Q   4194304
#define OFF_KV  5242880
#define OFF_OC  7340032
#define OFF_W1  8388608
#define OFF_W2  12582912

// ---------------- helpers ----------------
__device__ __forceinline__ uint32_t smem_u32(const void* p)
{
    uint32_t a;
    asm("{ .reg .u64 t; cvta.to.shared.u64 t, %1; cvt.u32.u64 %0, t; }" : "=r"(a) : "l"(p));
    return a;
}
__device__ __forceinline__ uint32_t packbf2(float lo, float hi)
{
    __nv_bfloat162 h = __floats2bfloat162_rn(lo, hi);
    return *reinterpret_cast<uint32_t*>(&h);
}
__device__ __forceinline__ void split_hilo(float v, __nv_bfloat16& h, __nv_bfloat16& l)
{
    h = __float2bfloat16(v);
    l = __float2bfloat16(v - __bfloat162float(h));
}
__device__ __forceinline__ void cp16(uint32_t s, const void* g)
{
    asm volatile("cp.async.cg.shared.global [%0], [%1], 16;" :: "r"(s), "l"(g));
}
__device__ __forceinline__ void cp_commit() { asm volatile("cp.async.commit_group;"); }

__device__ __forceinline__ void mma16816(float c[4], uint32_t a0, uint32_t a1,
                                         uint32_t a2, uint32_t a3,
                                         uint32_t b0, uint32_t b1)
{
    asm volatile("mma.sync.aligned.m16n8k16.row.col.f32.bf16.bf16.f32 "
                 "{%0,%1,%2,%3}, {%4,%5,%6,%7}, {%8,%9}, {%0,%1,%2,%3};"
                 : "+f"(c[0]), "+f"(c[1]), "+f"(c[2]), "+f"(c[3])
                 : "r"(a0), "r"(a1), "r"(a2), "r"(a3), "r"(b0), "r"(b1));
}
__device__ __forceinline__ void ldsm4_a(uint32_t* r, uint32_t a)
{
    asm volatile("ldmatrix.sync.aligned.m8n8.x4.shared.b16 {%0,%1,%2,%3}, [%4];"
                 : "=r"(r[0]), "=r"(r[1]), "=r"(r[2]), "=r"(r[3]) : "r"(a));
}
__device__ __forceinline__ void ldsm4t_a(uint32_t* r, uint32_t a)
{
    asm volatile("ldmatrix.sync.aligned.m8n8.x4.trans.shared.b16 {%0,%1,%2,%3}, [%4];"
                 : "=r"(r[0]), "=r"(r[1]), "=r"(r[2]), "=r"(r[3]) : "r"(a));
}

// ---------------- LayerNorm -> hi/lo ----------------
__global__ __launch_bounds__(256) void ln_hilo_kernel(const float* __restrict__ x,
                                                      __nv_bfloat16* __restrict__ hi,
                                                      __nv_bfloat16* __restrict__ lo)
{
    long long base = (long long)blockIdx.x * 1024;
    float v4[4];
    float s = 0.f, ss = 0.f;
#pragma unroll
    for (int i = 0; i < 4; i++) {
        v4[i] = x[base + threadIdx.x + i * 256];
        s += v4[i]; ss += v4[i] * v4[i];
    }
    __shared__ float shs[32], shq[32];
    for (int o = 16; o; o >>= 1) {
        s  += __shfl_xor_sync(0xffffffffu, s,  o);
        ss += __shfl_xor_sync(0xffffffffu, ss, o);
    }
    int w = threadIdx.x >> 5, l = threadIdx.x & 31;
    if (l == 0) { shs[w] = s; shq[w] = ss; }
    __syncthreads();
    if (w == 0) {
        float a = (l < 8) ? shs[l] : 0.f;
        float b = (l < 8) ? shq[l] : 0.f;
        for (int o = 4; o; o >>= 1) {
            a += __shfl_xor_sync(0xffffffffu, a, o);
            b += __shfl_xor_sync(0xffffffffu, b, o);
        }
        if (l == 0) { shs[0] = a; shq[0] = b; }
    }
    __syncthreads();
    float mean = shs[0] * (1.0f / 1024.0f);
    float var  = shq[0] * (1.0f / 1024.0f) - mean * mean;
    float inv  = rsqrtf(var + 1e-6f);
#pragma unroll
    for (int i = 0; i < 4; i++) {
        float h = (v4[i] - mean) * inv;
        __nv_bfloat16 hh, ll;
        split_hilo(h, hh, ll);
        hi[base + threadIdx.x + i * 256] = hh;
        lo[base + threadIdx.x + i * 256] = ll;
    }
}

// ---------------- fp32 -> hi/lo split ----------------
__global__ __launch_bounds__(256) void split_kernel(const float* __restrict__ x,
                                                    __nv_bfloat16* __restrict__ hi,
                                                    __nv_bfloat16* __restrict__ lo)
{
    long long i = ((long long)blockIdx.x * 256 + threadIdx.x) * 4;
    float4 v = *reinterpret_cast<const float4*>(&x[i]);
    __nv_bfloat16 h[4], l[4];
    split_hilo(v.x, h[0], l[0]); split_hilo(v.y, h[1], l[1]);
    split_hilo(v.z, h[2], l[2]); split_hilo(v.w, h[3], l[3]);
    uint2 uh, ul;
    uh.x = ((uint32_t)*(uint16_t*)&h[1] << 16) | *(uint16_t*)&h[0];
    uh.y = ((uint32_t)*(uint16_t*)&h[3] << 16) | *(uint16_t*)&h[2];
    ul.x = ((uint32_t)*(uint16_t*)&l[1] << 16) | *(uint16_t*)&l[0];
    ul.y = ((uint32_t)*(uint16_t*)&l[3] << 16) | *(uint16_t*)&l[2];
    *reinterpret_cast<uint2*>(&hi[i]) = uh;
    *reinterpret_cast<uint2*>(&lo[i]) = ul;
}

// ---------------- bf16 hi/lo 3-term GEMM, 128x256 tile, BK=32, 3-stage cp.async ----
// Warp tile 64x64 (8 warps, 2x4). MODE 0: fp32 +bias+res; 1: bf16 +bias; 2: gelu hi/lo.
template <int MODE>
__global__ __launch_bounds__(256) void gemm_bf3(
    const __nv_bfloat16* __restrict__ Ah, const __nv_bfloat16* __restrict__ Al,
    const __nv_bfloat16* __restrict__ Bh, const __nv_bfloat16* __restrict__ Bl,
    const float* __restrict__ bias, const float* __restrict__ res,
    void* __restrict__ out, void* __restrict__ out2, int K, int N)
{
    // per-stage smem (bytes):
    //   A: (128 hi | 128 lo) rows x pitch 40 bf16 -> 20480
    //   B: ( 32 hi |  32 lo) rows x pitch 264 bf16 -> 33792
    constexpr int STAGE = 54272;
    extern __shared__ __align__(16) char smem[];
    const uint32_t sbase = smem_u32(smem);

    const int tid = threadIdx.x;
    const int w = tid >> 5, lane = tid & 31;
    const int grp = lane >> 3, lrow8 = lane & 7;
    const int wr = w >> 2, wc = w & 3;              // 2x4 warps; warp tile 64x64
    const int rbase = wr * 64, cbase = wc * 64;

    const __nv_bfloat16* Abh = Ah + (long long)blockIdx.y * 128 * K;
    const __nv_bfloat16* Abl = Al + (long long)blockIdx.y * 128 * K;
    const __nv_bfloat16* Bbh = Bh + blockIdx.x * 256;
    const __nv_bfloat16* Bbl = Bl + blockIdx.x * 256;

    auto load_stage = [&](int kt, int s) {
        uint32_t sb = sbase + s * STAGE;
#pragma unroll
        for (int j = 0; j < 4; j++) {               // A: 1024 16B chunks
            int idx = tid + j * 256;
            int t = idx >> 9, within = idx & 511;
            int row = within >> 2, c = within & 3;
            const __nv_bfloat16* g = (t ? Abl : Abh) + (long long)row * K + kt * 32 + c * 8;
            cp16(sb + ((t * 128 + row) * 40 + c * 8) * 2, g);
        }
#pragma unroll
        for (int j = 0; j < 8; j++) {               // B: 2048 16B chunks
            int idx = tid + j * 256;
            int t = idx >> 10, within = idx & 1023;
            int row = within >> 5, c = within & 31;
            const __nv_bfloat16* g = (t ? Bbl : Bbh) + (long long)(kt * 32 + row) * N + c * 8;
            cp16(sb + 20480 + ((t * 32 + row) * 264 + c * 8) * 2, g);
        }
        cp_commit();
    };

    float acc[4][8][4];
#pragma unroll
    for (int i = 0; i < 4; i++)
#pragma unroll
        for (int j = 0; j < 8; j++)
#pragma unroll
            for (int e = 0; e < 4; e++) acc[i][j][e] = 0.f;

    const int KT = K >> 5;
    load_stage(0, 0);
    load_stage(1, 1);

    for (int kt = 0; kt < KT; kt++) {
        if (kt + 1 < KT) asm volatile("cp.async.wait_group 1;" ::: "memory");
        else             asm volatile("cp.async.wait_group 0;" ::: "memory");
        __syncthreads();
        if (kt + 2 < KT) load_stage(kt + 2, (kt + 2) % 3);

        const uint32_t Ab = sbase + (kt % 3) * STAGE;
        const uint32_t Bb = Ab + 20480;
#pragma unroll
        for (int kk = 0; kk < 32; kk += 16) {
            uint32_t ah[4][4], al[4][4];
#pragma unroll
            for (int i = 0; i < 4; i++) {
                uint32_t addr = Ab + ((rbase + i * 16 + (grp & 1) * 8 + lrow8) * 40 +
                                      kk + (grp & 2) * 4) * 2;
                ldsm4_a(ah[i], addr);
                ldsm4_a(al[i], addr + 128 * 40 * 2);
            }
            uint32_t bh[4][4], bl[4][4];
#pragma unroll
            for (int j = 0; j < 4; j++) {
                uint32_t addr = Bb + ((kk + (grp & 1) * 8 + lrow8) * 264 +
                                      cbase + j * 16 + (grp & 2) * 4) * 2;
                ldsm4t_a(bh[j], addr);
                ldsm4t_a(bl[j], addr + 32 * 264 * 2);
            }
#pragma unroll
            for (int i = 0; i < 4; i++)
#pragma unroll
                for (int jj = 0; jj < 8; jj++) {
                    uint32_t b0 = bh[jj >> 1][(jj & 1) * 2], b1 = bh[jj >> 1][(jj & 1) * 2 + 1];
                    mma16816(acc[i][jj], ah[i][0], ah[i][1], ah[i][2], ah[i][3], b0, b1);
                    mma16816(acc[i][jj], al[i][0], al[i][1], al[i][2], al[i][3], b0, b1);
                    uint32_t c0 = bl[jj >> 1][(jj & 1) * 2], c1 = bl[jj >> 1][(jj & 1) * 2 + 1];
                    mma16816(acc[i][jj], ah[i][0], ah[i][1], ah[i][2], ah[i][3], c0, c1);
                }
        }
    }

    // ---- epilogue straight from registers ----
    const int tr = lane >> 2, tc = (lane & 3) * 2;
#pragma unroll
    for (int i = 0; i < 4; i++) {
        long long gr0 = (long long)blockIdx.y * 128 + rbase + i * 16 + tr;
#pragma unroll
        for (int jj = 0; jj < 8; jj++) {
            int gc = blockIdx.x * 256 + cbase + jj * 8 + tc;
            float b0 = bias[gc], b1 = bias[gc + 1];
            float v0 = acc[i][jj][0] + b0, v1 = acc[i][jj][1] + b1;
            float v2 = acc[i][jj][2] + b0, v3 = acc[i][jj][3] + b1;
            if (MODE == 0) {
                float* fo = (float*)out;
                float2 r0 = *reinterpret_cast<const float2*>(&res[gr0 * N + gc]);
                float2 r1 = *reinterpret_cast<const float2*>(&res[(gr0 + 8) * N + gc]);
                *reinterpret_cast<float2*>(&fo[gr0 * N + gc]) =
                    make_float2(v0 + r0.x, v1 + r0.y);
                *reinterpret_cast<float2*>(&fo[(gr0 + 8) * N + gc]) =
                    make_float2(v2 + r1.x, v3 + r1.y);
            } else if (MODE == 1) {
                __nv_bfloat16* bo = (__nv_bfloat16*)out;
                *reinterpret_cast<uint32_t*>(&bo[gr0 * N + gc])       = packbf2(v0, v1);
                *reinterpret_cast<uint32_t*>(&bo[(gr0 + 8) * N + gc]) = packbf2(v2, v3);
            } else {
                float g[4] = { v0, v1, v2, v3 };
#pragma unroll
                for (int e = 0; e < 4; e++) {
                    float xx = g[e];
                    float tt = 0.7978845608028654f * (xx + 0.044715f * xx * xx * xx);
                    g[e] = 0.5f * xx * (1.0f + tanhf(tt));
                }
                __nv_bfloat16 h0, l0, h1, l1;
                __nv_bfloat16* ho = (__nv_bfloat16*)out;
                __nv_bfloat16* lo = (__nv_bfloat16*)out2;
                split_hilo(g[0], h0, l0); split_hilo(g[1], h1, l1);
                *reinterpret_cast<uint32_t*>(&ho[gr0 * N + gc]) =
                    ((uint32_t)*(uint16_t*)&h1 << 16) | *(uint16_t*)&h0;
                *reinterpret_cast<uint32_t*>(&lo[gr0 * N + gc]) =
                    ((uint32_t)*(uint16_t*)&l1 << 16) | *(uint16_t*)&l0;
                split_hilo(g[2], h0, l0); split_hilo(g[3], h1, l1);
                *reinterpret_cast<uint32_t*>(&ho[(gr0 + 8) * N + gc]) =
                    ((uint32_t)*(uint16_t*)&h1 << 16) | *(uint16_t*)&h0;
                *reinterpret_cast<uint32_t*>(&lo[(gr0 + 8) * N + gc]) =
                    ((uint32_t)*(uint16_t*)&l1 << 16) | *(uint16_t*)&l0;
            }
        }
    }
}

// ---------------- fused flash attention (bf16), hi/lo output ----------------
__global__ __launch_bounds__(128) void flash_kernel(
    const __nv_bfloat16* __restrict__ Qg, const __nv_bfloat16* __restrict__ Kg,
    const __nv_bfloat16* __restrict__ Vg,
    __nv_bfloat16* __restrict__ Ohi, __nv_bfloat16* __restrict__ Olo,
    int sq, int skv, int nk)
{
    constexpr int PD = 72;
    __shared__ __align__(16) __nv_bfloat16 Ks[64 * PD];
    __shared__ __align__(16) __nv_bfloat16 Vs[64 * PD];

    const int tid = threadIdx.x;
    const int w = tid >> 5, t = tid & 31;
    const int bh = blockIdx.y;
    const int b = bh >> 4, h = bh & 15;

    const long long qrow0 = (long long)b * 2048 + (long long)blockIdx.x * 128;
    const __nv_bfloat16* Qb = Qg + qrow0 * sq + h * 64;
    const __nv_bfloat16* Kb = Kg + (long long)b * nk * skv + h * 64;
    const __nv_bfloat16* Vb = Vg + (long long)b * nk * skv + h * 64;
    __nv_bfloat16* Obh = Ohi + qrow0 * 1024 + h * 64;
    __nv_bfloat16* Obl = Olo + qrow0 * 1024 + h * 64;

    const int qr = w * 32;
    const int tr = t >> 2, tc = (t & 3) * 2;

    uint32_t qa[2][4][4];
#pragma unroll
    for (int mt = 0; mt < 2; mt++) {
        int r0 = qr + mt * 16 + tr;
#pragma unroll
        for (int kc = 0; kc < 4; kc++) {
            int c0 = kc * 16 + tc;
            qa[mt][kc][0] = *reinterpret_cast<const uint32_t*>(&Qb[(long long)r0 * sq + c0]);
            qa[mt][kc][1] = *reinterpret_cast<const uint32_t*>(&Qb[(long long)(r0 + 8) * sq + c0]);
            qa[mt][kc][2] = *reinterpret_cast<const uint32_t*>(&Qb[(long long)r0 * sq + c0 + 8]);
            qa[mt][kc][3] = *reinterpret_cast<const uint32_t*>(&Qb[(long long)(r0 + 8) * sq + c0 + 8]);
        }
    }

    float o[2][8][4];
    float mrow[2][2], lrow[2][2];
#pragma unroll
    for (int mt = 0; mt < 2; mt++) {
        mrow[mt][0] = mrow[mt][1] = -1e30f;
        lrow[mt][0] = lrow[mt][1] = 0.f;
#pragma unroll
        for (int nb = 0; nb < 8; nb++)
#pragma unroll
            for (int e = 0; e < 4; e++) o[mt][nb][e] = 0.f;
    }

    const float CSC = 0.18033688011112042f;
    const int niter = nk >> 6;
    const int grp = t >> 3, lrow8 = t & 7;

    for (int kb = 0; kb < niter; kb++) {
        __syncthreads();
#pragma unroll
        for (int i = tid; i < 64 * 8; i += 128) {
            int r = i >> 3, c = i & 7;
            long long g = (long long)(kb * 64 + r) * skv + c * 8;
            *reinterpret_cast<uint4*>(&Ks[r * PD + c * 8]) =
                *reinterpret_cast<const uint4*>(&Kb[g]);
            *reinterpret_cast<uint4*>(&Vs[r * PD + c * 8]) =
                *reinterpret_cast<const uint4*>(&Vb[g]);
        }
        __syncthreads();

        float s[2][8][4];
#pragma unroll
        for (int mt = 0; mt < 2; mt++)
#pragma unroll
            for (int nb = 0; nb < 8; nb++)
#pragma unroll
                for (int e = 0; e < 4; e++) s[mt][nb][e] = 0.f;

#pragma unroll
        for (int kc = 0; kc < 4; kc++) {
#pragma unroll
            for (int nbp = 0; nbp < 4; nbp++) {
                uint32_t r[4];
                uint32_t addr = smem_u32(
                    &Ks[(nbp * 16 + (grp & 2) * 4 + lrow8) * PD + kc * 16 + (grp & 1) * 8]);
                ldsm4_a(r, addr);
#pragma unroll
                for (int mt = 0; mt < 2; mt++) {
                    mma16816(s[mt][2 * nbp],     qa[mt][kc][0], qa[mt][kc][1],
                             qa[mt][kc][2], qa[mt][kc][3], r[0], r[1]);
                    mma16816(s[mt][2 * nbp + 1], qa[mt][kc][0], qa[mt][kc][1],
                             qa[mt][kc][2], qa[mt][kc][3], r[2], r[3]);
                }
            }
        }

#pragma unroll
        for (int mt = 0; mt < 2; mt++) {
#pragma unroll
            for (int half = 0; half < 2; half++) {
                int e0 = 2 * half;
                float mx = -1e30f;
#pragma unroll
                for (int nb = 0; nb < 8; nb++)
                    mx = fmaxf(mx, fmaxf(s[mt][nb][e0], s[mt][nb][e0 + 1]));
                mx = fmaxf(mx, __shfl_xor_sync(0xffffffffu, mx, 1));
                mx = fmaxf(mx, __shfl_xor_sync(0xffffffffu, mx, 2));
                float newm = fmaxf(mrow[mt][half], mx);
                float alpha = exp2f((mrow[mt][half] - newm) * CSC);
                float sum = 0.f;
#pragma unroll
                for (int nb = 0; nb < 8; nb++) {
                    float p0 = exp2f((s[mt][nb][e0] - newm) * CSC);
                    float p1 = exp2f((s[mt][nb][e0 + 1] - newm) * CSC);
                    s[mt][nb][e0] = p0; s[mt][nb][e0 + 1] = p1;
                    sum += p0 + p1;
                }
                sum += __shfl_xor_sync(0xffffffffu, sum, 1);
                sum += __shfl_xor_sync(0xffffffffu, sum, 2);
                lrow[mt][half] = lrow[mt][half] * alpha + sum;
                mrow[mt][half] = newm;
#pragma unroll
                for (int nb = 0; nb < 8; nb++) {
                    o[mt][nb][e0]     *= alpha;
                    o[mt][nb][e0 + 1] *= alpha;
                }
            }
        }

#pragma unroll
        for (int kcP = 0; kcP < 4; kcP++) {
            uint32_t pa[2][4];
#pragma unroll
            for (int mt = 0; mt < 2; mt++) {
                pa[mt][0] = packbf2(s[mt][2 * kcP][0],     s[mt][2 * kcP][1]);
                pa[mt][1] = packbf2(s[mt][2 * kcP][2],     s[mt][2 * kcP][3]);
                pa[mt][2] = packbf2(s[mt][2 * kcP + 1][0], s[mt][2 * kcP + 1][1]);
                pa[mt][3] = packbf2(s[mt][2 * kcP + 1][2], s[mt][2 * kcP + 1][3]);
            }
#pragma unroll
            for (int nbp = 0; nbp < 4; nbp++) {
                uint32_t r[4];
                uint32_t addr = smem_u32(
                    &Vs[(kcP * 16 + (grp & 1) * 8 + lrow8) * PD + nbp * 16 + (grp & 2) * 4]);
                ldsm4t_a(r, addr);
#pragma unroll
                for (int mt = 0; mt < 2; mt++) {
                    mma16816(o[mt][2 * nbp],     pa[mt][0], pa[mt][1], pa[mt][2], pa[mt][3],
                             r[0], r[1]);
                    mma16816(o[mt][2 * nbp + 1], pa[mt][0], pa[mt][1], pa[mt][2], pa[mt][3],
                             r[2], r[3]);
                }
            }
        }
    }

#pragma unroll
    for (int mt = 0; mt < 2; mt++) {
        int r0 = qr + mt * 16 + tr;
        float inv0 = 1.0f / lrow[mt][0];
        float inv1 = 1.0f / lrow[mt][1];
#pragma unroll
        for (int nb = 0; nb < 8; nb++) {
            int col = nb * 8 + tc;
            float a0 = o[mt][nb][0] * inv0, a1 = o[mt][nb][1] * inv0;
            float b0 = o[mt][nb][2] * inv1, b1 = o[mt][nb][3] * inv1;
            __nv_bfloat16 h0, l0, h1, l1;
            split_hilo(a0, h0, l0); split_hilo(a1, h1, l1);
            *reinterpret_cast<uint32_t*>(&Obh[(long long)r0 * 1024 + col]) =
                ((uint32_t)*(uint16_t*)&h1 << 16) | *(uint16_t*)&h0;
            *reinterpret_cast<uint32_t*>(&Obl[(long long)r0 * 1024 + col]) =
                ((uint32_t)*(uint16_t*)&l1 << 16) | *(uint16_t*)&l0;
            split_hilo(b0, h0, l0); split_hilo(b1, h1, l1);
            *reinterpret_cast<uint32_t*>(&Obh[(long long)(r0 + 8) * 1024 + col]) =
                ((uint32_t)*(uint16_t*)&h1 << 16) | *(uint16_t*)&h0;
            *reinterpret_cast<uint32_t*>(&Obl[(long long)(r0 + 8) * 1024 + col]) =
                ((uint32_t)*(uint16_t*)&l1 << 16) | *(uint16_t*)&l0;
        }
    }
}

// ---------------- host ----------------
static void* devptr(const void* symbol)
{
    void* p = nullptr;
    cudaGetSymbolAddress(&p, symbol);
    return p;
}

extern "C" void kernel_launch(void* const* d_in, const int* in_sizes, int n_in,
                              void* d_out, int out_size)
{
    const float* x    = (const float*)d_in[0];
    const float* ctx  = (const float*)d_in[1];
    const float* Wqkv = (const float*)d_in[2];
    const float* bqkv = (const float*)d_in[3];
    const float* Wos  = (const float*)d_in[4];
    const float* bos  = (const float*)d_in[5];
    const float* Wq   = (const float*)d_in[6];
    const float* bq   = (const float*)d_in[7];
    const float* Wkv  = (const float*)d_in[8];
    const float* bkv  = (const float*)d_in[9];
    const float* Woc  = (const float*)d_in[10];
    const float* boc  = (const float*)d_in[11];
    const float* W1   = (const float*)d_in[12];
    const float* b1   = (const float*)d_in[13];
    const float* W2   = (const float*)d_in[14];
    const float* b2   = (const float*)d_in[15];
    float* out = (float*)d_out;

    __nv_bfloat16* wh  = (__nv_bfloat16*)devptr(g_w_hi);
    __nv_bfloat16* wl  = (__nv_bfloat16*)devptr(g_w_lo);
    __nv_bfloat16* lnh = (__nv_bfloat16*)devptr(g_lnh);
    __nv_bfloat16* lnl = (__nv_bfloat16*)devptr(g_lnl);
    __nv_bfloat16* ath = (__nv_bfloat16*)devptr(g_ath);
    __nv_bfloat16* atl = (__nv_bfloat16*)devptr(g_atl);
    __nv_bfloat16* cxh = (__nv_bfloat16*)devptr(g_cxh);
    __nv_bfloat16* cxl = (__nv_bfloat16*)devptr(g_cxl);
    __nv_bfloat16* mdh = (__nv_bfloat16*)devptr(g_mdh);
    __nv_bfloat16* mdl = (__nv_bfloat16*)devptr(g_mdl);
    __nv_bfloat16* qkv = (__nv_bfloat16*)devptr(g_qkv);
    __nv_bfloat16* q   = (__nv_bfloat16*)devptr(g_q);
    __nv_bfloat16* kv  = (__nv_bfloat16*)devptr(g_kv);
    float* x1 = (float*)devptr(g_x1);
    float* x2 = (float*)devptr(g_x2);

    const int SMEM = 3 * 54272;    // 162816 bytes
    cudaFuncSetAttribute(gemm_bf3<0>, cudaFuncAttributeMaxDynamicSharedMemorySize, SMEM);
    cudaFuncSetAttribute(gemm_bf3<1>, cudaFuncAttributeMaxDynamicSharedMemorySize, SMEM);
    cudaFuncSetAttribute(gemm_bf3<2>, cudaFuncAttributeMaxDynamicSharedMemorySize, SMEM);

    // ---- weight + ctx splits ----
    split_kernel<<<3145728 / 1024, 256>>>(Wqkv, wh + OFF_QKV, wl + OFF_QKV);
    split_kernel<<<1048576 / 1024, 256>>>(Wos,  wh + OFF_OS,  wl + OFF_OS);
    split_kernel<<<1048576 / 1024, 256>>>(Wq,   wh + OFF_Q,   wl + OFF_Q);
    split_kernel<<<2097152 / 1024, 256>>>(Wkv,  wh + OFF_KV,  wl + OFF_KV);
    split_kernel<<<1048576 / 1024, 256>>>(Woc,  wh + OFF_OC,  wl + OFF_OC);
    split_kernel<<<4194304 / 1024, 256>>>(W1,   wh + OFF_W1,  wl + OFF_W1);
    split_kernel<<<4194304 / 1024, 256>>>(W2,   wh + OFF_W2,  wl + OFF_W2);
    split_kernel<<<2097152 / 1024, 256>>>(ctx, cxh, cxl);

    // ---- self-attention ----
    ln_hilo_kernel<<<4096, 256>>>(x, lnh, lnl);
    gemm_bf3<1><<<dim3(12, 32), 256, SMEM>>>(lnh, lnl, wh + OFF_QKV, wl + OFF_QKV,
                                             bqkv, nullptr, qkv, nullptr, 1024, 3072);
    flash_kernel<<<dim3(16, 32), 128>>>(qkv, qkv + 1024, qkv + 2048, ath, atl,
                                        3072, 3072, 2048);
    gemm_bf3<0><<<dim3(4, 32), 256, SMEM>>>(ath, atl, wh + OFF_OS, wl + OFF_OS,
                                            bos, x, x1, nullptr, 1024, 1024);

    // ---- cross-attention ----
    ln_hilo_kernel<<<4096, 256>>>(x1, lnh, lnl);
    gemm_bf3<1><<<dim3(4, 32), 256, SMEM>>>(lnh, lnl, wh + OFF_Q, wl + OFF_Q,
                                            bq, nullptr, q, nullptr, 1024, 1024);
    gemm_bf3<1><<<dim3(8, 16), 256, SMEM>>>(cxh, cxl, wh + OFF_KV, wl + OFF_KV,
                                            bkv, nullptr, kv, nullptr, 1024, 2048);
    flash_kernel<<<dim3(16, 32), 128>>>(q, kv, kv + 1024, ath, atl, 1024, 2048, 1024);
    gemm_bf3<0><<<dim3(4, 32), 256, SMEM>>>(ath, atl, wh + OFF_OC, wl + OFF_OC,
                                            boc, x1, x2, nullptr, 1024, 1024);

    // ---- MLP ----
    ln_hilo_kernel<<<4096, 256>>>(x2, lnh, lnl);
    gemm_bf3<2><<<dim3(16, 32), 256, SMEM>>>(lnh, lnl, wh + OFF_W1, wl + OFF_W1,
                                             b1, nullptr, mdh, mdl, 1024, 4096);
    gemm_bf3<0><<<dim3(4, 32), 256, SMEM>>>(mdh, mdl, wh + OFF_W2, wl + OFF_W2,
                                            b2, x2, out, nullptr, 4096, 1024);
}

// round 8
// speedup vs baseline: 1.6109x; 1.6109x over previous
#include <cuda_runtime.h>
#include <cuda_bf16.h>
#include <cstdint>

// Dims: B=2, N=2048, M=1024, C=1024, H=16, D=64, HID=4096
// TQ = 4096 (B*N), TKV = 2048 (B*M)

// ---------------- scratch ----------------
__device__ __nv_bfloat16 g_w_hi[16777216];
__device__ __nv_bfloat16 g_w_lo[16777216];
__device__ __nv_bfloat16 g_lnh[4096u * 1024u], g_lnl[4096u * 1024u];
__device__ __nv_bfloat16 g_ath[4096u * 1024u], g_atl[4096u * 1024u];
__device__ __nv_bfloat16 g_cxh[2048u * 1024u], g_cxl[2048u * 1024u];
__device__ __nv_bfloat16 g_mdh[4096u * 4096u], g_mdl[4096u * 4096u];
__device__ __nv_bfloat16 g_qkv[4096u * 3072u];
__device__ __nv_bfloat16 g_q  [4096u * 1024u];
__device__ __nv_bfloat16 g_kv [2048u * 2048u];
__device__ float g_x1[4096u * 1024u];
__device__ float g_x2[4096u * 1024u];

// weight offsets (elements)
#define OFF_QKV 0
#define OFF_OS  3145728
#define OFF_Q   4194304
#define OFF_KV  5242880
#define OFF_OC  7340032
#define OFF_W1  8388608
#define OFF_W2  12582912

// ---------------- helpers ----------------
__device__ __forceinline__ uint32_t smem_u32(const void* p)
{
    uint32_t a;
    asm("{ .reg .u64 t; cvta.to.shared.u64 t, %1; cvt.u32.u64 %0, t; }" : "=r"(a) : "l"(p));
    return a;
}
__device__ __forceinline__ uint32_t packbf2(float lo, float hi)
{
    __nv_bfloat162 h = __floats2bfloat162_rn(lo, hi);
    return *reinterpret_cast<uint32_t*>(&h);
}
__device__ __forceinline__ void split_hilo(float v, __nv_bfloat16& h, __nv_bfloat16& l)
{
    h = __float2bfloat16(v);
    l = __float2bfloat16(v - __bfloat162float(h));
}
__device__ __forceinline__ void cp16(uint32_t s, const void* g)
{
    asm volatile("cp.async.cg.shared.global [%0], [%1], 16;" :: "r"(s), "l"(g));
}
__device__ __forceinline__ void cp_commit() { asm volatile("cp.async.commit_group;"); }

__device__ __forceinline__ void mma16816(float c[4], uint32_t a0, uint32_t a1,
                                         uint32_t a2, uint32_t a3,
                                         uint32_t b0, uint32_t b1)
{
    asm volatile("mma.sync.aligned.m16n8k16.row.col.f32.bf16.bf16.f32 "
                 "{%0,%1,%2,%3}, {%4,%5,%6,%7}, {%8,%9}, {%0,%1,%2,%3};"
                 : "+f"(c[0]), "+f"(c[1]), "+f"(c[2]), "+f"(c[3])
                 : "r"(a0), "r"(a1), "r"(a2), "r"(a3), "r"(b0), "r"(b1));
}
__device__ __forceinline__ void ldsm4_a(uint32_t* r, uint32_t a)
{
    asm volatile("ldmatrix.sync.aligned.m8n8.x4.shared.b16 {%0,%1,%2,%3}, [%4];"
                 : "=r"(r[0]), "=r"(r[1]), "=r"(r[2]), "=r"(r[3]) : "r"(a));
}
__device__ __forceinline__ void ldsm4t_a(uint32_t* r, uint32_t a)
{
    asm volatile("ldmatrix.sync.aligned.m8n8.x4.trans.shared.b16 {%0,%1,%2,%3}, [%4];"
                 : "=r"(r[0]), "=r"(r[1]), "=r"(r[2]), "=r"(r[3]) : "r"(a));
}

// ---------------- LayerNorm -> hi/lo ----------------
__global__ __launch_bounds__(256) void ln_hilo_kernel(const float* __restrict__ x,
                                                      __nv_bfloat16* __restrict__ hi,
                                                      __nv_bfloat16* __restrict__ lo)
{
    long long base = (long long)blockIdx.x * 1024;
    float v4[4];
    float s = 0.f, ss = 0.f;
#pragma unroll
    for (int i = 0; i < 4; i++) {
        v4[i] = x[base + threadIdx.x + i * 256];
        s += v4[i]; ss += v4[i] * v4[i];
    }
    __shared__ float shs[32], shq[32];
    for (int o = 16; o; o >>= 1) {
        s  += __shfl_xor_sync(0xffffffffu, s,  o);
        ss += __shfl_xor_sync(0xffffffffu, ss, o);
    }
    int w = threadIdx.x >> 5, l = threadIdx.x & 31;
    if (l == 0) { shs[w] = s; shq[w] = ss; }
    __syncthreads();
    if (w == 0) {
        float a = (l < 8) ? shs[l] : 0.f;
        float b = (l < 8) ? shq[l] : 0.f;
        for (int o = 4; o; o >>= 1) {
            a += __shfl_xor_sync(0xffffffffu, a, o);
            b += __shfl_xor_sync(0xffffffffu, b, o);
        }
        if (l == 0) { shs[0] = a; shq[0] = b; }
    }
    __syncthreads();
    float mean = shs[0] * (1.0f / 1024.0f);
    float var  = shq[0] * (1.0f / 1024.0f) - mean * mean;
    float inv  = rsqrtf(var + 1e-6f);
#pragma unroll
    for (int i = 0; i < 4; i++) {
        float h = (v4[i] - mean) * inv;
        __nv_bfloat16 hh, ll;
        split_hilo(h, hh, ll);
        hi[base + threadIdx.x + i * 256] = hh;
        lo[base + threadIdx.x + i * 256] = ll;
    }
}

// ---------------- fp32 -> hi/lo split ----------------
__global__ __launch_bounds__(256) void split_kernel(const float* __restrict__ x,
                                                    __nv_bfloat16* __restrict__ hi,
                                                    __nv_bfloat16* __restrict__ lo)
{
    long long i = ((long long)blockIdx.x * 256 + threadIdx.x) * 4;
    float4 v = *reinterpret_cast<const float4*>(&x[i]);
    __nv_bfloat16 h[4], l[4];
    split_hilo(v.x, h[0], l[0]); split_hilo(v.y, h[1], l[1]);
    split_hilo(v.z, h[2], l[2]); split_hilo(v.w, h[3], l[3]);
    uint2 uh, ul;
    uh.x = ((uint32_t)*(uint16_t*)&h[1] << 16) | *(uint16_t*)&h[0];
    uh.y = ((uint32_t)*(uint16_t*)&h[3] << 16) | *(uint16_t*)&h[2];
    ul.x = ((uint32_t)*(uint16_t*)&l[1] << 16) | *(uint16_t*)&l[0];
    ul.y = ((uint32_t)*(uint16_t*)&l[3] << 16) | *(uint16_t*)&l[2];
    *reinterpret_cast<uint2*>(&hi[i]) = uh;
    *reinterpret_cast<uint2*>(&lo[i]) = ul;
}

// ---------------- bf16 hi/lo 3-term GEMM ----------------
// Block tile 128x256, BK=32, 3-stage cp.async, 512 threads, warp tile 32x64.
// MODE 0: fp32 out = acc+bias+res; 1: bf16 out = acc+bias; 2: gelu hi/lo out.
template <int MODE>
__global__ __launch_bounds__(512) void gemm_bf3(
    const __nv_bfloat16* __restrict__ Ah, const __nv_bfloat16* __restrict__ Al,
    const __nv_bfloat16* __restrict__ Bh, const __nv_bfloat16* __restrict__ Bl,
    const float* __restrict__ bias, const float* __restrict__ res,
    void* __restrict__ out, void* __restrict__ out2, int K, int N)
{
    // per-stage smem (bytes):
    //   A: (128 hi | 128 lo) rows x pitch 40 bf16 -> 20480
    //   B: ( 32 hi |  32 lo) rows x pitch 264 bf16 -> 33792
    constexpr int STAGE = 54272;
    extern __shared__ __align__(16) char smem[];
    const uint32_t sbase = smem_u32(smem);

    const int tid = threadIdx.x;
    const int w = tid >> 5, lane = tid & 31;
    const int grp = lane >> 3, lrow8 = lane & 7;
    const int wr = w >> 2, wc = w & 3;              // 4x4 warps; warp tile 32x64
    const int rbase = wr * 32, cbase = wc * 64;

    const __nv_bfloat16* Abh = Ah + (long long)blockIdx.y * 128 * K;
    const __nv_bfloat16* Abl = Al + (long long)blockIdx.y * 128 * K;
    const __nv_bfloat16* Bbh = Bh + blockIdx.x * 256;
    const __nv_bfloat16* Bbl = Bl + blockIdx.x * 256;

    auto load_stage = [&](int kt, int s) {
        uint32_t sb = sbase + s * STAGE;
#pragma unroll
        for (int j = 0; j < 2; j++) {               // A: 1024 16B chunks
            int idx = tid + j * 512;
            int t = idx >> 9, within = idx & 511;
            int row = within >> 2, c = within & 3;
            const __nv_bfloat16* g = (t ? Abl : Abh) + (long long)row * K + kt * 32 + c * 8;
            cp16(sb + ((t * 128 + row) * 40 + c * 8) * 2, g);
        }
#pragma unroll
        for (int j = 0; j < 4; j++) {               // B: 2048 16B chunks
            int idx = tid + j * 512;
            int t = idx >> 10, within = idx & 1023;
            int row = within >> 5, c = within & 31;
            const __nv_bfloat16* g = (t ? Bbl : Bbh) + (long long)(kt * 32 + row) * N + c * 8;
            cp16(sb + 20480 + ((t * 32 + row) * 264 + c * 8) * 2, g);
        }
        cp_commit();
    };

    float acc[2][8][4];
#pragma unroll
    for (int i = 0; i < 2; i++)
#pragma unroll
        for (int j = 0; j < 8; j++)
#pragma unroll
            for (int e = 0; e < 4; e++) acc[i][j][e] = 0.f;

    const int KT = K >> 5;
    load_stage(0, 0);
    load_stage(1, 1);

    for (int kt = 0; kt < KT; kt++) {
        if (kt + 1 < KT) asm volatile("cp.async.wait_group 1;" ::: "memory");
        else             asm volatile("cp.async.wait_group 0;" ::: "memory");
        __syncthreads();
        if (kt + 2 < KT) load_stage(kt + 2, (kt + 2) % 3);

        const uint32_t Ab = sbase + (kt % 3) * STAGE;
        const uint32_t Bb = Ab + 20480;
#pragma unroll
        for (int kk = 0; kk < 32; kk += 16) {
            uint32_t ah[2][4], al[2][4];
#pragma unroll
            for (int i = 0; i < 2; i++) {
                uint32_t addr = Ab + ((rbase + i * 16 + (grp & 1) * 8 + lrow8) * 40 +
                                      kk + (grp & 2) * 4) * 2;
                ldsm4_a(ah[i], addr);
                ldsm4_a(al[i], addr + 128 * 40 * 2);
            }
            uint32_t bh[4][4], bl[4][4];
#pragma unroll
            for (int j = 0; j < 4; j++) {
                uint32_t addr = Bb + ((kk + (grp & 1) * 8 + lrow8) * 264 +
                                      cbase + j * 16 + (grp & 2) * 4) * 2;
                ldsm4t_a(bh[j], addr);
                ldsm4t_a(bl[j], addr + 32 * 264 * 2);
            }
#pragma unroll
            for (int i = 0; i < 2; i++)
#pragma unroll
                for (int jj = 0; jj < 8; jj++) {
                    uint32_t b0 = bh[jj >> 1][(jj & 1) * 2], b1 = bh[jj >> 1][(jj & 1) * 2 + 1];
                    mma16816(acc[i][jj], ah[i][0], ah[i][1], ah[i][2], ah[i][3], b0, b1);
                    mma16816(acc[i][jj], al[i][0], al[i][1], al[i][2], al[i][3], b0, b1);
                    uint32_t c0 = bl[jj >> 1][(jj & 1) * 2], c1 = bl[jj >> 1][(jj & 1) * 2 + 1];
                    mma16816(acc[i][jj], ah[i][0], ah[i][1], ah[i][2], ah[i][3], c0, c1);
                }
        }
    }

    // ---- epilogue straight from registers ----
    const int tr = lane >> 2, tc = (lane & 3) * 2;
#pragma unroll
    for (int i = 0; i < 2; i++) {
        long long gr0 = (long long)blockIdx.y * 128 + rbase + i * 16 + tr;
#pragma unroll
        for (int jj = 0; jj < 8; jj++) {
            int gc = blockIdx.x * 256 + cbase + jj * 8 + tc;
            float b0 = bias[gc], b1 = bias[gc + 1];
            float v0 = acc[i][jj][0] + b0, v1 = acc[i][jj][1] + b1;
            float v2 = acc[i][jj][2] + b0, v3 = acc[i][jj][3] + b1;
            if (MODE == 0) {
                float* fo = (float*)out;
                float2 r0 = *reinterpret_cast<const float2*>(&res[gr0 * N + gc]);
                float2 r1 = *reinterpret_cast<const float2*>(&res[(gr0 + 8) * N + gc]);
                *reinterpret_cast<float2*>(&fo[gr0 * N + gc]) =
                    make_float2(v0 + r0.x, v1 + r0.y);
                *reinterpret_cast<float2*>(&fo[(gr0 + 8) * N + gc]) =
                    make_float2(v2 + r1.x, v3 + r1.y);
            } else if (MODE == 1) {
                __nv_bfloat16* bo = (__nv_bfloat16*)out;
                *reinterpret_cast<uint32_t*>(&bo[gr0 * N + gc])       = packbf2(v0, v1);
                *reinterpret_cast<uint32_t*>(&bo[(gr0 + 8) * N + gc]) = packbf2(v2, v3);
            } else {
                float g[4] = { v0, v1, v2, v3 };
#pragma unroll
                for (int e = 0; e < 4; e++) {
                    float xx = g[e];
                    float tt = 0.7978845608028654f * (xx + 0.044715f * xx * xx * xx);
                    g[e] = 0.5f * xx * (1.0f + tanhf(tt));
                }
                __nv_bfloat16 h0, l0, h1, l1;
                __nv_bfloat16* ho = (__nv_bfloat16*)out;
                __nv_bfloat16* lo = (__nv_bfloat16*)out2;
                split_hilo(g[0], h0, l0); split_hilo(g[1], h1, l1);
                *reinterpret_cast<uint32_t*>(&ho[gr0 * N + gc]) =
                    ((uint32_t)*(uint16_t*)&h1 << 16) | *(uint16_t*)&h0;
                *reinterpret_cast<uint32_t*>(&lo[gr0 * N + gc]) =
                    ((uint32_t)*(uint16_t*)&l1 << 16) | *(uint16_t*)&l0;
                split_hilo(g[2], h0, l0); split_hilo(g[3], h1, l1);
                *reinterpret_cast<uint32_t*>(&ho[(gr0 + 8) * N + gc]) =
                    ((uint32_t)*(uint16_t*)&h1 << 16) | *(uint16_t*)&h0;
                *reinterpret_cast<uint32_t*>(&lo[(gr0 + 8) * N + gc]) =
                    ((uint32_t)*(uint16_t*)&l1 << 16) | *(uint16_t*)&l0;
            }
        }
    }
}

// ---------------- fused flash attention (bf16), hi/lo output ----------------
__global__ __launch_bounds__(128) void flash_kernel(
    const __nv_bfloat16* __restrict__ Qg, const __nv_bfloat16* __restrict__ Kg,
    const __nv_bfloat16* __restrict__ Vg,
    __nv_bfloat16* __restrict__ Ohi, __nv_bfloat16* __restrict__ Olo,
    int sq, int skv, int nk)
{
    constexpr int PD = 72;
    __shared__ __align__(16) __nv_bfloat16 Ks[64 * PD];
    __shared__ __align__(16) __nv_bfloat16 Vs[64 * PD];

    const int tid = threadIdx.x;
    const int w = tid >> 5, t = tid & 31;
    const int bh = blockIdx.y;
    const int b = bh >> 4, h = bh & 15;

    const long long qrow0 = (long long)b * 2048 + (long long)blockIdx.x * 128;
    const __nv_bfloat16* Qb = Qg + qrow0 * sq + h * 64;
    const __nv_bfloat16* Kb = Kg + (long long)b * nk * skv + h * 64;
    const __nv_bfloat16* Vb = Vg + (long long)b * nk * skv + h * 64;
    __nv_bfloat16* Obh = Ohi + qrow0 * 1024 + h * 64;
    __nv_bfloat16* Obl = Olo + qrow0 * 1024 + h * 64;

    const int qr = w * 32;
    const int tr = t >> 2, tc = (t & 3) * 2;

    uint32_t qa[2][4][4];
#pragma unroll
    for (int mt = 0; mt < 2; mt++) {
        int r0 = qr + mt * 16 + tr;
#pragma unroll
        for (int kc = 0; kc < 4; kc++) {
            int c0 = kc * 16 + tc;
            qa[mt][kc][0] = *reinterpret_cast<const uint32_t*>(&Qb[(long long)r0 * sq + c0]);
            qa[mt][kc][1] = *reinterpret_cast<const uint32_t*>(&Qb[(long long)(r0 + 8) * sq + c0]);
            qa[mt][kc][2] = *reinterpret_cast<const uint32_t*>(&Qb[(long long)r0 * sq + c0 + 8]);
            qa[mt][kc][3] = *reinterpret_cast<const uint32_t*>(&Qb[(long long)(r0 + 8) * sq + c0 + 8]);
        }
    }

    float o[2][8][4];
    float mrow[2][2], lrow[2][2];
#pragma unroll
    for (int mt = 0; mt < 2; mt++) {
        mrow[mt][0] = mrow[mt][1] = -1e30f;
        lrow[mt][0] = lrow[mt][1] = 0.f;
#pragma unroll
        for (int nb = 0; nb < 8; nb++)
#pragma unroll
            for (int e = 0; e < 4; e++) o[mt][nb][e] = 0.f;
    }

    const float CSC = 0.18033688011112042f;
    const int niter = nk >> 6;
    const int grp = t >> 3, lrow8 = t & 7;

    for (int kb = 0; kb < niter; kb++) {
        __syncthreads();
#pragma unroll
        for (int i = tid; i < 64 * 8; i += 128) {
            int r = i >> 3, c = i & 7;
            long long g = (long long)(kb * 64 + r) * skv + c * 8;
            *reinterpret_cast<uint4*>(&Ks[r * PD + c * 8]) =
                *reinterpret_cast<const uint4*>(&Kb[g]);
            *reinterpret_cast<uint4*>(&Vs[r * PD + c * 8]) =
                *reinterpret_cast<const uint4*>(&Vb[g]);
        }
        __syncthreads();

        float s[2][8][4];
#pragma unroll
        for (int mt = 0; mt < 2; mt++)
#pragma unroll
            for (int nb = 0; nb < 8; nb++)
#pragma unroll
                for (int e = 0; e < 4; e++) s[mt][nb][e] = 0.f;

#pragma unroll
        for (int kc = 0; kc < 4; kc++) {
#pragma unroll
            for (int nbp = 0; nbp < 4; nbp++) {
                uint32_t r[4];
                uint32_t addr = smem_u32(
                    &Ks[(nbp * 16 + (grp & 2) * 4 + lrow8) * PD + kc * 16 + (grp & 1) * 8]);
                ldsm4_a(r, addr);
#pragma unroll
                for (int mt = 0; mt < 2; mt++) {
                    mma16816(s[mt][2 * nbp],     qa[mt][kc][0], qa[mt][kc][1],
                             qa[mt][kc][2], qa[mt][kc][3], r[0], r[1]);
                    mma16816(s[mt][2 * nbp + 1], qa[mt][kc][0], qa[mt][kc][1],
                             qa[mt][kc][2], qa[mt][kc][3], r[2], r[3]);
                }
            }
        }

#pragma unroll
        for (int mt = 0; mt < 2; mt++) {
#pragma unroll
            for (int half = 0; half < 2; half++) {
                int e0 = 2 * half;
                float mx = -1e30f;
#pragma unroll
                for (int nb = 0; nb < 8; nb++)
                    mx = fmaxf(mx, fmaxf(s[mt][nb][e0], s[mt][nb][e0 + 1]));
                mx = fmaxf(mx, __shfl_xor_sync(0xffffffffu, mx, 1));
                mx = fmaxf(mx, __shfl_xor_sync(0xffffffffu, mx, 2));
                float newm = fmaxf(mrow[mt][half], mx);
                float alpha = exp2f((mrow[mt][half] - newm) * CSC);
                float sum = 0.f;
#pragma unroll
                for (int nb = 0; nb < 8; nb++) {
                    float p0 = exp2f((s[mt][nb][e0] - newm) * CSC);
                    float p1 = exp2f((s[mt][nb][e0 + 1] - newm) * CSC);
                    s[mt][nb][e0] = p0; s[mt][nb][e0 + 1] = p1;
                    sum += p0 + p1;
                }
                sum += __shfl_xor_sync(0xffffffffu, sum, 1);
                sum += __shfl_xor_sync(0xffffffffu, sum, 2);
                lrow[mt][half] = lrow[mt][half] * alpha + sum;
                mrow[mt][half] = newm;
#pragma unroll
                for (int nb = 0; nb < 8; nb++) {
                    o[mt][nb][e0]     *= alpha;
                    o[mt][nb][e0 + 1] *= alpha;
                }
            }
        }

#pragma unroll
        for (int kcP = 0; kcP < 4; kcP++) {
            uint32_t pa[2][4];
#pragma unroll
            for (int mt = 0; mt < 2; mt++) {
                pa[mt][0] = packbf2(s[mt][2 * kcP][0],     s[mt][2 * kcP][1]);
                pa[mt][1] = packbf2(s[mt][2 * kcP][2],     s[mt][2 * kcP][3]);
                pa[mt][2] = packbf2(s[mt][2 * kcP + 1][0], s[mt][2 * kcP + 1][1]);
                pa[mt][3] = packbf2(s[mt][2 * kcP + 1][2], s[mt][2 * kcP + 1][3]);
            }
#pragma unroll
            for (int nbp = 0; nbp < 4; nbp++) {
                uint32_t r[4];
                uint32_t addr = smem_u32(
                    &Vs[(kcP * 16 + (grp & 1) * 8 + lrow8) * PD + nbp * 16 + (grp & 2) * 4]);
                ldsm4t_a(r, addr);
#pragma unroll
                for (int mt = 0; mt < 2; mt++) {
                    mma16816(o[mt][2 * nbp],     pa[mt][0], pa[mt][1], pa[mt][2], pa[mt][3],
                             r[0], r[1]);
                    mma16816(o[mt][2 * nbp + 1], pa[mt][0], pa[mt][1], pa[mt][2], pa[mt][3],
                             r[2], r[3]);
                }
            }
        }
    }

#pragma unroll
    for (int mt = 0; mt < 2; mt++) {
        int r0 = qr + mt * 16 + tr;
        float inv0 = 1.0f / lrow[mt][0];
        float inv1 = 1.0f / lrow[mt][1];
#pragma unroll
        for (int nb = 0; nb < 8; nb++) {
            int col = nb * 8 + tc;
            float a0 = o[mt][nb][0] * inv0, a1 = o[mt][nb][1] * inv0;
            float b0 = o[mt][nb][2] * inv1, b1 = o[mt][nb][3] * inv1;
            __nv_bfloat16 h0, l0, h1, l1;
            split_hilo(a0, h0, l0); split_hilo(a1, h1, l1);
            *reinterpret_cast<uint32_t*>(&Obh[(long long)r0 * 1024 + col]) =
                ((uint32_t)*(uint16_t*)&h1 << 16) | *(uint16_t*)&h0;
            *reinterpret_cast<uint32_t*>(&Obl[(long long)r0 * 1024 + col]) =
                ((uint32_t)*(uint16_t*)&l1 << 16) | *(uint16_t*)&l0;
            split_hilo(b0, h0, l0); split_hilo(b1, h1, l1);
            *reinterpret_cast<uint32_t*>(&Obh[(long long)(r0 + 8) * 1024 + col]) =
                ((uint32_t)*(uint16_t*)&h1 << 16) | *(uint16_t*)&h0;
            *reinterpret_cast<uint32_t*>(&Obl[(long long)(r0 + 8) * 1024 + col]) =
                ((uint32_t)*(uint16_t*)&l1 << 16) | *(uint16_t*)&l0;
        }
    }
}

// ---------------- host ----------------
static void* devptr(const void* symbol)
{
    void* p = nullptr;
    cudaGetSymbolAddress(&p, symbol);
    return p;
}

extern "C" void kernel_launch(void* const* d_in, const int* in_sizes, int n_in,
                              void* d_out, int out_size)
{
    const float* x    = (const float*)d_in[0];
    const float* ctx  = (const float*)d_in[1];
    const float* Wqkv = (const float*)d_in[2];
    const float* bqkv = (const float*)d_in[3];
    const float* Wos  = (const float*)d_in[4];
    const float* bos  = (const float*)d_in[5];
    const float* Wq   = (const float*)d_in[6];
    const float* bq   = (const float*)d_in[7];
    const float* Wkv  = (const float*)d_in[8];
    const float* bkv  = (const float*)d_in[9];
    const float* Woc  = (const float*)d_in[10];
    const float* boc  = (const float*)d_in[11];
    const float* W1   = (const float*)d_in[12];
    const float* b1   = (const float*)d_in[13];
    const float* W2   = (const float*)d_in[14];
    const float* b2   = (const float*)d_in[15];
    float* out = (float*)d_out;

    __nv_bfloat16* wh  = (__nv_bfloat16*)devptr(g_w_hi);
    __nv_bfloat16* wl  = (__nv_bfloat16*)devptr(g_w_lo);
    __nv_bfloat16* lnh = (__nv_bfloat16*)devptr(g_lnh);
    __nv_bfloat16* lnl = (__nv_bfloat16*)devptr(g_lnl);
    __nv_bfloat16* ath = (__nv_bfloat16*)devptr(g_ath);
    __nv_bfloat16* atl = (__nv_bfloat16*)devptr(g_atl);
    __nv_bfloat16* cxh = (__nv_bfloat16*)devptr(g_cxh);
    __nv_bfloat16* cxl = (__nv_bfloat16*)devptr(g_cxl);
    __nv_bfloat16* mdh = (__nv_bfloat16*)devptr(g_mdh);
    __nv_bfloat16* mdl = (__nv_bfloat16*)devptr(g_mdl);
    __nv_bfloat16* qkv = (__nv_bfloat16*)devptr(g_qkv);
    __nv_bfloat16* q   = (__nv_bfloat16*)devptr(g_q);
    __nv_bfloat16* kv  = (__nv_bfloat16*)devptr(g_kv);
    float* x1 = (float*)devptr(g_x1);
    float* x2 = (float*)devptr(g_x2);

    const int SMEM = 3 * 54272;    // 162816 bytes
    cudaFuncSetAttribute(gemm_bf3<0>, cudaFuncAttributeMaxDynamicSharedMemorySize, SMEM);
    cudaFuncSetAttribute(gemm_bf3<1>, cudaFuncAttributeMaxDynamicSharedMemorySize, SMEM);
    cudaFuncSetAttribute(gemm_bf3<2>, cudaFuncAttributeMaxDynamicSharedMemorySize, SMEM);

    // ---- weight + ctx splits ----
    split_kernel<<<3145728 / 1024, 256>>>(Wqkv, wh + OFF_QKV, wl + OFF_QKV);
    split_kernel<<<1048576 / 1024, 256>>>(Wos,  wh + OFF_OS,  wl + OFF_OS);
    split_kernel<<<1048576 / 1024, 256>>>(Wq,   wh + OFF_Q,   wl + OFF_Q);
    split_kernel<<<2097152 / 1024, 256>>>(Wkv,  wh + OFF_KV,  wl + OFF_KV);
    split_kernel<<<1048576 / 1024, 256>>>(Woc,  wh + OFF_OC,  wl + OFF_OC);
    split_kernel<<<4194304 / 1024, 256>>>(W1,   wh + OFF_W1,  wl + OFF_W1);
    split_kernel<<<4194304 / 1024, 256>>>(W2,   wh + OFF_W2,  wl + OFF_W2);
    split_kernel<<<2097152 / 1024, 256>>>(ctx, cxh, cxl);

    // ---- self-attention ----
    ln_hilo_kernel<<<4096, 256>>>(x, lnh, lnl);
    gemm_bf3<1><<<dim3(12, 32), 512, SMEM>>>(lnh, lnl, wh + OFF_QKV, wl + OFF_QKV,
                                             bqkv, nullptr, qkv, nullptr, 1024, 3072);
    flash_kernel<<<dim3(16, 32), 128>>>(qkv, qkv + 1024, qkv + 2048, ath, atl,
                                        3072, 3072, 2048);
    gemm_bf3<0><<<dim3(4, 32), 512, SMEM>>>(ath, atl, wh + OFF_OS, wl + OFF_OS,
                                            bos, x, x1, nullptr, 1024, 1024);

    // ---- cross-attention ----
    ln_hilo_kernel<<<4096, 256>>>(x1, lnh, lnl);
    gemm_bf3<1><<<dim3(4, 32), 512, SMEM>>>(lnh, lnl, wh + OFF_Q, wl + OFF_Q,
                                            bq, nullptr, q, nullptr, 1024, 1024);
    gemm_bf3<1><<<dim3(8, 16), 512, SMEM>>>(cxh, cxl, wh + OFF_KV, wl + OFF_KV,
                                            bkv, nullptr, kv, nullptr, 1024, 2048);
    flash_kernel<<<dim3(16, 32), 128>>>(q, kv, kv + 1024, ath, atl, 1024, 2048, 1024);
    gemm_bf3<0><<<dim3(4, 32), 512, SMEM>>>(ath, atl, wh + OFF_OC, wl + OFF_OC,
                                            boc, x1, x2, nullptr, 1024, 1024);

    // ---- MLP ----
    ln_hilo_kernel<<<4096, 256>>>(x2, lnh, lnl);
    gemm_bf3<2><<<dim3(16, 32), 512, SMEM>>>(lnh, lnl, wh + OFF_W1, wl + OFF_W1,
                                             b1, nullptr, mdh, mdl, 1024, 4096);
    gemm_bf3<0><<<dim3(4, 32), 512, SMEM>>>(mdh, mdl, wh + OFF_W2, wl + OFF_W2,
                                            b2, x2, out, nullptr, 4096, 1024);
}

// round 9
// speedup vs baseline: 1.6588x; 1.0297x over previous
#include <cuda_runtime.h>
#include <cuda_bf16.h>
#include <cstdint>

// Dims: B=2, N=2048, M=1024, C=1024, H=16, D=64, HID=4096
// TQ = 4096 (B*N), TKV = 2048 (B*M)

// ---------------- scratch ----------------
__device__ __nv_bfloat16 g_w_hi[16777216];
__device__ __nv_bfloat16 g_w_lo[16777216];
__device__ __nv_bfloat16 g_lnh[4096u * 1024u], g_lnl[4096u * 1024u];
__device__ __nv_bfloat16 g_ath[4096u * 1024u], g_atl[4096u * 1024u];
__device__ __nv_bfloat16 g_cxh[2048u * 1024u], g_cxl[2048u * 1024u];
__device__ __nv_bfloat16 g_mdh[4096u * 4096u], g_mdl[4096u * 4096u];
__device__ __nv_bfloat16 g_qkv[4096u * 3072u];
__device__ __nv_bfloat16 g_q  [4096u * 1024u];
__device__ __nv_bfloat16 g_kv [2048u * 2048u];
__device__ float g_x1[4096u * 1024u];
__device__ float g_x2[4096u * 1024u];

// weight offsets (elements) — contiguous in launch order
#define OFF_QKV 0
#define OFF_OS  3145728
#define OFF_Q   4194304
#define OFF_KV  5242880
#define OFF_OC  7340032
#define OFF_W1  8388608
#define OFF_W2  12582912
#define W_TOTAL 16777216

// ---------------- helpers ----------------
__device__ __forceinline__ uint32_t smem_u32(const void* p)
{
    uint32_t a;
    asm("{ .reg .u64 t; cvta.to.shared.u64 t, %1; cvt.u32.u64 %0, t; }" : "=r"(a) : "l"(p));
    return a;
}
__device__ __forceinline__ uint32_t packbf2(float lo, float hi)
{
    __nv_bfloat162 h = __floats2bfloat162_rn(lo, hi);
    return *reinterpret_cast<uint32_t*>(&h);
}
__device__ __forceinline__ void split_hilo(float v, __nv_bfloat16& h, __nv_bfloat16& l)
{
    h = __float2bfloat16(v);
    l = __float2bfloat16(v - __bfloat162float(h));
}
__device__ __forceinline__ void cp16(uint32_t s, const void* g)
{
    asm volatile("cp.async.cg.shared.global [%0], [%1], 16;" :: "r"(s), "l"(g));
}
__device__ __forceinline__ void cp_commit() { asm volatile("cp.async.commit_group;"); }

__device__ __forceinline__ void mma16816(float c[4], uint32_t a0, uint32_t a1,
                                         uint32_t a2, uint32_t a3,
                                         uint32_t b0, uint32_t b1)
{
    asm volatile("mma.sync.aligned.m16n8k16.row.col.f32.bf16.bf16.f32 "
                 "{%0,%1,%2,%3}, {%4,%5,%6,%7}, {%8,%9}, {%0,%1,%2,%3};"
                 : "+f"(c[0]), "+f"(c[1]), "+f"(c[2]), "+f"(c[3])
                 : "r"(a0), "r"(a1), "r"(a2), "r"(a3), "r"(b0), "r"(b1));
}
__device__ __forceinline__ void ldsm4_a(uint32_t* r, uint32_t a)
{
    asm volatile("ldmatrix.sync.aligned.m8n8.x4.shared.b16 {%0,%1,%2,%3}, [%4];"
                 : "=r"(r[0]), "=r"(r[1]), "=r"(r[2]), "=r"(r[3]) : "r"(a));
}
__device__ __forceinline__ void ldsm4t_a(uint32_t* r, uint32_t a)
{
    asm volatile("ldmatrix.sync.aligned.m8n8.x4.trans.shared.b16 {%0,%1,%2,%3}, [%4];"
                 : "=r"(r[0]), "=r"(r[1]), "=r"(r[2]), "=r"(r[3]) : "r"(a));
}

// ---------------- LayerNorm -> hi/lo ----------------
__global__ __launch_bounds__(256) void ln_hilo_kernel(const float* __restrict__ x,
                                                      __nv_bfloat16* __restrict__ hi,
                                                      __nv_bfloat16* __restrict__ lo)
{
    long long base = (long long)blockIdx.x * 1024;
    float v4[4];
    float s = 0.f, ss = 0.f;
#pragma unroll
    for (int i = 0; i < 4; i++) {
        v4[i] = x[base + threadIdx.x + i * 256];
        s += v4[i]; ss += v4[i] * v4[i];
    }
    __shared__ float shs[32], shq[32];
    for (int o = 16; o; o >>= 1) {
        s  += __shfl_xor_sync(0xffffffffu, s,  o);
        ss += __shfl_xor_sync(0xffffffffu, ss, o);
    }
    int w = threadIdx.x >> 5, l = threadIdx.x & 31;
    if (l == 0) { shs[w] = s; shq[w] = ss; }
    __syncthreads();
    if (w == 0) {
        float a = (l < 8) ? shs[l] : 0.f;
        float b = (l < 8) ? shq[l] : 0.f;
        for (int o = 4; o; o >>= 1) {
            a += __shfl_xor_sync(0xffffffffu, a, o);
            b += __shfl_xor_sync(0xffffffffu, b, o);
        }
        if (l == 0) { shs[0] = a; shq[0] = b; }
    }
    __syncthreads();
    float mean = shs[0] * (1.0f / 1024.0f);
    float var  = shq[0] * (1.0f / 1024.0f) - mean * mean;
    float inv  = rsqrtf(var + 1e-6f);
#pragma unroll
    for (int i = 0; i < 4; i++) {
        float h = (v4[i] - mean) * inv;
        __nv_bfloat16 hh, ll;
        split_hilo(h, hh, ll);
        hi[base + threadIdx.x + i * 256] = hh;
        lo[base + threadIdx.x + i * 256] = ll;
    }
}

// ---------------- batched weight split: 7 sources -> contiguous hi/lo ----------------
__global__ __launch_bounds__(256) void wsplit_all_kernel(
    const float* __restrict__ s0, const float* __restrict__ s1,
    const float* __restrict__ s2, const float* __restrict__ s3,
    const float* __restrict__ s4, const float* __restrict__ s5,
    const float* __restrict__ s6,
    __nv_bfloat16* __restrict__ hi, __nv_bfloat16* __restrict__ lo)
{
    long long e = ((long long)blockIdx.x * 256 + threadIdx.x) * 4;
    const float* src;
    long long off;
    if      (e < OFF_OS)  { src = s0; off = 0; }
    else if (e < OFF_Q)   { src = s1; off = OFF_OS; }
    else if (e < OFF_KV)  { src = s2; off = OFF_Q; }
    else if (e < OFF_OC)  { src = s3; off = OFF_KV; }
    else if (e < OFF_W1)  { src = s4; off = OFF_OC; }
    else if (e < OFF_W2)  { src = s5; off = OFF_W1; }
    else                  { src = s6; off = OFF_W2; }
    float4 v = *reinterpret_cast<const float4*>(&src[e - off]);
    __nv_bfloat16 h[4], l[4];
    split_hilo(v.x, h[0], l[0]); split_hilo(v.y, h[1], l[1]);
    split_hilo(v.z, h[2], l[2]); split_hilo(v.w, h[3], l[3]);
    uint2 uh, ul;
    uh.x = ((uint32_t)*(uint16_t*)&h[1] << 16) | *(uint16_t*)&h[0];
    uh.y = ((uint32_t)*(uint16_t*)&h[3] << 16) | *(uint16_t*)&h[2];
    ul.x = ((uint32_t)*(uint16_t*)&l[1] << 16) | *(uint16_t*)&l[0];
    ul.y = ((uint32_t)*(uint16_t*)&l[3] << 16) | *(uint16_t*)&l[2];
    *reinterpret_cast<uint2*>(&hi[e]) = uh;
    *reinterpret_cast<uint2*>(&lo[e]) = ul;
}

// ---------------- fp32 -> hi/lo split (ctx) ----------------
__global__ __launch_bounds__(256) void split_kernel(const float* __restrict__ x,
                                                    __nv_bfloat16* __restrict__ hi,
                                                    __nv_bfloat16* __restrict__ lo)
{
    long long i = ((long long)blockIdx.x * 256 + threadIdx.x) * 4;
    float4 v = *reinterpret_cast<const float4*>(&x[i]);
    __nv_bfloat16 h[4], l[4];
    split_hilo(v.x, h[0], l[0]); split_hilo(v.y, h[1], l[1]);
    split_hilo(v.z, h[2], l[2]); split_hilo(v.w, h[3], l[3]);
    uint2 uh, ul;
    uh.x = ((uint32_t)*(uint16_t*)&h[1] << 16) | *(uint16_t*)&h[0];
    uh.y = ((uint32_t)*(uint16_t*)&h[3] << 16) | *(uint16_t*)&h[2];
    ul.x = ((uint32_t)*(uint16_t*)&l[1] << 16) | *(uint16_t*)&l[0];
    ul.y = ((uint32_t)*(uint16_t*)&l[3] << 16) | *(uint16_t*)&l[2];
    *reinterpret_cast<uint2*>(&hi[i]) = uh;
    *reinterpret_cast<uint2*>(&lo[i]) = ul;
}

// ---------------- bf16 hi/lo 3-term GEMM (unchanged from R8 win) ----------------
// Block tile 128x256, BK=32, 3-stage cp.async, 512 threads, warp tile 32x64.
template <int MODE>
__global__ __launch_bounds__(512) void gemm_bf3(
    const __nv_bfloat16* __restrict__ Ah, const __nv_bfloat16* __restrict__ Al,
    const __nv_bfloat16* __restrict__ Bh, const __nv_bfloat16* __restrict__ Bl,
    const float* __restrict__ bias, const float* __restrict__ res,
    void* __restrict__ out, void* __restrict__ out2, int K, int N)
{
    constexpr int STAGE = 54272;
    extern __shared__ __align__(16) char smem[];
    const uint32_t sbase = smem_u32(smem);

    const int tid = threadIdx.x;
    const int w = tid >> 5, lane = tid & 31;
    const int grp = lane >> 3, lrow8 = lane & 7;
    const int wr = w >> 2, wc = w & 3;
    const int rbase = wr * 32, cbase = wc * 64;

    const __nv_bfloat16* Abh = Ah + (long long)blockIdx.y * 128 * K;
    const __nv_bfloat16* Abl = Al + (long long)blockIdx.y * 128 * K;
    const __nv_bfloat16* Bbh = Bh + blockIdx.x * 256;
    const __nv_bfloat16* Bbl = Bl + blockIdx.x * 256;

    auto load_stage = [&](int kt, int s) {
        uint32_t sb = sbase + s * STAGE;
#pragma unroll
        for (int j = 0; j < 2; j++) {
            int idx = tid + j * 512;
            int t = idx >> 9, within = idx & 511;
            int row = within >> 2, c = within & 3;
            const __nv_bfloat16* g = (t ? Abl : Abh) + (long long)row * K + kt * 32 + c * 8;
            cp16(sb + ((t * 128 + row) * 40 + c * 8) * 2, g);
        }
#pragma unroll
        for (int j = 0; j < 4; j++) {
            int idx = tid + j * 512;
            int t = idx >> 10, within = idx & 1023;
            int row = within >> 5, c = within & 31;
            const __nv_bfloat16* g = (t ? Bbl : Bbh) + (long long)(kt * 32 + row) * N + c * 8;
            cp16(sb + 20480 + ((t * 32 + row) * 264 + c * 8) * 2, g);
        }
        cp_commit();
    };

    float acc[2][8][4];
#pragma unroll
    for (int i = 0; i < 2; i++)
#pragma unroll
        for (int j = 0; j < 8; j++)
#pragma unroll
            for (int e = 0; e < 4; e++) acc[i][j][e] = 0.f;

    const int KT = K >> 5;
    load_stage(0, 0);
    load_stage(1, 1);

    for (int kt = 0; kt < KT; kt++) {
        if (kt + 1 < KT) asm volatile("cp.async.wait_group 1;" ::: "memory");
        else             asm volatile("cp.async.wait_group 0;" ::: "memory");
        __syncthreads();
        if (kt + 2 < KT) load_stage(kt + 2, (kt + 2) % 3);

        const uint32_t Ab = sbase + (kt % 3) * STAGE;
        const uint32_t Bb = Ab + 20480;
#pragma unroll
        for (int kk = 0; kk < 32; kk += 16) {
            uint32_t ah[2][4], al[2][4];
#pragma unroll
            for (int i = 0; i < 2; i++) {
                uint32_t addr = Ab + ((rbase + i * 16 + (grp & 1) * 8 + lrow8) * 40 +
                                      kk + (grp & 2) * 4) * 2;
                ldsm4_a(ah[i], addr);
                ldsm4_a(al[i], addr + 128 * 40 * 2);
            }
            uint32_t bh[4][4], bl[4][4];
#pragma unroll
            for (int j = 0; j < 4; j++) {
                uint32_t addr = Bb + ((kk + (grp & 1) * 8 + lrow8) * 264 +
                                      cbase + j * 16 + (grp & 2) * 4) * 2;
                ldsm4t_a(bh[j], addr);
                ldsm4t_a(bl[j], addr + 32 * 264 * 2);
            }
#pragma unroll
            for (int i = 0; i < 2; i++)
#pragma unroll
                for (int jj = 0; jj < 8; jj++) {
                    uint32_t b0 = bh[jj >> 1][(jj & 1) * 2], b1 = bh[jj >> 1][(jj & 1) * 2 + 1];
                    mma16816(acc[i][jj], ah[i][0], ah[i][1], ah[i][2], ah[i][3], b0, b1);
                    mma16816(acc[i][jj], al[i][0], al[i][1], al[i][2], al[i][3], b0, b1);
                    uint32_t c0 = bl[jj >> 1][(jj & 1) * 2], c1 = bl[jj >> 1][(jj & 1) * 2 + 1];
                    mma16816(acc[i][jj], ah[i][0], ah[i][1], ah[i][2], ah[i][3], c0, c1);
                }
        }
    }

    const int tr = lane >> 2, tc = (lane & 3) * 2;
#pragma unroll
    for (int i = 0; i < 2; i++) {
        long long gr0 = (long long)blockIdx.y * 128 + rbase + i * 16 + tr;
#pragma unroll
        for (int jj = 0; jj < 8; jj++) {
            int gc = blockIdx.x * 256 + cbase + jj * 8 + tc;
            float b0 = bias[gc], b1 = bias[gc + 1];
            float v0 = acc[i][jj][0] + b0, v1 = acc[i][jj][1] + b1;
            float v2 = acc[i][jj][2] + b0, v3 = acc[i][jj][3] + b1;
            if (MODE == 0) {
                float* fo = (float*)out;
                float2 r0 = *reinterpret_cast<const float2*>(&res[gr0 * N + gc]);
                float2 r1 = *reinterpret_cast<const float2*>(&res[(gr0 + 8) * N + gc]);
                *reinterpret_cast<float2*>(&fo[gr0 * N + gc]) =
                    make_float2(v0 + r0.x, v1 + r0.y);
                *reinterpret_cast<float2*>(&fo[(gr0 + 8) * N + gc]) =
                    make_float2(v2 + r1.x, v3 + r1.y);
            } else if (MODE == 1) {
                __nv_bfloat16* bo = (__nv_bfloat16*)out;
                *reinterpret_cast<uint32_t*>(&bo[gr0 * N + gc])       = packbf2(v0, v1);
                *reinterpret_cast<uint32_t*>(&bo[(gr0 + 8) * N + gc]) = packbf2(v2, v3);
            } else {
                float g[4] = { v0, v1, v2, v3 };
#pragma unroll
                for (int e = 0; e < 4; e++) {
                    float xx = g[e];
                    float tt = 0.7978845608028654f * (xx + 0.044715f * xx * xx * xx);
                    g[e] = 0.5f * xx * (1.0f + tanhf(tt));
                }
                __nv_bfloat16 h0, l0, h1, l1;
                __nv_bfloat16* ho = (__nv_bfloat16*)out;
                __nv_bfloat16* lo = (__nv_bfloat16*)out2;
                split_hilo(g[0], h0, l0); split_hilo(g[1], h1, l1);
                *reinterpret_cast<uint32_t*>(&ho[gr0 * N + gc]) =
                    ((uint32_t)*(uint16_t*)&h1 << 16) | *(uint16_t*)&h0;
                *reinterpret_cast<uint32_t*>(&lo[gr0 * N + gc]) =
                    ((uint32_t)*(uint16_t*)&l1 << 16) | *(uint16_t*)&l0;
                split_hilo(g[2], h0, l0); split_hilo(g[3], h1, l1);
                *reinterpret_cast<uint32_t*>(&ho[(gr0 + 8) * N + gc]) =
                    ((uint32_t)*(uint16_t*)&h1 << 16) | *(uint16_t*)&h0;
                *reinterpret_cast<uint32_t*>(&lo[(gr0 + 8) * N + gc]) =
                    ((uint32_t)*(uint16_t*)&l1 << 16) | *(uint16_t*)&l0;
            }
        }
    }
}

// ---------------- flash attention: bf16, 3-stage cp.async KV pipeline ----------------
// Dynamic smem: 3 stages x (K 64x72 | V 64x72) bf16 = 3 x 18432 = 55296 bytes.
__global__ __launch_bounds__(128) void flash_kernel(
    const __nv_bfloat16* __restrict__ Qg, const __nv_bfloat16* __restrict__ Kg,
    const __nv_bfloat16* __restrict__ Vg,
    __nv_bfloat16* __restrict__ Ohi, __nv_bfloat16* __restrict__ Olo,
    int sq, int skv, int nk)
{
    constexpr int PD = 72;
    constexpr int STG = 2 * 64 * PD * 2;       // 18432 bytes per stage
    constexpr int VOFF = 64 * PD * 2;          // V offset within stage
    extern __shared__ __align__(16) char fsmem[];
    const uint32_t sb = smem_u32(fsmem);

    const int tid = threadIdx.x;
    const int w = tid >> 5, t = tid & 31;
    const int bh = blockIdx.y;
    const int b = bh >> 4, h = bh & 15;

    const long long qrow0 = (long long)b * 2048 + (long long)blockIdx.x * 128;
    const __nv_bfloat16* Qb = Qg + qrow0 * sq + h * 64;
    const __nv_bfloat16* Kb = Kg + (long long)b * nk * skv + h * 64;
    const __nv_bfloat16* Vb = Vg + (long long)b * nk * skv + h * 64;
    __nv_bfloat16* Obh = Ohi + qrow0 * 1024 + h * 64;
    __nv_bfloat16* Obl = Olo + qrow0 * 1024 + h * 64;

    const int qr = w * 32;
    const int tr = t >> 2, tc = (t & 3) * 2;

    uint32_t qa[2][4][4];
#pragma unroll
    for (int mt = 0; mt < 2; mt++) {
        int r0 = qr + mt * 16 + tr;
#pragma unroll
        for (int kc = 0; kc < 4; kc++) {
            int c0 = kc * 16 + tc;
            qa[mt][kc][0] = *reinterpret_cast<const uint32_t*>(&Qb[(long long)r0 * sq + c0]);
            qa[mt][kc][1] = *reinterpret_cast<const uint32_t*>(&Qb[(long long)(r0 + 8) * sq + c0]);
            qa[mt][kc][2] = *reinterpret_cast<const uint32_t*>(&Qb[(long long)r0 * sq + c0 + 8]);
            qa[mt][kc][3] = *reinterpret_cast<const uint32_t*>(&Qb[(long long)(r0 + 8) * sq + c0 + 8]);
        }
    }

    auto load_kv = [&](int kb, int s) {
        uint32_t base = sb + s * STG;
#pragma unroll
        for (int j = 0; j < 8; j++) {
            int i = tid + j * 128;
            int half = i >> 9, within = i & 511;
            int r = within >> 3, c = within & 7;
            const __nv_bfloat16* g = (half ? Vb : Kb) +
                                     (long long)(kb * 64 + r) * skv + c * 8;
            cp16(base + half * VOFF + (r * PD + c * 8) * 2, g);
        }
        cp_commit();
    };

    float o[2][8][4];
    float mrow[2][2], lrow[2][2];
#pragma unroll
    for (int mt = 0; mt < 2; mt++) {
        mrow[mt][0] = mrow[mt][1] = -1e30f;
        lrow[mt][0] = lrow[mt][1] = 0.f;
#pragma unroll
        for (int nb = 0; nb < 8; nb++)
#pragma unroll
            for (int e = 0; e < 4; e++) o[mt][nb][e] = 0.f;
    }

    const float CSC = 0.18033688011112042f;
    const int niter = nk >> 6;
    const int grp = t >> 3, lrow8 = t & 7;

    load_kv(0, 0);
    load_kv(1, 1);

    for (int kb = 0; kb < niter; kb++) {
        if (kb + 1 < niter) asm volatile("cp.async.wait_group 1;" ::: "memory");
        else                asm volatile("cp.async.wait_group 0;" ::: "memory");
        __syncthreads();
        if (kb + 2 < niter) load_kv(kb + 2, (kb + 2) % 3);

        const uint32_t Kbase = sb + (kb % 3) * STG;
        const uint32_t Vbase = Kbase + VOFF;

        float s[2][8][4];
#pragma unroll
        for (int mt = 0; mt < 2; mt++)
#pragma unroll
            for (int nb = 0; nb < 8; nb++)
#pragma unroll
                for (int e = 0; e < 4; e++) s[mt][nb][e] = 0.f;

#pragma unroll
        for (int kc = 0; kc < 4; kc++) {
#pragma unroll
            for (int nbp = 0; nbp < 4; nbp++) {
                uint32_t r[4];
                uint32_t addr = Kbase +
                    ((nbp * 16 + (grp & 2) * 4 + lrow8) * PD + kc * 16 + (grp & 1) * 8) * 2;
                ldsm4_a(r, addr);
#pragma unroll
                for (int mt = 0; mt < 2; mt++) {
                    mma16816(s[mt][2 * nbp],     qa[mt][kc][0], qa[mt][kc][1],
                             qa[mt][kc][2], qa[mt][kc][3], r[0], r[1]);
                    mma16816(s[mt][2 * nbp + 1], qa[mt][kc][0], qa[mt][kc][1],
                             qa[mt][kc][2], qa[mt][kc][3], r[2], r[3]);
                }
            }
        }

#pragma unroll
        for (int mt = 0; mt < 2; mt++) {
#pragma unroll
            for (int half = 0; half < 2; half++) {
                int e0 = 2 * half;
                float mx = -1e30f;
#pragma unroll
                for (int nb = 0; nb < 8; nb++)
                    mx = fmaxf(mx, fmaxf(s[mt][nb][e0], s[mt][nb][e0 + 1]));
                mx = fmaxf(mx, __shfl_xor_sync(0xffffffffu, mx, 1));
                mx = fmaxf(mx, __shfl_xor_sync(0xffffffffu, mx, 2));
                float newm = fmaxf(mrow[mt][half], mx);
                float alpha = exp2f((mrow[mt][half] - newm) * CSC);
                float sum = 0.f;
#pragma unroll
                for (int nb = 0; nb < 8; nb++) {
                    float p0 = exp2f((s[mt][nb][e0] - newm) * CSC);
                    float p1 = exp2f((s[mt][nb][e0 + 1] - newm) * CSC);
                    s[mt][nb][e0] = p0; s[mt][nb][e0 + 1] = p1;
                    sum += p0 + p1;
                }
                sum += __shfl_xor_sync(0xffffffffu, sum, 1);
                sum += __shfl_xor_sync(0xffffffffu, sum, 2);
                lrow[mt][half] = lrow[mt][half] * alpha + sum;
                mrow[mt][half] = newm;
#pragma unroll
                for (int nb = 0; nb < 8; nb++) {
                    o[mt][nb][e0]     *= alpha;
                    o[mt][nb][e0 + 1] *= alpha;
                }
            }
        }

#pragma unroll
        for (int kcP = 0; kcP < 4; kcP++) {
            uint32_t pa[2][4];
#pragma unroll
            for (int mt = 0; mt < 2; mt++) {
                pa[mt][0] = packbf2(s[mt][2 * kcP][0],     s[mt][2 * kcP][1]);
                pa[mt][1] = packbf2(s[mt][2 * kcP][2],     s[mt][2 * kcP][3]);
                pa[mt][2] = packbf2(s[mt][2 * kcP + 1][0], s[mt][2 * kcP + 1][1]);
                pa[mt][3] = packbf2(s[mt][2 * kcP + 1][2], s[mt][2 * kcP + 1][3]);
            }
#pragma unroll
            for (int nbp = 0; nbp < 4; nbp++) {
                uint32_t r[4];
                uint32_t addr = Vbase +
                    ((kcP * 16 + (grp & 1) * 8 + lrow8) * PD + nbp * 16 + (grp & 2) * 4) * 2;
                ldsm4t_a(r, addr);
#pragma unroll
                for (int mt = 0; mt < 2; mt++) {
                    mma16816(o[mt][2 * nbp],     pa[mt][0], pa[mt][1], pa[mt][2], pa[mt][3],
                             r[0], r[1]);
                    mma16816(o[mt][2 * nbp + 1], pa[mt][0], pa[mt][1], pa[mt][2], pa[mt][3],
                             r[2], r[3]);
                }
            }
        }
    }

#pragma unroll
    for (int mt = 0; mt < 2; mt++) {
        int r0 = qr + mt * 16 + tr;
        float inv0 = 1.0f / lrow[mt][0];
        float inv1 = 1.0f / lrow[mt][1];
#pragma unroll
        for (int nb = 0; nb < 8; nb++) {
            int col = nb * 8 + tc;
            float a0 = o[mt][nb][0] * inv0, a1 = o[mt][nb][1] * inv0;
            float b0 = o[mt][nb][2] * inv1, b1 = o[mt][nb][3] * inv1;
            __nv_bfloat16 h0, l0, h1, l1;
            split_hilo(a0, h0, l0); split_hilo(a1, h1, l1);
            *reinterpret_cast<uint32_t*>(&Obh[(long long)r0 * 1024 + col]) =
                ((uint32_t)*(uint16_t*)&h1 << 16) | *(uint16_t*)&h0;
            *reinterpret_cast<uint32_t*>(&Obl[(long long)r0 * 1024 + col]) =
                ((uint32_t)*(uint16_t*)&l1 << 16) | *(uint16_t*)&l0;
            split_hilo(b0, h0, l0); split_hilo(b1, h1, l1);
            *reinterpret_cast<uint32_t*>(&Obh[(long long)(r0 + 8) * 1024 + col]) =
                ((uint32_t)*(uint16_t*)&h1 << 16) | *(uint16_t*)&h0;
            *reinterpret_cast<uint32_t*>(&Obl[(long long)(r0 + 8) * 1024 + col]) =
                ((uint32_t)*(uint16_t*)&l1 << 16) | *(uint16_t*)&l0;
        }
    }
}

// ---------------- host ----------------
static void* devptr(const void* symbol)
{
    void* p = nullptr;
    cudaGetSymbolAddress(&p, symbol);
    return p;
}

extern "C" void kernel_launch(void* const* d_in, const int* in_sizes, int n_in,
                              void* d_out, int out_size)
{
    const float* x    = (const float*)d_in[0];
    const float* ctx  = (const float*)d_in[1];
    const float* Wqkv = (const float*)d_in[2];
    const float* bqkv = (const float*)d_in[3];
    const float* Wos  = (const float*)d_in[4];
    const float* bos  = (const float*)d_in[5];
    const float* Wq   = (const float*)d_in[6];
    const float* bq   = (const float*)d_in[7];
    const float* Wkv  = (const float*)d_in[8];
    const float* bkv  = (const float*)d_in[9];
    const float* Woc  = (const float*)d_in[10];
    const float* boc  = (const float*)d_in[11];
    const float* W1   = (const float*)d_in[12];
    const float* b1   = (const float*)d_in[13];
    const float* W2   = (const float*)d_in[14];
    const float* b2   = (const float*)d_in[15];
    float* out = (float*)d_out;

    __nv_bfloat16* wh  = (__nv_bfloat16*)devptr(g_w_hi);
    __nv_bfloat16* wl  = (__nv_bfloat16*)devptr(g_w_lo);
    __nv_bfloat16* lnh = (__nv_bfloat16*)devptr(g_lnh);
    __nv_bfloat16* lnl = (__nv_bfloat16*)devptr(g_lnl);
    __nv_bfloat16* ath = (__nv_bfloat16*)devptr(g_ath);
    __nv_bfloat16* atl = (__nv_bfloat16*)devptr(g_atl);
    __nv_bfloat16* cxh = (__nv_bfloat16*)devptr(g_cxh);
    __nv_bfloat16* cxl = (__nv_bfloat16*)devptr(g_cxl);
    __nv_bfloat16* mdh = (__nv_bfloat16*)devptr(g_mdh);
    __nv_bfloat16* mdl = (__nv_bfloat16*)devptr(g_mdl);
    __nv_bfloat16* qkv = (__nv_bfloat16*)devptr(g_qkv);
    __nv_bfloat16* q   = (__nv_bfloat16*)devptr(g_q);
    __nv_bfloat16* kv  = (__nv_bfloat16*)devptr(g_kv);
    float* x1 = (float*)devptr(g_x1);
    float* x2 = (float*)devptr(g_x2);

    const int SMEM  = 3 * 54272;   // gemm: 162816 bytes
    const int FSMEM = 3 * 18432;   // flash: 55296 bytes
    cudaFuncSetAttribute(gemm_bf3<0>, cudaFuncAttributeMaxDynamicSharedMemorySize, SMEM);
    cudaFuncSetAttribute(gemm_bf3<1>, cudaFuncAttributeMaxDynamicSharedMemorySize, SMEM);
    cudaFuncSetAttribute(gemm_bf3<2>, cudaFuncAttributeMaxDynamicSharedMemorySize, SMEM);
    cudaFuncSetAttribute(flash_kernel, cudaFuncAttributeMaxDynamicSharedMemorySize, FSMEM);

    // ---- splits ----
    wsplit_all_kernel<<<W_TOTAL / 1024, 256>>>(Wqkv, Wos, Wq, Wkv, Woc, W1, W2, wh, wl);
    split_kernel<<<2097152 / 1024, 256>>>(ctx, cxh, cxl);

    // ---- self-attention ----
    ln_hilo_kernel<<<4096, 256>>>(x, lnh, lnl);
    gemm_bf3<1><<<dim3(12, 32), 512, SMEM>>>(lnh, lnl, wh + OFF_QKV, wl + OFF_QKV,
                                             bqkv, nullptr, qkv, nullptr, 1024, 3072);
    flash_kernel<<<dim3(16, 32), 128, FSMEM>>>(qkv, qkv + 1024, qkv + 2048, ath, atl,
                                               3072, 3072, 2048);
    gemm_bf3<0><<<dim3(4, 32), 512, SMEM>>>(ath, atl, wh + OFF_OS, wl + OFF_OS,
                                            bos, x, x1, nullptr, 1024, 1024);

    // ---- cross-attention ----
    ln_hilo_kernel<<<4096, 256>>>(x1, lnh, lnl);
    gemm_bf3<1><<<dim3(4, 32), 512, SMEM>>>(lnh, lnl, wh + OFF_Q, wl + OFF_Q,
                                            bq, nullptr, q, nullptr, 1024, 1024);
    gemm_bf3<1><<<dim3(8, 16), 512, SMEM>>>(cxh, cxl, wh + OFF_KV, wl + OFF_KV,
                                            bkv, nullptr, kv, nullptr, 1024, 2048);
    flash_kernel<<<dim3(16, 32), 128, FSMEM>>>(q, kv, kv + 1024, ath, atl,
                                               1024, 2048, 1024);
    gemm_bf3<0><<<dim3(4, 32), 512, SMEM>>>(ath, atl, wh + OFF_OC, wl + OFF_OC,
                                            boc, x1, x2, nullptr, 1024, 1024);

    // ---- MLP ----
    ln_hilo_kernel<<<4096, 256>>>(x2, lnh, lnl);
    gemm_bf3<2><<<dim3(16, 32), 512, SMEM>>>(lnh, lnl, wh + OFF_W1, wl + OFF_W1,
                                             b1, nullptr, mdh, mdl, 1024, 4096);
    gemm_bf3<0><<<dim3(4, 32), 512, SMEM>>>(mdh, mdl, wh + OFF_W2, wl + OFF_W2,
                                            b2, x2, out, nullptr, 4096, 1024);
}

// round 11
// speedup vs baseline: 2.1315x; 1.2850x over previous
#include <cuda_runtime.h>
#include <cuda_fp16.h>
#include <cstdint>

// Dims: B=2, N=2048, M=1024, C=1024, H=16, D=64, HID=4096
// TQ = 4096 (B*N), TKV = 2048 (B*M)

// ---------------- scratch ----------------
__device__ __half g_w_hi[16777216];                      // weights fp16 (B operand)
__device__ __half g_lnh[4096u * 1024u], g_lnl[4096u * 1024u];
__device__ __half g_ath[4096u * 1024u], g_atl[4096u * 1024u];
__device__ __half g_cxh[2048u * 1024u], g_cxl[2048u * 1024u];
__device__ __half g_mdh[4096u * 4096u], g_mdl[4096u * 4096u];
__device__ __half g_qkv[4096u * 3072u];
__device__ __half g_q  [4096u * 1024u];
__device__ __half g_kv [2048u * 2048u];
__device__ float g_x1[4096u * 1024u];
__device__ float g_x2[4096u * 1024u];

// weight offsets (elements) — contiguous in launch order
#define OFF_QKV 0
#define OFF_OS  3145728
#define OFF_Q   4194304
#define OFF_KV  5242880
#define OFF_OC  7340032
#define OFF_W1  8388608
#define OFF_W2  12582912
#define W_TOTAL 16777216

// ---------------- helpers ----------------
__device__ __forceinline__ uint32_t smem_u32(const void* p)
{
    uint32_t a;
    asm("{ .reg .u64 t; cvta.to.shared.u64 t, %1; cvt.u32.u64 %0, t; }" : "=r"(a) : "l"(p));
    return a;
}
__device__ __forceinline__ uint32_t packh2(float lo, float hi)
{
    __half2 h = __floats2half2_rn(lo, hi);
    return *reinterpret_cast<uint32_t*>(&h);
}
__device__ __forceinline__ void split_hilo(float v, __half& h, __half& l)
{
    h = __float2half_rn(v);
    l = __float2half_rn(v - __half2float(h));
}
__device__ __forceinline__ void cp16(uint32_t s, const void* g)
{
    asm volatile("cp.async.cg.shared.global [%0], [%1], 16;" :: "r"(s), "l"(g));
}
__device__ __forceinline__ void cp_commit() { asm volatile("cp.async.commit_group;"); }

__device__ __forceinline__ void mma16816(float c[4], uint32_t a0, uint32_t a1,
                                         uint32_t a2, uint32_t a3,
                                         uint32_t b0, uint32_t b1)
{
    asm volatile("mma.sync.aligned.m16n8k16.row.col.f32.f16.f16.f32 "
                 "{%0,%1,%2,%3}, {%4,%5,%6,%7}, {%8,%9}, {%0,%1,%2,%3};"
                 : "+f"(c[0]), "+f"(c[1]), "+f"(c[2]), "+f"(c[3])
                 : "r"(a0), "r"(a1), "r"(a2), "r"(a3), "r"(b0), "r"(b1));
}
__device__ __forceinline__ void ldsm4_a(uint32_t* r, uint32_t a)
{
    asm volatile("ldmatrix.sync.aligned.m8n8.x4.shared.b16 {%0,%1,%2,%3}, [%4];"
                 : "=r"(r[0]), "=r"(r[1]), "=r"(r[2]), "=r"(r[3]) : "r"(a));
}
__device__ __forceinline__ void ldsm4t_a(uint32_t* r, uint32_t a)
{
    asm volatile("ldmatrix.sync.aligned.m8n8.x4.trans.shared.b16 {%0,%1,%2,%3}, [%4];"
                 : "=r"(r[0]), "=r"(r[1]), "=r"(r[2]), "=r"(r[3]) : "r"(a));
}

// ---------------- LayerNorm -> fp16 hi/lo ----------------
__global__ __launch_bounds__(256) void ln_hilo_kernel(const float* __restrict__ x,
                                                      __half* __restrict__ hi,
                                                      __half* __restrict__ lo)
{
    long long base = (long long)blockIdx.x * 1024;
    float v4[4];
    float s = 0.f, ss = 0.f;
#pragma unroll
    for (int i = 0; i < 4; i++) {
        v4[i] = x[base + threadIdx.x + i * 256];
        s += v4[i]; ss += v4[i] * v4[i];
    }
    __shared__ float shs[32], shq[32];
    for (int o = 16; o; o >>= 1) {
        s  += __shfl_xor_sync(0xffffffffu, s,  o);
        ss += __shfl_xor_sync(0xffffffffu, ss, o);
    }
    int w = threadIdx.x >> 5, l = threadIdx.x & 31;
    if (l == 0) { shs[w] = s; shq[w] = ss; }
    __syncthreads();
    if (w == 0) {
        float a = (l < 8) ? shs[l] : 0.f;
        float b = (l < 8) ? shq[l] : 0.f;
        for (int o = 4; o; o >>= 1) {
            a += __shfl_xor_sync(0xffffffffu, a, o);
            b += __shfl_xor_sync(0xffffffffu, b, o);
        }
        if (l == 0) { shs[0] = a; shq[0] = b; }
    }
    __syncthreads();
    float mean = shs[0] * (1.0f / 1024.0f);
    float var  = shq[0] * (1.0f / 1024.0f) - mean * mean;
    float inv  = rsqrtf(var + 1e-6f);
#pragma unroll
    for (int i = 0; i < 4; i++) {
        float h = (v4[i] - mean) * inv;
        __half hh, ll;
        split_hilo(h, hh, ll);
        hi[base + threadIdx.x + i * 256] = hh;
        lo[base + threadIdx.x + i * 256] = ll;
    }
}

// ---------------- batched weight convert: 7 fp32 sources -> contiguous fp16 ----------------
__global__ __launch_bounds__(256) void wsplit_all_kernel(
    const float* __restrict__ s0, const float* __restrict__ s1,
    const float* __restrict__ s2, const float* __restrict__ s3,
    const float* __restrict__ s4, const float* __restrict__ s5,
    const float* __restrict__ s6,
    __half* __restrict__ hi)
{
    long long e = ((long long)blockIdx.x * 256 + threadIdx.x) * 4;
    const float* src;
    long long off;
    if      (e < OFF_OS)  { src = s0; off = 0; }
    else if (e < OFF_Q)   { src = s1; off = OFF_OS; }
    else if (e < OFF_KV)  { src = s2; off = OFF_Q; }
    else if (e < OFF_OC)  { src = s3; off = OFF_KV; }
    else if (e < OFF_W1)  { src = s4; off = OFF_OC; }
    else if (e < OFF_W2)  { src = s5; off = OFF_W1; }
    else                  { src = s6; off = OFF_W2; }
    float4 v = *reinterpret_cast<const float4*>(&src[e - off]);
    uint2 uh;
    uh.x = packh2(v.x, v.y);
    uh.y = packh2(v.z, v.w);
    *reinterpret_cast<uint2*>(&hi[e]) = uh;
}

// ---------------- fp32 -> fp16 hi/lo split (ctx) ----------------
__global__ __launch_bounds__(256) void split_kernel(const float* __restrict__ x,
                                                    __half* __restrict__ hi,
                                                    __half* __restrict__ lo)
{
    long long i = ((long long)blockIdx.x * 256 + threadIdx.x) * 4;
    float4 v = *reinterpret_cast<const float4*>(&x[i]);
    __half h[4], l[4];
    split_hilo(v.x, h[0], l[0]); split_hilo(v.y, h[1], l[1]);
    split_hilo(v.z, h[2], l[2]); split_hilo(v.w, h[3], l[3]);
    uint2 uh, ul;
    uh.x = ((uint32_t)*(uint16_t*)&h[1] << 16) | *(uint16_t*)&h[0];
    uh.y = ((uint32_t)*(uint16_t*)&h[3] << 16) | *(uint16_t*)&h[2];
    ul.x = ((uint32_t)*(uint16_t*)&l[1] << 16) | *(uint16_t*)&l[0];
    ul.y = ((uint32_t)*(uint16_t*)&l[3] << 16) | *(uint16_t*)&l[2];
    *reinterpret_cast<uint2*>(&hi[i]) = uh;
    *reinterpret_cast<uint2*>(&lo[i]) = ul;
}

// ---------------- fp16 2-term GEMM ----------------
// C[M,N] = (Ah+Al) @ Bh.  Block tile 128x256, BK=32, 3-stage cp.async,
// 512 threads, warp tile 32x64.
// MODE 0: fp32 out = acc+bias+res; 1: fp16 out = acc+bias; 2: gelu fp16 hi/lo out.
template <int MODE>
__global__ __launch_bounds__(512) void gemm_f16(
    const __half* __restrict__ Ah, const __half* __restrict__ Al,
    const __half* __restrict__ Bh,
    const float* __restrict__ bias, const float* __restrict__ res,
    void* __restrict__ out, void* __restrict__ out2, int K, int N)
{
    // per-stage smem (bytes):
    //   A: (128 hi | 128 lo) rows x pitch 40 fp16 -> 20480
    //   B:  32 rows x pitch 264 fp16              -> 16896
    constexpr int STAGE = 37376;
    constexpr int BOFF  = 20480;
    extern __shared__ __align__(16) char smem[];
    const uint32_t sbase = smem_u32(smem);

    const int tid = threadIdx.x;
    const int w = tid >> 5, lane = tid & 31;
    const int grp = lane >> 3, lrow8 = lane & 7;
    const int wr = w >> 2, wc = w & 3;              // 4x4 warps; warp tile 32x64
    const int rbase = wr * 32, cbase = wc * 64;

    const __half* Abh = Ah + (long long)blockIdx.y * 128 * K;
    const __half* Abl = Al + (long long)blockIdx.y * 128 * K;
    const __half* Bbh = Bh + blockIdx.x * 256;

    auto load_stage = [&](int kt, int s) {
        uint32_t sb = sbase + s * STAGE;
#pragma unroll
        for (int j = 0; j < 2; j++) {               // A: 1024 16B chunks
            int idx = tid + j * 512;
            int t = idx >> 9, within = idx & 511;
            int row = within >> 2, c = within & 3;
            const __half* g = (t ? Abl : Abh) + (long long)row * K + kt * 32 + c * 8;
            cp16(sb + ((t * 128 + row) * 40 + c * 8) * 2, g);
        }
#pragma unroll
        for (int j = 0; j < 2; j++) {               // B: 1024 16B chunks
            int idx = tid + j * 512;
            int row = idx >> 5, c = idx & 31;
            const __half* g = Bbh + (long long)(kt * 32 + row) * N + c * 8;
            cp16(sb + BOFF + (row * 264 + c * 8) * 2, g);
        }
        cp_commit();
    };

    float acc[2][8][4];
#pragma unroll
    for (int i = 0; i < 2; i++)
#pragma unroll
        for (int j = 0; j < 8; j++)
#pragma unroll
            for (int e = 0; e < 4; e++) acc[i][j][e] = 0.f;

    const int KT = K >> 5;
    load_stage(0, 0);
    load_stage(1, 1);

    for (int kt = 0; kt < KT; kt++) {
        if (kt + 1 < KT) asm volatile("cp.async.wait_group 1;" ::: "memory");
        else             asm volatile("cp.async.wait_group 0;" ::: "memory");
        __syncthreads();
        if (kt + 2 < KT) load_stage(kt + 2, (kt + 2) % 3);

        const uint32_t Ab = sbase + (kt % 3) * STAGE;
        const uint32_t Bb = Ab + BOFF;
#pragma unroll
        for (int kk = 0; kk < 32; kk += 16) {
            uint32_t ah[2][4], al[2][4];
#pragma unroll
            for (int i = 0; i < 2; i++) {
                uint32_t addr = Ab + ((rbase + i * 16 + (grp & 1) * 8 + lrow8) * 40 +
                                      kk + (grp & 2) * 4) * 2;
                ldsm4_a(ah[i], addr);
                ldsm4_a(al[i], addr + 128 * 40 * 2);
            }
            uint32_t bh[4][4];
#pragma unroll
            for (int j = 0; j < 4; j++) {
                uint32_t addr = Bb + ((kk + (grp & 1) * 8 + lrow8) * 264 +
                                      cbase + j * 16 + (grp & 2) * 4) * 2;
                ldsm4t_a(bh[j], addr);
            }
#pragma unroll
            for (int i = 0; i < 2; i++)
#pragma unroll
                for (int jj = 0; jj < 8; jj++) {
                    uint32_t b0 = bh[jj >> 1][(jj & 1) * 2], b1 = bh[jj >> 1][(jj & 1) * 2 + 1];
                    mma16816(acc[i][jj], ah[i][0], ah[i][1], ah[i][2], ah[i][3], b0, b1);
                    mma16816(acc[i][jj], al[i][0], al[i][1], al[i][2], al[i][3], b0, b1);
                }
        }
    }

    // ---- epilogue straight from registers ----
    const int tr = lane >> 2, tc = (lane & 3) * 2;
#pragma unroll
    for (int i = 0; i < 2; i++) {
        long long gr0 = (long long)blockIdx.y * 128 + rbase + i * 16 + tr;
#pragma unroll
        for (int jj = 0; jj < 8; jj++) {
            int gc = blockIdx.x * 256 + cbase + jj * 8 + tc;
            float b0 = bias[gc], b1 = bias[gc + 1];
            float v0 = acc[i][jj][0] + b0, v1 = acc[i][jj][1] + b1;
            float v2 = acc[i][jj][2] + b0, v3 = acc[i][jj][3] + b1;
            if (MODE == 0) {
                float* fo = (float*)out;
                float2 r0 = *reinterpret_cast<const float2*>(&res[gr0 * N + gc]);
                float2 r1 = *reinterpret_cast<const float2*>(&res[(gr0 + 8) * N + gc]);
                *reinterpret_cast<float2*>(&fo[gr0 * N + gc]) =
                    make_float2(v0 + r0.x, v1 + r0.y);
                *reinterpret_cast<float2*>(&fo[(gr0 + 8) * N + gc]) =
                    make_float2(v2 + r1.x, v3 + r1.y);
            } else if (MODE == 1) {
                __half* bo = (__half*)out;
                *reinterpret_cast<uint32_t*>(&bo[gr0 * N + gc])       = packh2(v0, v1);
                *reinterpret_cast<uint32_t*>(&bo[(gr0 + 8) * N + gc]) = packh2(v2, v3);
            } else {
                float g[4] = { v0, v1, v2, v3 };
#pragma unroll
                for (int e = 0; e < 4; e++) {
                    float xx = g[e];
                    float tt = 0.7978845608028654f * (xx + 0.044715f * xx * xx * xx);
                    g[e] = 0.5f * xx * (1.0f + tanhf(tt));
                }
                __half h0, l0, h1, l1;
                __half* ho = (__half*)out;
                __half* lo = (__half*)out2;
                split_hilo(g[0], h0, l0); split_hilo(g[1], h1, l1);
                *reinterpret_cast<uint32_t*>(&ho[gr0 * N + gc]) =
                    ((uint32_t)*(uint16_t*)&h1 << 16) | *(uint16_t*)&h0;
                *reinterpret_cast<uint32_t*>(&lo[gr0 * N + gc]) =
                    ((uint32_t)*(uint16_t*)&l1 << 16) | *(uint16_t*)&l0;
                split_hilo(g[2], h0, l0); split_hilo(g[3], h1, l1);
                *reinterpret_cast<uint32_t*>(&ho[(gr0 + 8) * N + gc]) =
                    ((uint32_t)*(uint16_t*)&h1 << 16) | *(uint16_t*)&h0;
                *reinterpret_cast<uint32_t*>(&lo[(gr0 + 8) * N + gc]) =
                    ((uint32_t)*(uint16_t*)&l1 << 16) | *(uint16_t*)&l0;
            }
        }
    }
}

// ---------------- flash attention: fp16, 3-stage cp.async KV pipeline ----------------
__global__ __launch_bounds__(128) void flash_kernel(
    const __half* __restrict__ Qg, const __half* __restrict__ Kg,
    const __half* __restrict__ Vg,
    __half* __restrict__ Ohi, __half* __restrict__ Olo,
    int sq, int skv, int nk)
{
    constexpr int PD = 72;
    constexpr int STG = 2 * 64 * PD * 2;       // 18432 bytes per stage
    constexpr int VOFF = 64 * PD * 2;
    extern __shared__ __align__(16) char fsmem[];
    const uint32_t sb = smem_u32(fsmem);

    const int tid = threadIdx.x;
    const int w = tid >> 5, t = tid & 31;
    const int bh = blockIdx.y;
    const int b = bh >> 4, h = bh & 15;

    const long long qrow0 = (long long)b * 2048 + (long long)blockIdx.x * 128;
    const __half* Qb = Qg + qrow0 * sq + h * 64;
    const __half* Kb = Kg + (long long)b * nk * skv + h * 64;
    const __half* Vb = Vg + (long long)b * nk * skv + h * 64;
    __half* Obh = Ohi + qrow0 * 1024 + h * 64;
    __half* Obl = Olo + qrow0 * 1024 + h * 64;

    const int qr = w * 32;
    const int tr = t >> 2, tc = (t & 3) * 2;

    uint32_t qa[2][4][4];
#pragma unroll
    for (int mt = 0; mt < 2; mt++) {
        int r0 = qr + mt * 16 + tr;
#pragma unroll
        for (int kc = 0; kc < 4; kc++) {
            int c0 = kc * 16 + tc;
            qa[mt][kc][0] = *reinterpret_cast<const uint32_t*>(&Qb[(long long)r0 * sq + c0]);
            qa[mt][kc][1] = *reinterpret_cast<const uint32_t*>(&Qb[(long long)(r0 + 8) * sq + c0]);
            qa[mt][kc][2] = *reinterpret_cast<const uint32_t*>(&Qb[(long long)r0 * sq + c0 + 8]);
            qa[mt][kc][3] = *reinterpret_cast<const uint32_t*>(&Qb[(long long)(r0 + 8) * sq + c0 + 8]);
        }
    }

    auto load_kv = [&](int kb, int s) {
        uint32_t base = sb + s * STG;
#pragma unroll
        for (int j = 0; j < 8; j++) {
            int i = tid + j * 128;
            int half_ = i >> 9, within = i & 511;
            int r = within >> 3, c = within & 7;
            const __half* g = (half_ ? Vb : Kb) +
                              (long long)(kb * 64 + r) * skv + c * 8;
            cp16(base + half_ * VOFF + (r * PD + c * 8) * 2, g);
        }
        cp_commit();
    };

    float o[2][8][4];
    float mrow[2][2], lrow[2][2];
#pragma unroll
    for (int mt = 0; mt < 2; mt++) {
        mrow[mt][0] = mrow[mt][1] = -1e30f;
        lrow[mt][0] = lrow[mt][1] = 0.f;
#pragma unroll
        for (int nb = 0; nb < 8; nb++)
#pragma unroll
            for (int e = 0; e < 4; e++) o[mt][nb][e] = 0.f;
    }

    const float CSC = 0.18033688011112042f;     // (1/8)*log2(e)
    const int niter = nk >> 6;
    const int grp = t >> 3, lrow8 = t & 7;

    load_kv(0, 0);
    load_kv(1, 1);

    for (int kb = 0; kb < niter; kb++) {
        if (kb + 1 < niter) asm volatile("cp.async.wait_group 1;" ::: "memory");
        else                asm volatile("cp.async.wait_group 0;" ::: "memory");
        __syncthreads();
        if (kb + 2 < niter) load_kv(kb + 2, (kb + 2) % 3);

        const uint32_t Kbase = sb + (kb % 3) * STG;
        const uint32_t Vbase = Kbase + VOFF;

        float s[2][8][4];
#pragma unroll
        for (int mt = 0; mt < 2; mt++)
#pragma unroll
            for (int nb = 0; nb < 8; nb++)
#pragma unroll
                for (int e = 0; e < 4; e++) s[mt][nb][e] = 0.f;

#pragma unroll
        for (int kc = 0; kc < 4; kc++) {
#pragma unroll
            for (int nbp = 0; nbp < 4; nbp++) {
                uint32_t r[4];
                uint32_t addr = Kbase +
                    ((nbp * 16 + (grp & 2) * 4 + lrow8) * PD + kc * 16 + (grp & 1) * 8) * 2;
                ldsm4_a(r, addr);
#pragma unroll
                for (int mt = 0; mt < 2; mt++) {
                    mma16816(s[mt][2 * nbp],     qa[mt][kc][0], qa[mt][kc][1],
                             qa[mt][kc][2], qa[mt][kc][3], r[0], r[1]);
                    mma16816(s[mt][2 * nbp + 1], qa[mt][kc][0], qa[mt][kc][1],
                             qa[mt][kc][2], qa[mt][kc][3], r[2], r[3]);
                }
            }
        }

#pragma unroll
        for (int mt = 0; mt < 2; mt++) {
#pragma unroll
            for (int half_ = 0; half_ < 2; half_++) {
                int e0 = 2 * half_;
                float mx = -1e30f;
#pragma unroll
                for (int nb = 0; nb < 8; nb++)
                    mx = fmaxf(mx, fmaxf(s[mt][nb][e0], s[mt][nb][e0 + 1]));
                mx = fmaxf(mx, __shfl_xor_sync(0xffffffffu, mx, 1));
                mx = fmaxf(mx, __shfl_xor_sync(0xffffffffu, mx, 2));
                float newm = fmaxf(mrow[mt][half_], mx);
                float alpha = exp2f((mrow[mt][half_] - newm) * CSC);
                float sum = 0.f;
#pragma unroll
                for (int nb = 0; nb < 8; nb++) {
                    float p0 = exp2f((s[mt][nb][e0] - newm) * CSC);
                    float p1 = exp2f((s[mt][nb][e0 + 1] - newm) * CSC);
                    s[mt][nb][e0] = p0; s[mt][nb][e0 + 1] = p1;
                    sum += p0 + p1;
                }
                sum += __shfl_xor_sync(0xffffffffu, sum, 1);
                sum += __shfl_xor_sync(0xffffffffu, sum, 2);
                lrow[mt][half_] = lrow[mt][half_] * alpha + sum;
                mrow[mt][half_] = newm;
#pragma unroll
                for (int nb = 0; nb < 8; nb++) {
                    o[mt][nb][e0]     *= alpha;
                    o[mt][nb][e0 + 1] *= alpha;
                }
            }
        }

#pragma unroll
        for (int kcP = 0; kcP < 4; kcP++) {
            uint32_t pa[2][4];
#pragma unroll
            for (int mt = 0; mt < 2; mt++) {
                pa[mt][0] = packh2(s[mt][2 * kcP][0],     s[mt][2 * kcP][1]);
                pa[mt][1] = packh2(s[mt][2 * kcP][2],     s[mt][2 * kcP][3]);
                pa[mt][2] = packh2(s[mt][2 * kcP + 1][0], s[mt][2 * kcP + 1][1]);
                pa[mt][3] = packh2(s[mt][2 * kcP + 1][2], s[mt][2 * kcP + 1][3]);
            }
#pragma unroll
            for (int nbp = 0; nbp < 4; nbp++) {
                uint32_t r[4];
                uint32_t addr = Vbase +
                    ((kcP * 16 + (grp & 1) * 8 + lrow8) * PD + nbp * 16 + (grp & 2) * 4) * 2;
                ldsm4t_a(r, addr);
#pragma unroll
                for (int mt = 0; mt < 2; mt++) {
                    mma16816(o[mt][2 * nbp],     pa[mt][0], pa[mt][1], pa[mt][2], pa[mt][3],
                             r[0], r[1]);
                    mma16816(o[mt][2 * nbp + 1], pa[mt][0], pa[mt][1], pa[mt][2], pa[mt][3],
                             r[2], r[3]);
                }
            }
        }
    }

#pragma unroll
    for (int mt = 0; mt < 2; mt++) {
        int r0 = qr + mt * 16 + tr;
        float inv0 = 1.0f / lrow[mt][0];
        float inv1 = 1.0f / lrow[mt][1];
#pragma unroll
        for (int nb = 0; nb < 8; nb++) {
            int col = nb * 8 + tc;
            float a0 = o[mt][nb][0] * inv0, a1 = o[mt][nb][1] * inv0;
            float b0 = o[mt][nb][2] * inv1, b1 = o[mt][nb][3] * inv1;
            __half h0, l0, h1, l1;
            split_hilo(a0, h0, l0); split_hilo(a1, h1, l1);
            *reinterpret_cast<uint32_t*>(&Obh[(long long)r0 * 1024 + col]) =
                ((uint32_t)*(uint16_t*)&h1 << 16) | *(uint16_t*)&h0;
            *reinterpret_cast<uint32_t*>(&Obl[(long long)r0 * 1024 + col]) =
                ((uint32_t)*(uint16_t*)&l1 << 16) | *(uint16_t*)&l0;
            split_hilo(b0, h0, l0); split_hilo(b1, h1, l1);
            *reinterpret_cast<uint32_t*>(&Obh[(long long)(r0 + 8) * 1024 + col]) =
                ((uint32_t)*(uint16_t*)&h1 << 16) | *(uint16_t*)&h0;
            *reinterpret_cast<uint32_t*>(&Obl[(long long)(r0 + 8) * 1024 + col]) =
                ((uint32_t)*(uint16_t*)&l1 << 16) | *(uint16_t*)&l0;
        }
    }
}

// ---------------- host ----------------
static void* devptr(const void* symbol)
{
    void* p = nullptr;
    cudaGetSymbolAddress(&p, symbol);
    return p;
}

extern "C" void kernel_launch(void* const* d_in, const int* in_sizes, int n_in,
                              void* d_out, int out_size)
{
    const float* x    = (const float*)d_in[0];
    const float* ctx  = (const float*)d_in[1];
    const float* Wqkv = (const float*)d_in[2];
    const float* bqkv = (const float*)d_in[3];
    const float* Wos  = (const float*)d_in[4];
    const float* bos  = (const float*)d_in[5];
    const float* Wq   = (const float*)d_in[6];
    const float* bq   = (const float*)d_in[7];
    const float* Wkv  = (const float*)d_in[8];
    const float* bkv  = (const float*)d_in[9];
    const float* Woc  = (const float*)d_in[10];
    const float* boc  = (const float*)d_in[11];
    const float* W1   = (const float*)d_in[12];
    const float* b1   = (const float*)d_in[13];
    const float* W2   = (const float*)d_in[14];
    const float* b2   = (const float*)d_in[15];
    float* out = (float*)d_out;

    __half* wh  = (__half*)devptr(g_w_hi);
    __half* lnh = (__half*)devptr(g_lnh);
    __half* lnl = (__half*)devptr(g_lnl);
    __half* ath = (__half*)devptr(g_ath);
    __half* atl = (__half*)devptr(g_atl);
    __half* cxh = (__half*)devptr(g_cxh);
    __half* cxl = (__half*)devptr(g_cxl);
    __half* mdh = (__half*)devptr(g_mdh);
    __half* mdl = (__half*)devptr(g_mdl);
    __half* qkv = (__half*)devptr(g_qkv);
    __half* q   = (__half*)devptr(g_q);
    __half* kv  = (__half*)devptr(g_kv);
    float* x1 = (float*)devptr(g_x1);
    float* x2 = (float*)devptr(g_x2);

    const int SMEM  = 3 * 37376;   // gemm: 112128 bytes
    const int FSMEM = 3 * 18432;   // flash: 55296 bytes
    cudaFuncSetAttribute(gemm_f16<0>, cudaFuncAttributeMaxDynamicSharedMemorySize, SMEM);
    cudaFuncSetAttribute(gemm_f16<1>, cudaFuncAttributeMaxDynamicSharedMemorySize, SMEM);
    cudaFuncSetAttribute(gemm_f16<2>, cudaFuncAttributeMaxDynamicSharedMemorySize, SMEM);
    cudaFuncSetAttribute(flash_kernel, cudaFuncAttributeMaxDynamicSharedMemorySize, FSMEM);

    // ---- splits ----
    wsplit_all_kernel<<<W_TOTAL / 1024, 256>>>(Wqkv, Wos, Wq, Wkv, Woc, W1, W2, wh);
    split_kernel<<<2097152 / 1024, 256>>>(ctx, cxh, cxl);

    // ---- self-attention ----
    ln_hilo_kernel<<<4096, 256>>>(x, lnh, lnl);
    gemm_f16<1><<<dim3(12, 32), 512, SMEM>>>(lnh, lnl, wh + OFF_QKV,
                                             bqkv, nullptr, qkv, nullptr, 1024, 3072);
    flash_kernel<<<dim3(16, 32), 128, FSMEM>>>(qkv, qkv + 1024, qkv + 2048, ath, atl,
                                               3072, 3072, 2048);
    gemm_f16<0><<<dim3(4, 32), 512, SMEM>>>(ath, atl, wh + OFF_OS,
                                            bos, x, x1, nullptr, 1024, 1024);

    // ---- cross-attention ----
    ln_hilo_kernel<<<4096, 256>>>(x1, lnh, lnl);
    gemm_f16<1><<<dim3(4, 32), 512, SMEM>>>(lnh, lnl, wh + OFF_Q,
                                            bq, nullptr, q, nullptr, 1024, 1024);
    gemm_f16<1><<<dim3(8, 16), 512, SMEM>>>(cxh, cxl, wh + OFF_KV,
                                            bkv, nullptr, kv, nullptr, 1024, 2048);
    flash_kernel<<<dim3(16, 32), 128, FSMEM>>>(q, kv, kv + 1024, ath, atl,
                                               1024, 2048, 1024);
    gemm_f16<0><<<dim3(4, 32), 512, SMEM>>>(ath, atl, wh + OFF_OC,
                                            boc, x1, x2, nullptr, 1024, 1024);

    // ---- MLP ----
    ln_hilo_kernel<<<4096, 256>>>(x2, lnh, lnl);
    gemm_f16<2><<<dim3(16, 32), 512, SMEM>>>(lnh, lnl, wh + OFF_W1,
                                             b1, nullptr, mdh, mdl, 1024, 4096);
    gemm_f16<0><<<dim3(4, 32), 512, SMEM>>>(mdh, mdl, wh + OFF_W2,
                                            b2, x2, out, nullptr, 4096, 1024);
}

// round 14
// speedup vs baseline: 2.1907x; 1.0278x over previous
#include <cuda_runtime.h>
#include <cuda_fp16.h>
#include <cstdint>

// Dims: B=2, N=2048, M=1024, C=1024, H=16, D=64, HID=4096
// TQ = 4096 (B*N), TKV = 2048 (B*M)

// ---------------- scratch ----------------
__device__ __half g_w_hi[16777216];                      // weights fp16 (B operand)
__device__ __half g_lnh[4096u * 1024u], g_lnl[4096u * 1024u];
__device__ __half g_ath[4096u * 1024u], g_atl[4096u * 1024u];
__device__ __half g_cxh[2048u * 1024u], g_cxl[2048u * 1024u];
__device__ __half g_mdh[4096u * 4096u], g_mdl[4096u * 4096u];
__device__ __half g_qkv[4096u * 3072u];
__device__ __half g_q  [4096u * 1024u];
__device__ __half g_kv [2048u * 2048u];
__device__ float g_x1[4096u * 1024u];
__device__ float g_x2[4096u * 1024u];

// weight offsets (elements) — contiguous in launch order
#define OFF_QKV 0
#define OFF_OS  3145728
#define OFF_Q   4194304
#define OFF_KV  5242880
#define OFF_OC  7340032
#define OFF_W1  8388608
#define OFF_W2  12582912
#define W_TOTAL 16777216

// ---------------- helpers ----------------
__device__ __forceinline__ uint32_t smem_u32(const void* p)
{
    uint32_t a;
    asm("{ .reg .u64 t; cvta.to.shared.u64 t, %1; cvt.u32.u64 %0, t; }" : "=r"(a) : "l"(p));
    return a;
}
__device__ __forceinline__ uint32_t packh2(float lo, float hi)
{
    __half2 h = __floats2half2_rn(lo, hi);
    return *reinterpret_cast<uint32_t*>(&h);
}
__device__ __forceinline__ void split_hilo(float v, __half& h, __half& l)
{
    h = __float2half_rn(v);
    l = __float2half_rn(v - __half2float(h));
}
__device__ __forceinline__ void cp16(uint32_t s, const void* g)
{
    asm volatile("cp.async.cg.shared.global [%0], [%1], 16;" :: "r"(s), "l"(g));
}
__device__ __forceinline__ void cp_commit() { asm volatile("cp.async.commit_group;"); }

__device__ __forceinline__ void mma16816(float c[4], uint32_t a0, uint32_t a1,
                                         uint32_t a2, uint32_t a3,
                                         uint32_t b0, uint32_t b1)
{
    asm volatile("mma.sync.aligned.m16n8k16.row.col.f32.f16.f16.f32 "
                 "{%0,%1,%2,%3}, {%4,%5,%6,%7}, {%8,%9}, {%0,%1,%2,%3};"
                 : "+f"(c[0]), "+f"(c[1]), "+f"(c[2]), "+f"(c[3])
                 : "r"(a0), "r"(a1), "r"(a2), "r"(a3), "r"(b0), "r"(b1));
}
__device__ __forceinline__ void ldsm4_a(uint32_t* r, uint32_t a)
{
    asm volatile("ldmatrix.sync.aligned.m8n8.x4.shared.b16 {%0,%1,%2,%3}, [%4];"
                 : "=r"(r[0]), "=r"(r[1]), "=r"(r[2]), "=r"(r[3]) : "r"(a));
}
__device__ __forceinline__ void ldsm4t_a(uint32_t* r, uint32_t a)
{
    asm volatile("ldmatrix.sync.aligned.m8n8.x4.trans.shared.b16 {%0,%1,%2,%3}, [%4];"
                 : "=r"(r[0]), "=r"(r[1]), "=r"(r[2]), "=r"(r[3]) : "r"(a));
}

// ---------------- LayerNorm -> fp16 hi/lo ----------------
__global__ __launch_bounds__(256) void ln_hilo_kernel(const float* __restrict__ x,
                                                      __half* __restrict__ hi,
                                                      __half* __restrict__ lo)
{
    long long base = (long long)blockIdx.x * 1024;
    float v4[4];
    float s = 0.f, ss = 0.f;
#pragma unroll
    for (int i = 0; i < 4; i++) {
        v4[i] = x[base + threadIdx.x + i * 256];
        s += v4[i]; ss += v4[i] * v4[i];
    }
    __shared__ float shs[32], shq[32];
    for (int o = 16; o; o >>= 1) {
        s  += __shfl_xor_sync(0xffffffffu, s,  o);
        ss += __shfl_xor_sync(0xffffffffu, ss, o);
    }
    int w = threadIdx.x >> 5, l = threadIdx.x & 31;
    if (l == 0) { shs[w] = s; shq[w] = ss; }
    __syncthreads();
    if (w == 0) {
        float a = (l < 8) ? shs[l] : 0.f;
        float b = (l < 8) ? shq[l] : 0.f;
        for (int o = 4; o; o >>= 1) {
            a += __shfl_xor_sync(0xffffffffu, a, o);
            b += __shfl_xor_sync(0xffffffffu, b, o);
        }
        if (l == 0) { shs[0] = a; shq[0] = b; }
    }
    __syncthreads();
    float mean = shs[0] * (1.0f / 1024.0f);
    float var  = shq[0] * (1.0f / 1024.0f) - mean * mean;
    float inv  = rsqrtf(var + 1e-6f);
#pragma unroll
    for (int i = 0; i < 4; i++) {
        float h = (v4[i] - mean) * inv;
        __half hh, ll;
        split_hilo(h, hh, ll);
        hi[base + threadIdx.x + i * 256] = hh;
        lo[base + threadIdx.x + i * 256] = ll;
    }
}

// ---------------- batched weight convert: 7 fp32 sources -> contiguous fp16 ----------------
__global__ __launch_bounds__(256) void wsplit_all_kernel(
    const float* __restrict__ s0, const float* __restrict__ s1,
    const float* __restrict__ s2, const float* __restrict__ s3,
    const float* __restrict__ s4, const float* __restrict__ s5,
    const float* __restrict__ s6,
    __half* __restrict__ hi)
{
    long long e = ((long long)blockIdx.x * 256 + threadIdx.x) * 4;
    const float* src;
    long long off;
    if      (e < OFF_OS)  { src = s0; off = 0; }
    else if (e < OFF_Q)   { src = s1; off = OFF_OS; }
    else if (e < OFF_KV)  { src = s2; off = OFF_Q; }
    else if (e < OFF_OC)  { src = s3; off = OFF_KV; }
    else if (e < OFF_W1)  { src = s4; off = OFF_OC; }
    else if (e < OFF_W2)  { src = s5; off = OFF_W1; }
    else                  { src = s6; off = OFF_W2; }
    float4 v = *reinterpret_cast<const float4*>(&src[e - off]);
    uint2 uh;
    uh.x = packh2(v.x, v.y);
    uh.y = packh2(v.z, v.w);
    *reinterpret_cast<uint2*>(&hi[e]) = uh;
}

// ---------------- fp32 -> fp16 hi/lo split (ctx) ----------------
__global__ __launch_bounds__(256) void split_kernel(const float* __restrict__ x,
                                                    __half* __restrict__ hi,
                                                    __half* __restrict__ lo)
{
    long long i = ((long long)blockIdx.x * 256 + threadIdx.x) * 4;
    float4 v = *reinterpret_cast<const float4*>(&x[i]);
    __half h[4], l[4];
    split_hilo(v.x, h[0], l[0]); split_hilo(v.y, h[1], l[1]);
    split_hilo(v.z, h[2], l[2]); split_hilo(v.w, h[3], l[3]);
    uint2 uh, ul;
    uh.x = ((uint32_t)*(uint16_t*)&h[1] << 16) | *(uint16_t*)&h[0];
    uh.y = ((uint32_t)*(uint16_t*)&h[3] << 16) | *(uint16_t*)&h[2];
    ul.x = ((uint32_t)*(uint16_t*)&l[1] << 16) | *(uint16_t*)&l[0];
    ul.y = ((uint32_t)*(uint16_t*)&l[3] << 16) | *(uint16_t*)&l[2];
    *reinterpret_cast<uint2*>(&hi[i]) = uh;
    *reinterpret_cast<uint2*>(&lo[i]) = ul;
}

// ---------------- fp16 2-term GEMM ----------------
// C[M,N] = (Ah+Al) @ Bh.  Block tile 128x128, BK=32, 3-stage cp.async,
// 256 threads (8 warps, 4x2), warp tile 32x64, 2 CTAs/SM.
// MODE 0: fp32 out = acc+bias+res; 1: fp16 out = acc+bias; 2: gelu fp16 hi/lo out.
template <int MODE>
__global__ __launch_bounds__(256, 2) void gemm_f16(
    const __half* __restrict__ Ah, const __half* __restrict__ Al,
    const __half* __restrict__ Bh,
    const float* __restrict__ bias, const float* __restrict__ res,
    void* __restrict__ out, void* __restrict__ out2, int K, int N)
{
    // per-stage smem (bytes):
    //   A: (128 hi | 128 lo) rows x pitch 40 fp16 -> 20480
    //   B:  32 rows x pitch 136 fp16              -> 8704
    constexpr int STAGE = 29184;
    constexpr int BOFF  = 20480;
    extern __shared__ __align__(16) char smem[];
    const uint32_t sbase = smem_u32(smem);

    const int tid = threadIdx.x;
    const int w = tid >> 5, lane = tid & 31;
    const int grp = lane >> 3, lrow8 = lane & 7;
    const int wr = w >> 1, wc = w & 1;              // 4x2 warps; warp tile 32x64
    const int rbase = wr * 32, cbase = wc * 64;

    const __half* Abh = Ah + (long long)blockIdx.y * 128 * K;
    const __half* Abl = Al + (long long)blockIdx.y * 128 * K;
    const __half* Bbh = Bh + blockIdx.x * 128;

    auto load_stage = [&](int kt, int s) {
        uint32_t sb = sbase + s * STAGE;
#pragma unroll
        for (int j = 0; j < 4; j++) {               // A: 1024 16B chunks
            int idx = tid + j * 256;
            int t = idx >> 9, within = idx & 511;
            int row = within >> 2, c = within & 3;
            const __half* g = (t ? Abl : Abh) + (long long)row * K + kt * 32 + c * 8;
            cp16(sb + ((t * 128 + row) * 40 + c * 8) * 2, g);
        }
#pragma unroll
        for (int j = 0; j < 2; j++) {               // B: 512 16B chunks
            int idx = tid + j * 256;
            int row = idx >> 4, c = idx & 15;
            const __half* g = Bbh + (long long)(kt * 32 + row) * N + c * 8;
            cp16(sb + BOFF + (row * 136 + c * 8) * 2, g);
        }
        cp_commit();
    };

    float acc[2][8][4];
#pragma unroll
    for (int i = 0; i < 2; i++)
#pragma unroll
        for (int j = 0; j < 8; j++)
#pragma unroll
            for (int e = 0; e < 4; e++) acc[i][j][e] = 0.f;

    const int KT = K >> 5;
    load_stage(0, 0);
    load_stage(1, 1);

    for (int kt = 0; kt < KT; kt++) {
        if (kt + 1 < KT) asm volatile("cp.async.wait_group 1;" ::: "memory");
        else             asm volatile("cp.async.wait_group 0;" ::: "memory");
        __syncthreads();
        if (kt + 2 < KT) load_stage(kt + 2, (kt + 2) % 3);

        const uint32_t Ab = sbase + (kt % 3) * STAGE;
        const uint32_t Bb = Ab + BOFF;
#pragma unroll
        for (int kk = 0; kk < 32; kk += 16) {
            uint32_t ah[2][4], al[2][4];
#pragma unroll
            for (int i = 0; i < 2; i++) {
                uint32_t addr = Ab + ((rbase + i * 16 + (grp & 1) * 8 + lrow8) * 40 +
                                      kk + (grp & 2) * 4) * 2;
                ldsm4_a(ah[i], addr);
                ldsm4_a(al[i], addr + 128 * 40 * 2);
            }
            uint32_t bh[4][4];
#pragma unroll
            for (int j = 0; j < 4; j++) {
                uint32_t addr = Bb + ((kk + (grp & 1) * 8 + lrow8) * 136 +
                                      cbase + j * 16 + (grp & 2) * 4) * 2;
                ldsm4t_a(bh[j], addr);
            }
#pragma unroll
            for (int i = 0; i < 2; i++)
#pragma unroll
                for (int jj = 0; jj < 8; jj++) {
                    uint32_t b0 = bh[jj >> 1][(jj & 1) * 2], b1 = bh[jj >> 1][(jj & 1) * 2 + 1];
                    mma16816(acc[i][jj], ah[i][0], ah[i][1], ah[i][2], ah[i][3], b0, b1);
                    mma16816(acc[i][jj], al[i][0], al[i][1], al[i][2], al[i][3], b0, b1);
                }
        }
    }

    // ---- epilogue straight from registers ----
    const int tr = lane >> 2, tc = (lane & 3) * 2;
#pragma unroll
    for (int i = 0; i < 2; i++) {
        long long gr0 = (long long)blockIdx.y * 128 + rbase + i * 16 + tr;
#pragma unroll
        for (int jj = 0; jj < 8; jj++) {
            int gc = blockIdx.x * 128 + cbase + jj * 8 + tc;
            float b0 = bias[gc], b1 = bias[gc + 1];
            float v0 = acc[i][jj][0] + b0, v1 = acc[i][jj][1] + b1;
            float v2 = acc[i][jj][2] + b0, v3 = acc[i][jj][3] + b1;
            if (MODE == 0) {
                float* fo = (float*)out;
                float2 r0 = *reinterpret_cast<const float2*>(&res[gr0 * N + gc]);
                float2 r1 = *reinterpret_cast<const float2*>(&res[(gr0 + 8) * N + gc]);
                *reinterpret_cast<float2*>(&fo[gr0 * N + gc]) =
                    make_float2(v0 + r0.x, v1 + r0.y);
                *reinterpret_cast<float2*>(&fo[(gr0 + 8) * N + gc]) =
                    make_float2(v2 + r1.x, v3 + r1.y);
            } else if (MODE == 1) {
                __half* bo = (__half*)out;
                *reinterpret_cast<uint32_t*>(&bo[gr0 * N + gc])       = packh2(v0, v1);
                *reinterpret_cast<uint32_t*>(&bo[(gr0 + 8) * N + gc]) = packh2(v2, v3);
            } else {
                float g[4] = { v0, v1, v2, v3 };
#pragma unroll
                for (int e = 0; e < 4; e++) {
                    float xx = g[e];
                    float tt = 0.7978845608028654f * (xx + 0.044715f * xx * xx * xx);
                    g[e] = 0.5f * xx * (1.0f + tanhf(tt));
                }
                __half h0, l0, h1, l1;
                __half* ho = (__half*)out;
                __half* lo = (__half*)out2;
                split_hilo(g[0], h0, l0); split_hilo(g[1], h1, l1);
                *reinterpret_cast<uint32_t*>(&ho[gr0 * N + gc]) =
                    ((uint32_t)*(uint16_t*)&h1 << 16) | *(uint16_t*)&h0;
                *reinterpret_cast<uint32_t*>(&lo[gr0 * N + gc]) =
                    ((uint32_t)*(uint16_t*)&l1 << 16) | *(uint16_t*)&l0;
                split_hilo(g[2], h0, l0); split_hilo(g[3], h1, l1);
                *reinterpret_cast<uint32_t*>(&ho[(gr0 + 8) * N + gc]) =
                    ((uint32_t)*(uint16_t*)&h1 << 16) | *(uint16_t*)&h0;
                *reinterpret_cast<uint32_t*>(&lo[(gr0 + 8) * N + gc]) =
                    ((uint32_t)*(uint16_t*)&l1 << 16) | *(uint16_t*)&l0;
            }
        }
    }
}

// ---------------- flash attention: fp16, 3-stage cp.async KV pipeline ----------------
__global__ __launch_bounds__(128) void flash_kernel(
    const __half* __restrict__ Qg, const __half* __restrict__ Kg,
    const __half* __restrict__ Vg,
    __half* __restrict__ Ohi, __half* __restrict__ Olo,
    int sq, int skv, int nk)
{
    constexpr int PD = 72;
    constexpr int STG = 2 * 64 * PD * 2;       // 18432 bytes per stage
    constexpr int VOFF = 64 * PD * 2;
    extern __shared__ __align__(16) char fsmem[];
    const uint32_t sb = smem_u32(fsmem);

    const int tid = threadIdx.x;
    const int w = tid >> 5, t = tid & 31;
    const int bh = blockIdx.y;
    const int b = bh >> 4, h = bh & 15;

    const long long qrow0 = (long long)b * 2048 + (long long)blockIdx.x * 128;
    const __half* Qb = Qg + qrow0 * sq + h * 64;
    const __half* Kb = Kg + (long long)b * nk * skv + h * 64;
    const __half* Vb = Vg + (long long)b * nk * skv + h * 64;
    __half* Obh = Ohi + qrow0 * 1024 + h * 64;
    __half* Obl = Olo + qrow0 * 1024 + h * 64;

    const int qr = w * 32;
    const int tr = t >> 2, tc = (t & 3) * 2;

    uint32_t qa[2][4][4];
#pragma unroll
    for (int mt = 0; mt < 2; mt++) {
        int r0 = qr + mt * 16 + tr;
#pragma unroll
        for (int kc = 0; kc < 4; kc++) {
            int c0 = kc * 16 + tc;
            qa[mt][kc][0] = *reinterpret_cast<const uint32_t*>(&Qb[(long long)r0 * sq + c0]);
            qa[mt][kc][1] = *reinterpret_cast<const uint32_t*>(&Qb[(long long)(r0 + 8) * sq + c0]);
            qa[mt][kc][2] = *reinterpret_cast<const uint32_t*>(&Qb[(long long)r0 * sq + c0 + 8]);
            qa[mt][kc][3] = *reinterpret_cast<const uint32_t*>(&Qb[(long long)(r0 + 8) * sq + c0 + 8]);
        }
    }

    auto load_kv = [&](int kb, int s) {
        uint32_t base = sb + s * STG;
#pragma unroll
        for (int j = 0; j < 8; j++) {
            int i = tid + j * 128;
            int half_ = i >> 9, within = i & 511;
            int r = within >> 3, c = within & 7;
            const __half* g = (half_ ? Vb : Kb) +
                              (long long)(kb * 64 + r) * skv + c * 8;
            cp16(base + half_ * VOFF + (r * PD + c * 8) * 2, g);
        }
        cp_commit();
    };

    float o[2][8][4];
    float mrow[2][2], lrow[2][2];
#pragma unroll
    for (int mt = 0; mt < 2; mt++) {
        mrow[mt][0] = mrow[mt][1] = -1e30f;
        lrow[mt][0] = lrow[mt][1] = 0.f;
#pragma unroll
        for (int nb = 0; nb < 8; nb++)
#pragma unroll
            for (int e = 0; e < 4; e++) o[mt][nb][e] = 0.f;
    }

    const float CSC = 0.18033688011112042f;     // (1/8)*log2(e)
    const int niter = nk >> 6;
    const int grp = t >> 3, lrow8 = t & 7;

    load_kv(0, 0);
    load_kv(1, 1);

    for (int kb = 0; kb < niter; kb++) {
        if (kb + 1 < niter) asm volatile("cp.async.wait_group 1;" ::: "memory");
        else                asm volatile("cp.async.wait_group 0;" ::: "memory");
        __syncthreads();
        if (kb + 2 < niter) load_kv(kb + 2, (kb + 2) % 3);

        const uint32_t Kbase = sb + (kb % 3) * STG;
        const uint32_t Vbase = Kbase + VOFF;

        float s[2][8][4];
#pragma unroll
        for (int mt = 0; mt < 2; mt++)
#pragma unroll
            for (int nb = 0; nb < 8; nb++)
#pragma unroll
                for (int e = 0; e < 4; e++) s[mt][nb][e] = 0.f;

#pragma unroll
        for (int kc = 0; kc < 4; kc++) {
#pragma unroll
            for (int nbp = 0; nbp < 4; nbp++) {
                uint32_t r[4];
                uint32_t addr = Kbase +
                    ((nbp * 16 + (grp & 2) * 4 + lrow8) * PD + kc * 16 + (grp & 1) * 8) * 2;
                ldsm4_a(r, addr);
#pragma unroll
                for (int mt = 0; mt < 2; mt++) {
                    mma16816(s[mt][2 * nbp],     qa[mt][kc][0], qa[mt][kc][1],
                             qa[mt][kc][2], qa[mt][kc][3], r[0], r[1]);
                    mma16816(s[mt][2 * nbp + 1], qa[mt][kc][0], qa[mt][kc][1],
                             qa[mt][kc][2], qa[mt][kc][3], r[2], r[3]);
                }
            }
        }

#pragma unroll
        for (int mt = 0; mt < 2; mt++) {
#pragma unroll
            for (int half_ = 0; half_ < 2; half_++) {
                int e0 = 2 * half_;
                float mx = -1e30f;
#pragma unroll
                for (int nb = 0; nb < 8; nb++)
                    mx = fmaxf(mx, fmaxf(s[mt][nb][e0], s[mt][nb][e0 + 1]));
                mx = fmaxf(mx, __shfl_xor_sync(0xffffffffu, mx, 1));
                mx = fmaxf(mx, __shfl_xor_sync(0xffffffffu, mx, 2));
                float newm = fmaxf(mrow[mt][half_], mx);
                float alpha = exp2f((mrow[mt][half_] - newm) * CSC);
                float sum = 0.f;
#pragma unroll
                for (int nb = 0; nb < 8; nb++) {
                    float p0 = exp2f((s[mt][nb][e0] - newm) * CSC);
                    float p1 = exp2f((s[mt][nb][e0 + 1] - newm) * CSC);
                    s[mt][nb][e0] = p0; s[mt][nb][e0 + 1] = p1;
                    sum += p0 + p1;
                }
                sum += __shfl_xor_sync(0xffffffffu, sum, 1);
                sum += __shfl_xor_sync(0xffffffffu, sum, 2);
                lrow[mt][half_] = lrow[mt][half_] * alpha + sum;
                mrow[mt][half_] = newm;
#pragma unroll
                for (int nb = 0; nb < 8; nb++) {
                    o[mt][nb][e0]     *= alpha;
                    o[mt][nb][e0 + 1] *= alpha;
                }
            }
        }

#pragma unroll
        for (int kcP = 0; kcP < 4; kcP++) {
            uint32_t pa[2][4];
#pragma unroll
            for (int mt = 0; mt < 2; mt++) {
                pa[mt][0] = packh2(s[mt][2 * kcP][0],     s[mt][2 * kcP][1]);
                pa[mt][1] = packh2(s[mt][2 * kcP][2],     s[mt][2 * kcP][3]);
                pa[mt][2] = packh2(s[mt][2 * kcP + 1][0], s[mt][2 * kcP + 1][1]);
                pa[mt][3] = packh2(s[mt][2 * kcP + 1][2], s[mt][2 * kcP + 1][3]);
            }
#pragma unroll
            for (int nbp = 0; nbp < 4; nbp++) {
                uint32_t r[4];
                uint32_t addr = Vbase +
                    ((kcP * 16 + (grp & 1) * 8 + lrow8) * PD + nbp * 16 + (grp & 2) * 4) * 2;
                ldsm4t_a(r, addr);
#pragma unroll
                for (int mt = 0; mt < 2; mt++) {
                    mma16816(o[mt][2 * nbp],     pa[mt][0], pa[mt][1], pa[mt][2], pa[mt][3],
                             r[0], r[1]);
                    mma16816(o[mt][2 * nbp + 1], pa[mt][0], pa[mt][1], pa[mt][2], pa[mt][3],
                             r[2], r[3]);
                }
            }
        }
    }

#pragma unroll
    for (int mt = 0; mt < 2; mt++) {
        int r0 = qr + mt * 16 + tr;
        float inv0 = 1.0f / lrow[mt][0];
        float inv1 = 1.0f / lrow[mt][1];
#pragma unroll
        for (int nb = 0; nb < 8; nb++) {
            int col = nb * 8 + tc;
            float a0 = o[mt][nb][0] * inv0, a1 = o[mt][nb][1] * inv0;
            float b0 = o[mt][nb][2] * inv1, b1 = o[mt][nb][3] * inv1;
            __half h0, l0, h1, l1;
            split_hilo(a0, h0, l0); split_hilo(a1, h1, l1);
            *reinterpret_cast<uint32_t*>(&Obh[(long long)r0 * 1024 + col]) =
                ((uint32_t)*(uint16_t*)&h1 << 16) | *(uint16_t*)&h0;
            *reinterpret_cast<uint32_t*>(&Obl[(long long)r0 * 1024 + col]) =
                ((uint32_t)*(uint16_t*)&l1 << 16) | *(uint16_t*)&l0;
            split_hilo(b0, h0, l0); split_hilo(b1, h1, l1);
            *reinterpret_cast<uint32_t*>(&Obh[(long long)(r0 + 8) * 1024 + col]) =
                ((uint32_t)*(uint16_t*)&h1 << 16) | *(uint16_t*)&h0;
            *reinterpret_cast<uint32_t*>(&Obl[(long long)(r0 + 8) * 1024 + col]) =
                ((uint32_t)*(uint16_t*)&l1 << 16) | *(uint16_t*)&l0;
        }
    }
}

// ---------------- host ----------------
static void* devptr(const void* symbol)
{
    void* p = nullptr;
    cudaGetSymbolAddress(&p, symbol);
    return p;
}

extern "C" void kernel_launch(void* const* d_in, const int* in_sizes, int n_in,
                              void* d_out, int out_size)
{
    const float* x    = (const float*)d_in[0];
    const float* ctx  = (const float*)d_in[1];
    const float* Wqkv = (const float*)d_in[2];
    const float* bqkv = (const float*)d_in[3];
    const float* Wos  = (const float*)d_in[4];
    const float* bos  = (const float*)d_in[5];
    const float* Wq   = (const float*)d_in[6];
    const float* bq   = (const float*)d_in[7];
    const float* Wkv  = (const float*)d_in[8];
    const float* bkv  = (const float*)d_in[9];
    const float* Woc  = (const float*)d_in[10];
    const float* boc  = (const float*)d_in[11];
    const float* W1   = (const float*)d_in[12];
    const float* b1   = (const float*)d_in[13];
    const float* W2   = (const float*)d_in[14];
    const float* b2   = (const float*)d_in[15];
    float* out = (float*)d_out;

    __half* wh  = (__half*)devptr(g_w_hi);
    __half* lnh = (__half*)devptr(g_lnh);
    __half* lnl = (__half*)devptr(g_lnl);
    __half* ath = (__half*)devptr(g_ath);
    __half* atl = (__half*)devptr(g_atl);
    __half* cxh = (__half*)devptr(g_cxh);
    __half* cxl = (__half*)devptr(g_cxl);
    __half* mdh = (__half*)devptr(g_mdh);
    __half* mdl = (__half*)devptr(g_mdl);
    __half* qkv = (__half*)devptr(g_qkv);
    __half* q   = (__half*)devptr(g_q);
    __half* kv  = (__half*)devptr(g_kv);
    float* x1 = (float*)devptr(g_x1);
    float* x2 = (float*)devptr(g_x2);

    const int SMEM  = 3 * 29184;   // gemm: 87552 bytes (2 CTAs/SM)
    const int FSMEM = 3 * 18432;   // flash: 55296 bytes
    cudaFuncSetAttribute(gemm_f16<0>, cudaFuncAttributeMaxDynamicSharedMemorySize, SMEM);
    cudaFuncSetAttribute(gemm_f16<1>, cudaFuncAttributeMaxDynamicSharedMemorySize, SMEM);
    cudaFuncSetAttribute(gemm_f16<2>, cudaFuncAttributeMaxDynamicSharedMemorySize, SMEM);
    cudaFuncSetAttribute(flash_kernel, cudaFuncAttributeMaxDynamicSharedMemorySize, FSMEM);

    // ---- splits ----
    wsplit_all_kernel<<<W_TOTAL / 1024, 256>>>(Wqkv, Wos, Wq, Wkv, Woc, W1, W2, wh);
    split_kernel<<<2097152 / 1024, 256>>>(ctx, cxh, cxl);

    // ---- self-attention ----
    ln_hilo_kernel<<<4096, 256>>>(x, lnh, lnl);
    gemm_f16<1><<<dim3(24, 32), 256, SMEM>>>(lnh, lnl, wh + OFF_QKV,
                                             bqkv, nullptr, qkv, nullptr, 1024, 3072);
    flash_kernel<<<dim3(16, 32), 128, FSMEM>>>(qkv, qkv + 1024, qkv + 2048, ath, atl,
                                               3072, 3072, 2048);
    gemm_f16<0><<<dim3(8, 32), 256, SMEM>>>(ath, atl, wh + OFF_OS,
                                            bos, x, x1, nullptr, 1024, 1024);

    // ---- cross-attention ----
    ln_hilo_kernel<<<4096, 256>>>(x1, lnh, lnl);
    gemm_f16<1><<<dim3(8, 32), 256, SMEM>>>(lnh, lnl, wh + OFF_Q,
                                            bq, nullptr, q, nullptr, 1024, 1024);
    gemm_f16<1><<<dim3(16, 16), 256, SMEM>>>(cxh, cxl, wh + OFF_KV,
                                             bkv, nullptr, kv, nullptr, 1024, 2048);
    flash_kernel<<<dim3(16, 32), 128, FSMEM>>>(q, kv, kv + 1024, ath, atl,
                                               1024, 2048, 1024);
    gemm_f16<0><<<dim3(8, 32), 256, SMEM>>>(ath, atl, wh + OFF_OC,
                                            boc, x1, x2, nullptr, 1024, 1024);

    // ---- MLP ----
    ln_hilo_kernel<<<4096, 256>>>(x2, lnh, lnl);
    gemm_f16<2><<<dim3(32, 32), 256, SMEM>>>(lnh, lnl, wh + OFF_W1,
                                             b1, nullptr, mdh, mdl, 1024, 4096);
    gemm_f16<0><<<dim3(8, 32), 256, SMEM>>>(mdh, mdl, wh + OFF_W2,
                                            b2, x2, out, nullptr, 4096, 1024);
}

// round 15
// speedup vs baseline: 3.3200x; 1.5154x over previous
#include <cuda_runtime.h>
#include <cuda_fp16.h>
#include <cstdint>

// Dims: B=2, N=2048, M=1024, C=1024, H=16, D=64, HID=4096
// TQ = 4096 (B*N), TKV = 2048 (B*M)

// ---------------- scratch ----------------
__device__ __half g_w_hi[16777216];                 // weights fp16 (B operand)
__device__ __half g_lnh[4096u * 1024u];             // LN out fp16
__device__ __half g_ath[4096u * 1024u];             // attention out fp16
__device__ __half g_cxh[2048u * 1024u];             // ctx fp16
__device__ __half g_mdh[4096u * 4096u];             // MLP mid fp16
__device__ __half g_qkv[4096u * 3072u];
__device__ __half g_q  [4096u * 1024u];
__device__ __half g_kv [2048u * 2048u];
__device__ float g_x1[4096u * 1024u];
__device__ float g_x2[4096u * 1024u];

// weight offsets (elements) — contiguous in launch order
#define OFF_QKV 0
#define OFF_OS  3145728
#define OFF_Q   4194304
#define OFF_KV  5242880
#define OFF_OC  7340032
#define OFF_W1  8388608
#define OFF_W2  12582912
#define W_TOTAL 16777216

// ---------------- helpers ----------------
__device__ __forceinline__ uint32_t smem_u32(const void* p)
{
    uint32_t a;
    asm("{ .reg .u64 t; cvta.to.shared.u64 t, %1; cvt.u32.u64 %0, t; }" : "=r"(a) : "l"(p));
    return a;
}
__device__ __forceinline__ uint32_t packh2(float lo, float hi)
{
    __half2 h = __floats2half2_rn(lo, hi);
    return *reinterpret_cast<uint32_t*>(&h);
}
__device__ __forceinline__ void cp16(uint32_t s, const void* g)
{
    asm volatile("cp.async.cg.shared.global [%0], [%1], 16;" :: "r"(s), "l"(g));
}
__device__ __forceinline__ void cp_commit() { asm volatile("cp.async.commit_group;"); }

__device__ __forceinline__ void mma16816(float c[4], uint32_t a0, uint32_t a1,
                                         uint32_t a2, uint32_t a3,
                                         uint32_t b0, uint32_t b1)
{
    asm volatile("mma.sync.aligned.m16n8k16.row.col.f32.f16.f16.f32 "
                 "{%0,%1,%2,%3}, {%4,%5,%6,%7}, {%8,%9}, {%0,%1,%2,%3};"
                 : "+f"(c[0]), "+f"(c[1]), "+f"(c[2]), "+f"(c[3])
                 : "r"(a0), "r"(a1), "r"(a2), "r"(a3), "r"(b0), "r"(b1));
}
__device__ __forceinline__ void ldsm4_a(uint32_t* r, uint32_t a)
{
    asm volatile("ldmatrix.sync.aligned.m8n8.x4.shared.b16 {%0,%1,%2,%3}, [%4];"
                 : "=r"(r[0]), "=r"(r[1]), "=r"(r[2]), "=r"(r[3]) : "r"(a));
}
__device__ __forceinline__ void ldsm4t_a(uint32_t* r, uint32_t a)
{
    asm volatile("ldmatrix.sync.aligned.m8n8.x4.trans.shared.b16 {%0,%1,%2,%3}, [%4];"
                 : "=r"(r[0]), "=r"(r[1]), "=r"(r[2]), "=r"(r[3]) : "r"(a));
}

// ---------------- LayerNorm -> fp16 ----------------
__global__ __launch_bounds__(256) void ln_kernel(const float* __restrict__ x,
                                                 __half* __restrict__ hi)
{
    long long base = (long long)blockIdx.x * 1024;
    float v4[4];
    float s = 0.f, ss = 0.f;
#pragma unroll
    for (int i = 0; i < 4; i++) {
        v4[i] = x[base + threadIdx.x + i * 256];
        s += v4[i]; ss += v4[i] * v4[i];
    }
    __shared__ float shs[32], shq[32];
    for (int o = 16; o; o >>= 1) {
        s  += __shfl_xor_sync(0xffffffffu, s,  o);
        ss += __shfl_xor_sync(0xffffffffu, ss, o);
    }
    int w = threadIdx.x >> 5, l = threadIdx.x & 31;
    if (l == 0) { shs[w] = s; shq[w] = ss; }
    __syncthreads();
    if (w == 0) {
        float a = (l < 8) ? shs[l] : 0.f;
        float b = (l < 8) ? shq[l] : 0.f;
        for (int o = 4; o; o >>= 1) {
            a += __shfl_xor_sync(0xffffffffu, a, o);
            b += __shfl_xor_sync(0xffffffffu, b, o);
        }
        if (l == 0) { shs[0] = a; shq[0] = b; }
    }
    __syncthreads();
    float mean = shs[0] * (1.0f / 1024.0f);
    float var  = shq[0] * (1.0f / 1024.0f) - mean * mean;
    float inv  = rsqrtf(var + 1e-6f);
#pragma unroll
    for (int i = 0; i < 4; i++)
        hi[base + threadIdx.x + i * 256] = __float2half_rn((v4[i] - mean) * inv);
}

// ---------------- batched weight convert: 7 fp32 sources -> contiguous fp16 ----------------
__global__ __launch_bounds__(256) void wsplit_all_kernel(
    const float* __restrict__ s0, const float* __restrict__ s1,
    const float* __restrict__ s2, const float* __restrict__ s3,
    const float* __restrict__ s4, const float* __restrict__ s5,
    const float* __restrict__ s6,
    __half* __restrict__ hi)
{
    long long e = ((long long)blockIdx.x * 256 + threadIdx.x) * 4;
    const float* src;
    long long off;
    if      (e < OFF_OS)  { src = s0; off = 0; }
    else if (e < OFF_Q)   { src = s1; off = OFF_OS; }
    else if (e < OFF_KV)  { src = s2; off = OFF_Q; }
    else if (e < OFF_OC)  { src = s3; off = OFF_KV; }
    else if (e < OFF_W1)  { src = s4; off = OFF_OC; }
    else if (e < OFF_W2)  { src = s5; off = OFF_W1; }
    else                  { src = s6; off = OFF_W2; }
    float4 v = *reinterpret_cast<const float4*>(&src[e - off]);
    uint2 uh;
    uh.x = packh2(v.x, v.y);
    uh.y = packh2(v.z, v.w);
    *reinterpret_cast<uint2*>(&hi[e]) = uh;
}

// ---------------- fp32 -> fp16 convert (ctx) ----------------
__global__ __launch_bounds__(256) void conv_kernel(const float* __restrict__ x,
                                                   __half* __restrict__ hi)
{
    long long i = ((long long)blockIdx.x * 256 + threadIdx.x) * 4;
    float4 v = *reinterpret_cast<const float4*>(&x[i]);
    uint2 uh;
    uh.x = packh2(v.x, v.y);
    uh.y = packh2(v.z, v.w);
    *reinterpret_cast<uint2*>(&hi[i]) = uh;
}

// ---------------- fp16 single-term GEMM ----------------
// C[M,N] = A @ B.  Block tile 128x128, BK=32, 3-stage cp.async,
// 256 threads (8 warps, 4x2), warp tile 32x64, 2 CTAs/SM.
// MODE 0: fp32 out = acc+bias+res; 1: fp16 out = acc+bias; 2: fp16 out = gelu(acc+bias).
template <int MODE>
__global__ __launch_bounds__(256, 2) void gemm_f16(
    const __half* __restrict__ Ah, const __half* __restrict__ Bh,
    const float* __restrict__ bias, const float* __restrict__ res,
    void* __restrict__ out, int K, int N)
{
    // per-stage smem (bytes):
    //   A: 128 rows x pitch 40 fp16 -> 10240
    //   B:  32 rows x pitch 136 fp16 -> 8704
    constexpr int STAGE = 18944;
    constexpr int BOFF  = 10240;
    extern __shared__ __align__(16) char smem[];
    const uint32_t sbase = smem_u32(smem);

    const int tid = threadIdx.x;
    const int w = tid >> 5, lane = tid & 31;
    const int grp = lane >> 3, lrow8 = lane & 7;
    const int wr = w >> 1, wc = w & 1;              // 4x2 warps; warp tile 32x64
    const int rbase = wr * 32, cbase = wc * 64;

    const __half* Abh = Ah + (long long)blockIdx.y * 128 * K;
    const __half* Bbh = Bh + blockIdx.x * 128;

    auto load_stage = [&](int kt, int s) {
        uint32_t sb = sbase + s * STAGE;
#pragma unroll
        for (int j = 0; j < 2; j++) {               // A: 512 16B chunks
            int idx = tid + j * 256;
            int row = idx >> 2, c = idx & 3;
            const __half* g = Abh + (long long)row * K + kt * 32 + c * 8;
            cp16(sb + (row * 40 + c * 8) * 2, g);
        }
#pragma unroll
        for (int j = 0; j < 2; j++) {               // B: 512 16B chunks
            int idx = tid + j * 256;
            int row = idx >> 4, c = idx & 15;
            const __half* g = Bbh + (long long)(kt * 32 + row) * N + c * 8;
            cp16(sb + BOFF + (row * 136 + c * 8) * 2, g);
        }
        cp_commit();
    };

    float acc[2][8][4];
#pragma unroll
    for (int i = 0; i < 2; i++)
#pragma unroll
        for (int j = 0; j < 8; j++)
#pragma unroll
            for (int e = 0; e < 4; e++) acc[i][j][e] = 0.f;

    const int KT = K >> 5;
    load_stage(0, 0);
    load_stage(1, 1);

    for (int kt = 0; kt < KT; kt++) {
        if (kt + 1 < KT) asm volatile("cp.async.wait_group 1;" ::: "memory");
        else             asm volatile("cp.async.wait_group 0;" ::: "memory");
        __syncthreads();
        if (kt + 2 < KT) load_stage(kt + 2, (kt + 2) % 3);

        const uint32_t Ab = sbase + (kt % 3) * STAGE;
        const uint32_t Bb = Ab + BOFF;
#pragma unroll
        for (int kk = 0; kk < 32; kk += 16) {
            uint32_t ah[2][4];
#pragma unroll
            for (int i = 0; i < 2; i++) {
                uint32_t addr = Ab + ((rbase + i * 16 + (grp & 1) * 8 + lrow8) * 40 +
                                      kk + (grp & 2) * 4) * 2;
                ldsm4_a(ah[i], addr);
            }
            uint32_t bh[4][4];
#pragma unroll
            for (int j = 0; j < 4; j++) {
                uint32_t addr = Bb + ((kk + (grp & 1) * 8 + lrow8) * 136 +
                                      cbase + j * 16 + (grp & 2) * 4) * 2;
                ldsm4t_a(bh[j], addr);
            }
#pragma unroll
            for (int i = 0; i < 2; i++)
#pragma unroll
                for (int jj = 0; jj < 8; jj++) {
                    uint32_t b0 = bh[jj >> 1][(jj & 1) * 2], b1 = bh[jj >> 1][(jj & 1) * 2 + 1];
                    mma16816(acc[i][jj], ah[i][0], ah[i][1], ah[i][2], ah[i][3], b0, b1);
                }
        }
    }

    // ---- epilogue straight from registers ----
    const int tr = lane >> 2, tc = (lane & 3) * 2;
#pragma unroll
    for (int i = 0; i < 2; i++) {
        long long gr0 = (long long)blockIdx.y * 128 + rbase + i * 16 + tr;
#pragma unroll
        for (int jj = 0; jj < 8; jj++) {
            int gc = blockIdx.x * 128 + cbase + jj * 8 + tc;
            float b0 = bias[gc], b1 = bias[gc + 1];
            float v0 = acc[i][jj][0] + b0, v1 = acc[i][jj][1] + b1;
            float v2 = acc[i][jj][2] + b0, v3 = acc[i][jj][3] + b1;
            if (MODE == 0) {
                float* fo = (float*)out;
                float2 r0 = *reinterpret_cast<const float2*>(&res[gr0 * N + gc]);
                float2 r1 = *reinterpret_cast<const float2*>(&res[(gr0 + 8) * N + gc]);
                *reinterpret_cast<float2*>(&fo[gr0 * N + gc]) =
                    make_float2(v0 + r0.x, v1 + r0.y);
                *reinterpret_cast<float2*>(&fo[(gr0 + 8) * N + gc]) =
                    make_float2(v2 + r1.x, v3 + r1.y);
            } else if (MODE == 1) {
                __half* bo = (__half*)out;
                *reinterpret_cast<uint32_t*>(&bo[gr0 * N + gc])       = packh2(v0, v1);
                *reinterpret_cast<uint32_t*>(&bo[(gr0 + 8) * N + gc]) = packh2(v2, v3);
            } else {
                float g[4] = { v0, v1, v2, v3 };
#pragma unroll
                for (int e = 0; e < 4; e++) {
                    float xx = g[e];
                    float tt = 0.7978845608028654f * (xx + 0.044715f * xx * xx * xx);
                    g[e] = 0.5f * xx * (1.0f + tanhf(tt));
                }
                __half* ho = (__half*)out;
                *reinterpret_cast<uint32_t*>(&ho[gr0 * N + gc])       = packh2(g[0], g[1]);
                *reinterpret_cast<uint32_t*>(&ho[(gr0 + 8) * N + gc]) = packh2(g[2], g[3]);
            }
        }
    }
}

// ---------------- flash attention: fp16, 3-stage cp.async KV pipeline ----------------
__global__ __launch_bounds__(128) void flash_kernel(
    const __half* __restrict__ Qg, const __half* __restrict__ Kg,
    const __half* __restrict__ Vg, __half* __restrict__ Ohi,
    int sq, int skv, int nk)
{
    constexpr int PD = 72;
    constexpr int STG = 2 * 64 * PD * 2;       // 18432 bytes per stage
    constexpr int VOFF = 64 * PD * 2;
    extern __shared__ __align__(16) char fsmem[];
    const uint32_t sb = smem_u32(fsmem);

    const int tid = threadIdx.x;
    const int w = tid >> 5, t = tid & 31;
    const int bh = blockIdx.y;
    const int b = bh >> 4, h = bh & 15;

    const long long qrow0 = (long long)b * 2048 + (long long)blockIdx.x * 128;
    const __half* Qb = Qg + qrow0 * sq + h * 64;
    const __half* Kb = Kg + (long long)b * nk * skv + h * 64;
    const __half* Vb = Vg + (long long)b * nk * skv + h * 64;
    __half* Obh = Ohi + qrow0 * 1024 + h * 64;

    const int qr = w * 32;
    const int tr = t >> 2, tc = (t & 3) * 2;

    uint32_t qa[2][4][4];
#pragma unroll
    for (int mt = 0; mt < 2; mt++) {
        int r0 = qr + mt * 16 + tr;
#pragma unroll
        for (int kc = 0; kc < 4; kc++) {
            int c0 = kc * 16 + tc;
            qa[mt][kc][0] = *reinterpret_cast<const uint32_t*>(&Qb[(long long)r0 * sq + c0]);
            qa[mt][kc][1] = *reinterpret_cast<const uint32_t*>(&Qb[(long long)(r0 + 8) * sq + c0]);
            qa[mt][kc][2] = *reinterpret_cast<const uint32_t*>(&Qb[(long long)r0 * sq + c0 + 8]);
            qa[mt][kc][3] = *reinterpret_cast<const uint32_t*>(&Qb[(long long)(r0 + 8) * sq + c0 + 8]);
        }
    }

    auto load_kv = [&](int kb, int s) {
        uint32_t base = sb + s * STG;
#pragma unroll
        for (int j = 0; j < 8; j++) {
            int i = tid + j * 128;
            int half_ = i >> 9, within = i & 511;
            int r = within >> 3, c = within & 7;
            const __half* g = (half_ ? Vb : Kb) +
                              (long long)(kb * 64 + r) * skv + c * 8;
            cp16(base + half_ * VOFF + (r * PD + c * 8) * 2, g);
        }
        cp_commit();
    };

    float o[2][8][4];
    float mrow[2][2], lrow[2][2];
#pragma unroll
    for (int mt = 0; mt < 2; mt++) {
        mrow[mt][0] = mrow[mt][1] = -1e30f;
        lrow[mt][0] = lrow[mt][1] = 0.f;
#pragma unroll
        for (int nb = 0; nb < 8; nb++)
#pragma unroll
            for (int e = 0; e < 4; e++) o[mt][nb][e] = 0.f;
    }

    const float CSC = 0.18033688011112042f;     // (1/8)*log2(e)
    const int niter = nk >> 6;
    const int grp = t >> 3, lrow8 = t & 7;

    load_kv(0, 0);
    load_kv(1, 1);

    for (int kb = 0; kb < niter; kb++) {
        if (kb + 1 < niter) asm volatile("cp.async.wait_group 1;" ::: "memory");
        else                asm volatile("cp.async.wait_group 0;" ::: "memory");
        __syncthreads();
        if (kb + 2 < niter) load_kv(kb + 2, (kb + 2) % 3);

        const uint32_t Kbase = sb + (kb % 3) * STG;
        const uint32_t Vbase = Kbase + VOFF;

        float s[2][8][4];
#pragma unroll
        for (int mt = 0; mt < 2; mt++)
#pragma unroll
            for (int nb = 0; nb < 8; nb++)
#pragma unroll
                for (int e = 0; e < 4; e++) s[mt][nb][e] = 0.f;

#pragma unroll
        for (int kc = 0; kc < 4; kc++) {
#pragma unroll
            for (int nbp = 0; nbp < 4; nbp++) {
                uint32_t r[4];
                uint32_t addr = Kbase +
                    ((nbp * 16 + (grp & 2) * 4 + lrow8) * PD + kc * 16 + (grp & 1) * 8) * 2;
                ldsm4_a(r, addr);
#pragma unroll
                for (int mt = 0; mt < 2; mt++) {
                    mma16816(s[mt][2 * nbp],     qa[mt][kc][0], qa[mt][kc][1],
                             qa[mt][kc][2], qa[mt][kc][3], r[0], r[1]);
                    mma16816(s[mt][2 * nbp + 1], qa[mt][kc][0], qa[mt][kc][1],
                             qa[mt][kc][2], qa[mt][kc][3], r[2], r[3]);
                }
            }
        }

#pragma unroll
        for (int mt = 0; mt < 2; mt++) {
#pragma unroll
            for (int half_ = 0; half_ < 2; half_++) {
                int e0 = 2 * half_;
                float mx = -1e30f;
#pragma unroll
                for (int nb = 0; nb < 8; nb++)
                    mx = fmaxf(mx, fmaxf(s[mt][nb][e0], s[mt][nb][e0 + 1]));
                mx = fmaxf(mx, __shfl_xor_sync(0xffffffffu, mx, 1));
                mx = fmaxf(mx, __shfl_xor_sync(0xffffffffu, mx, 2));
                float newm = fmaxf(mrow[mt][half_], mx);
                float alpha = exp2f((mrow[mt][half_] - newm) * CSC);
                float sum = 0.f;
#pragma unroll
                for (int nb = 0; nb < 8; nb++) {
                    float p0 = exp2f((s[mt][nb][e0] - newm) * CSC);
                    float p1 = exp2f((s[mt][nb][e0 + 1] - newm) * CSC);
                    s[mt][nb][e0] = p0; s[mt][nb][e0 + 1] = p1;
                    sum += p0 + p1;
                }
                sum += __shfl_xor_sync(0xffffffffu, sum, 1);
                sum += __shfl_xor_sync(0xffffffffu, sum, 2);
                lrow[mt][half_] = lrow[mt][half_] * alpha + sum;
                mrow[mt][half_] = newm;
#pragma unroll
                for (int nb = 0; nb < 8; nb++) {
                    o[mt][nb][e0]     *= alpha;
                    o[mt][nb][e0 + 1] *= alpha;
                }
            }
        }

#pragma unroll
        for (int kcP = 0; kcP < 4; kcP++) {
            uint32_t pa[2][4];
#pragma unroll
            for (int mt = 0; mt < 2; mt++) {
                pa[mt][0] = packh2(s[mt][2 * kcP][0],     s[mt][2 * kcP][1]);
                pa[mt][1] = packh2(s[mt][2 * kcP][2],     s[mt][2 * kcP][3]);
                pa[mt][2] = packh2(s[mt][2 * kcP + 1][0], s[mt][2 * kcP + 1][1]);
                pa[mt][3] = packh2(s[mt][2 * kcP + 1][2], s[mt][2 * kcP + 1][3]);
            }
#pragma unroll
            for (int nbp = 0; nbp < 4; nbp++) {
                uint32_t r[4];
                uint32_t addr = Vbase +
                    ((kcP * 16 + (grp & 1) * 8 + lrow8) * PD + nbp * 16 + (grp & 2) * 4) * 2;
                ldsm4t_a(r, addr);
#pragma unroll
                for (int mt = 0; mt < 2; mt++) {
                    mma16816(o[mt][2 * nbp],     pa[mt][0], pa[mt][1], pa[mt][2], pa[mt][3],
                             r[0], r[1]);
                    mma16816(o[mt][2 * nbp + 1], pa[mt][0], pa[mt][1], pa[mt][2], pa[mt][3],
                             r[2], r[3]);
                }
            }
        }
    }

#pragma unroll
    for (int mt = 0; mt < 2; mt++) {
        int r0 = qr + mt * 16 + tr;
        float inv0 = 1.0f / lrow[mt][0];
        float inv1 = 1.0f / lrow[mt][1];
#pragma unroll
        for (int nb = 0; nb < 8; nb++) {
            int col = nb * 8 + tc;
            *reinterpret_cast<uint32_t*>(&Obh[(long long)r0 * 1024 + col]) =
                packh2(o[mt][nb][0] * inv0, o[mt][nb][1] * inv0);
            *reinterpret_cast<uint32_t*>(&Obh[(long long)(r0 + 8) * 1024 + col]) =
                packh2(o[mt][nb][2] * inv1, o[mt][nb][3] * inv1);
        }
    }
}

// ---------------- host ----------------
static void* devptr(const void* symbol)
{
    void* p = nullptr;
    cudaGetSymbolAddress(&p, symbol);
    return p;
}

extern "C" void kernel_launch(void* const* d_in, const int* in_sizes, int n_in,
                              void* d_out, int out_size)
{
    const float* x    = (const float*)d_in[0];
    const float* ctx  = (const float*)d_in[1];
    const float* Wqkv = (const float*)d_in[2];
    const float* bqkv = (const float*)d_in[3];
    const float* Wos  = (const float*)d_in[4];
    const float* bos  = (const float*)d_in[5];
    const float* Wq   = (const float*)d_in[6];
    const float* bq   = (const float*)d_in[7];
    const float* Wkv  = (const float*)d_in[8];
    const float* bkv  = (const float*)d_in[9];
    const float* Woc  = (const float*)d_in[10];
    const float* boc  = (const float*)d_in[11];
    const float* W1   = (const float*)d_in[12];
    const float* b1   = (const float*)d_in[13];
    const float* W2   = (const float*)d_in[14];
    const float* b2   = (const float*)d_in[15];
    float* out = (float*)d_out;

    __half* wh  = (__half*)devptr(g_w_hi);
    __half* lnh = (__half*)devptr(g_lnh);
    __half* ath = (__half*)devptr(g_ath);
    __half* cxh = (__half*)devptr(g_cxh);
    __half* mdh = (__half*)devptr(g_mdh);
    __half* qkv = (__half*)devptr(g_qkv);
    __half* q   = (__half*)devptr(g_q);
    __half* kv  = (__half*)devptr(g_kv);
    float* x1 = (float*)devptr(g_x1);
    float* x2 = (float*)devptr(g_x2);

    const int SMEM  = 3 * 18944;   // gemm: 56832 bytes (2 CTAs/SM)
    const int FSMEM = 3 * 18432;   // flash: 55296 bytes
    cudaFuncSetAttribute(gemm_f16<0>, cudaFuncAttributeMaxDynamicSharedMemorySize, SMEM);
    cudaFuncSetAttribute(gemm_f16<1>, cudaFuncAttributeMaxDynamicSharedMemorySize, SMEM);
    cudaFuncSetAttribute(gemm_f16<2>, cudaFuncAttributeMaxDynamicSharedMemorySize, SMEM);
    cudaFuncSetAttribute(flash_kernel, cudaFuncAttributeMaxDynamicSharedMemorySize, FSMEM);

    // ---- conversions ----
    wsplit_all_kernel<<<W_TOTAL / 1024, 256>>>(Wqkv, Wos, Wq, Wkv, Woc, W1, W2, wh);
    conv_kernel<<<2097152 / 1024, 256>>>(ctx, cxh);

    // ---- self-attention ----
    ln_kernel<<<4096, 256>>>(x, lnh);
    gemm_f16<1><<<dim3(24, 32), 256, SMEM>>>(lnh, wh + OFF_QKV,
                                             bqkv, nullptr, qkv, 1024, 3072);
    flash_kernel<<<dim3(16, 32), 128, FSMEM>>>(qkv, qkv + 1024, qkv + 2048, ath,
                                               3072, 3072, 2048);
    gemm_f16<0><<<dim3(8, 32), 256, SMEM>>>(ath, wh + OFF_OS,
                                            bos, x, x1, 1024, 1024);

    // ---- cross-attention ----
    ln_kernel<<<4096, 256>>>(x1, lnh);
    gemm_f16<1><<<dim3(8, 32), 256, SMEM>>>(lnh, wh + OFF_Q,
                                            bq, nullptr, q, 1024, 1024);
    gemm_f16<1><<<dim3(16, 16), 256, SMEM>>>(cxh, wh + OFF_KV,
                                             bkv, nullptr, kv, 1024, 2048);
    flash_kernel<<<dim3(16, 32), 128, FSMEM>>>(q, kv, kv + 1024, ath,
                                               1024, 2048, 1024);
    gemm_f16<0><<<dim3(8, 32), 256, SMEM>>>(ath, wh + OFF_OC,
                                            boc, x1, x2, 1024, 1024);

    // ---- MLP ----
    ln_kernel<<<4096, 256>>>(x2, lnh);
    gemm_f16<2><<<dim3(32, 32), 256, SMEM>>>(lnh, wh + OFF_W1,
                                             b1, nullptr, mdh, 1024, 4096);
    gemm_f16<0><<<dim3(8, 32), 256, SMEM>>>(mdh, wh + OFF_W2,
                                            b2, x2, out, 4096, 1024);
}

// round 16
// speedup vs baseline: 3.4030x; 1.0250x over previous
#include <cuda_runtime.h>
#include <cuda_fp16.h>
#include <cstdint>

// Dims: B=2, N=2048, M=1024, C=1024, H=16, D=64, HID=4096
// TQ = 4096 (B*N), TKV = 2048 (B*M)

// ---------------- scratch ----------------
__device__ __half g_w_hi[16777216];                 // weights fp16 (B operand)
__device__ __half g_lnh[4096u * 1024u];             // LN out fp16
__device__ __half g_ath[4096u * 1024u];             // attention out fp16
__device__ __half g_cxh[2048u * 1024u];             // ctx fp16
__device__ __half g_mdh[4096u * 4096u];             // MLP mid fp16
__device__ __half g_qkv[4096u * 3072u];
__device__ __half g_q  [4096u * 1024u];
__device__ __half g_kv [2048u * 2048u];
__device__ float g_x1[4096u * 1024u];
__device__ float g_x2[4096u * 1024u];

// weight offsets (elements) — contiguous in launch order
#define OFF_QKV 0
#define OFF_OS  3145728
#define OFF_Q   4194304
#define OFF_KV  5242880
#define OFF_OC  7340032
#define OFF_W1  8388608
#define OFF_W2  12582912
#define W_TOTAL 16777216

// ---------------- helpers ----------------
__device__ __forceinline__ uint32_t smem_u32(const void* p)
{
    uint32_t a;
    asm("{ .reg .u64 t; cvta.to.shared.u64 t, %1; cvt.u32.u64 %0, t; }" : "=r"(a) : "l"(p));
    return a;
}
__device__ __forceinline__ uint32_t packh2(float lo, float hi)
{
    __half2 h = __floats2half2_rn(lo, hi);
    return *reinterpret_cast<uint32_t*>(&h);
}
__device__ __forceinline__ void cp16(uint32_t s, const void* g)
{
    asm volatile("cp.async.cg.shared.global [%0], [%1], 16;" :: "r"(s), "l"(g));
}
__device__ __forceinline__ void cp_commit() { asm volatile("cp.async.commit_group;"); }

__device__ __forceinline__ void mma16816(float c[4], uint32_t a0, uint32_t a1,
                                         uint32_t a2, uint32_t a3,
                                         uint32_t b0, uint32_t b1)
{
    asm volatile("mma.sync.aligned.m16n8k16.row.col.f32.f16.f16.f32 "
                 "{%0,%1,%2,%3}, {%4,%5,%6,%7}, {%8,%9}, {%0,%1,%2,%3};"
                 : "+f"(c[0]), "+f"(c[1]), "+f"(c[2]), "+f"(c[3])
                 : "r"(a0), "r"(a1), "r"(a2), "r"(a3), "r"(b0), "r"(b1));
}
__device__ __forceinline__ void ldsm4_a(uint32_t* r, uint32_t a)
{
    asm volatile("ldmatrix.sync.aligned.m8n8.x4.shared.b16 {%0,%1,%2,%3}, [%4];"
                 : "=r"(r[0]), "=r"(r[1]), "=r"(r[2]), "=r"(r[3]) : "r"(a));
}
__device__ __forceinline__ void ldsm4t_a(uint32_t* r, uint32_t a)
{
    asm volatile("ldmatrix.sync.aligned.m8n8.x4.trans.shared.b16 {%0,%1,%2,%3}, [%4];"
                 : "=r"(r[0]), "=r"(r[1]), "=r"(r[2]), "=r"(r[3]) : "r"(a));
}

// ---------------- LayerNorm -> fp16 ----------------
__global__ __launch_bounds__(256) void ln_kernel(const float* __restrict__ x,
                                                 __half* __restrict__ hi)
{
    long long base = (long long)blockIdx.x * 1024;
    float v4[4];
    float s = 0.f, ss = 0.f;
#pragma unroll
    for (int i = 0; i < 4; i++) {
        v4[i] = x[base + threadIdx.x + i * 256];
        s += v4[i]; ss += v4[i] * v4[i];
    }
    __shared__ float shs[32], shq[32];
    for (int o = 16; o; o >>= 1) {
        s  += __shfl_xor_sync(0xffffffffu, s,  o);
        ss += __shfl_xor_sync(0xffffffffu, ss, o);
    }
    int w = threadIdx.x >> 5, l = threadIdx.x & 31;
    if (l == 0) { shs[w] = s; shq[w] = ss; }
    __syncthreads();
    if (w == 0) {
        float a = (l < 8) ? shs[l] : 0.f;
        float b = (l < 8) ? shq[l] : 0.f;
        for (int o = 4; o; o >>= 1) {
            a += __shfl_xor_sync(0xffffffffu, a, o);
            b += __shfl_xor_sync(0xffffffffu, b, o);
        }
        if (l == 0) { shs[0] = a; shq[0] = b; }
    }
    __syncthreads();
    float mean = shs[0] * (1.0f / 1024.0f);
    float var  = shq[0] * (1.0f / 1024.0f) - mean * mean;
    float inv  = rsqrtf(var + 1e-6f);
#pragma unroll
    for (int i = 0; i < 4; i++)
        hi[base + threadIdx.x + i * 256] = __float2half_rn((v4[i] - mean) * inv);
}

// ---------------- batched weight convert: 7 fp32 sources -> contiguous fp16 ----------------
__global__ __launch_bounds__(256) void wsplit_all_kernel(
    const float* __restrict__ s0, const float* __restrict__ s1,
    const float* __restrict__ s2, const float* __restrict__ s3,
    const float* __restrict__ s4, const float* __restrict__ s5,
    const float* __restrict__ s6,
    __half* __restrict__ hi)
{
    long long e = ((long long)blockIdx.x * 256 + threadIdx.x) * 4;
    const float* src;
    long long off;
    if      (e < OFF_OS)  { src = s0; off = 0; }
    else if (e < OFF_Q)   { src = s1; off = OFF_OS; }
    else if (e < OFF_KV)  { src = s2; off = OFF_Q; }
    else if (e < OFF_OC)  { src = s3; off = OFF_KV; }
    else if (e < OFF_W1)  { src = s4; off = OFF_OC; }
    else if (e < OFF_W2)  { src = s5; off = OFF_W1; }
    else                  { src = s6; off = OFF_W2; }
    float4 v = *reinterpret_cast<const float4*>(&src[e - off]);
    uint2 uh;
    uh.x = packh2(v.x, v.y);
    uh.y = packh2(v.z, v.w);
    *reinterpret_cast<uint2*>(&hi[e]) = uh;
}

// ---------------- fp32 -> fp16 convert (ctx) ----------------
__global__ __launch_bounds__(256) void conv_kernel(const float* __restrict__ x,
                                                   __half* __restrict__ hi)
{
    long long i = ((long long)blockIdx.x * 256 + threadIdx.x) * 4;
    float4 v = *reinterpret_cast<const float4*>(&x[i]);
    uint2 uh;
    uh.x = packh2(v.x, v.y);
    uh.y = packh2(v.z, v.w);
    *reinterpret_cast<uint2*>(&hi[i]) = uh;
}

// ---------------- fp16 single-term GEMM, 64x64 warp tiles ----------------
// C[M,N] = A @ B.  Block tile 128x128, BK=32, 3-stage cp.async,
// 128 threads (4 warps, 2x2), warp tile 64x64, 2 CTAs/SM.
// MODE 0: fp32 out = acc+bias+res; 1: fp16 out = acc+bias; 2: fp16 out = gelu(acc+bias).
template <int MODE>
__global__ __launch_bounds__(128, 2) void gemm_f16(
    const __half* __restrict__ Ah, const __half* __restrict__ Bh,
    const float* __restrict__ bias, const float* __restrict__ res,
    void* __restrict__ out, int K, int N)
{
    // per-stage smem (bytes):
    //   A: 128 rows x pitch 40 fp16 -> 10240
    //   B:  32 rows x pitch 136 fp16 -> 8704
    constexpr int STAGE = 18944;
    constexpr int BOFF  = 10240;
    extern __shared__ __align__(16) char smem[];
    const uint32_t sbase = smem_u32(smem);

    const int tid = threadIdx.x;
    const int w = tid >> 5, lane = tid & 31;
    const int grp = lane >> 3, lrow8 = lane & 7;
    const int wr = w >> 1, wc = w & 1;              // 2x2 warps; warp tile 64x64
    const int rbase = wr * 64, cbase = wc * 64;

    const __half* Abh = Ah + (long long)blockIdx.y * 128 * K;
    const __half* Bbh = Bh + blockIdx.x * 128;

    auto load_stage = [&](int kt, int s) {
        uint32_t sb = sbase + s * STAGE;
#pragma unroll
        for (int j = 0; j < 4; j++) {               // A: 512 16B chunks
            int idx = tid + j * 128;
            int row = idx >> 2, c = idx & 3;
            const __half* g = Abh + (long long)row * K + kt * 32 + c * 8;
            cp16(sb + (row * 40 + c * 8) * 2, g);
        }
#pragma unroll
        for (int j = 0; j < 4; j++) {               // B: 512 16B chunks
            int idx = tid + j * 128;
            int row = idx >> 4, c = idx & 15;
            const __half* g = Bbh + (long long)(kt * 32 + row) * N + c * 8;
            cp16(sb + BOFF + (row * 136 + c * 8) * 2, g);
        }
        cp_commit();
    };

    float acc[4][8][4];
#pragma unroll
    for (int i = 0; i < 4; i++)
#pragma unroll
        for (int j = 0; j < 8; j++)
#pragma unroll
            for (int e = 0; e < 4; e++) acc[i][j][e] = 0.f;

    const int KT = K >> 5;
    load_stage(0, 0);
    load_stage(1, 1);

    for (int kt = 0; kt < KT; kt++) {
        if (kt + 1 < KT) asm volatile("cp.async.wait_group 1;" ::: "memory");
        else             asm volatile("cp.async.wait_group 0;" ::: "memory");
        __syncthreads();
        if (kt + 2 < KT) load_stage(kt + 2, (kt + 2) % 3);

        const uint32_t Ab = sbase + (kt % 3) * STAGE;
        const uint32_t Bb = Ab + BOFF;
#pragma unroll
        for (int kk = 0; kk < 32; kk += 16) {
            uint32_t ah[4][4];
#pragma unroll
            for (int i = 0; i < 4; i++) {
                uint32_t addr = Ab + ((rbase + i * 16 + (grp & 1) * 8 + lrow8) * 40 +
                                      kk + (grp & 2) * 4) * 2;
                ldsm4_a(ah[i], addr);
            }
            uint32_t bh[4][4];
#pragma unroll
            for (int j = 0; j < 4; j++) {
                uint32_t addr = Bb + ((kk + (grp & 1) * 8 + lrow8) * 136 +
                                      cbase + j * 16 + (grp & 2) * 4) * 2;
                ldsm4t_a(bh[j], addr);
            }
#pragma unroll
            for (int i = 0; i < 4; i++)
#pragma unroll
                for (int jj = 0; jj < 8; jj++) {
                    uint32_t b0 = bh[jj >> 1][(jj & 1) * 2], b1 = bh[jj >> 1][(jj & 1) * 2 + 1];
                    mma16816(acc[i][jj], ah[i][0], ah[i][1], ah[i][2], ah[i][3], b0, b1);
                }
        }
    }

    // ---- epilogue straight from registers ----
    const int tr = lane >> 2, tc = (lane & 3) * 2;
#pragma unroll
    for (int i = 0; i < 4; i++) {
        long long gr0 = (long long)blockIdx.y * 128 + rbase + i * 16 + tr;
#pragma unroll
        for (int jj = 0; jj < 8; jj++) {
            int gc = blockIdx.x * 128 + cbase + jj * 8 + tc;
            float b0 = bias[gc], b1 = bias[gc + 1];
            float v0 = acc[i][jj][0] + b0, v1 = acc[i][jj][1] + b1;
            float v2 = acc[i][jj][2] + b0, v3 = acc[i][jj][3] + b1;
            if (MODE == 0) {
                float* fo = (float*)out;
                float2 r0 = *reinterpret_cast<const float2*>(&res[gr0 * N + gc]);
                float2 r1 = *reinterpret_cast<const float2*>(&res[(gr0 + 8) * N + gc]);
                *reinterpret_cast<float2*>(&fo[gr0 * N + gc]) =
                    make_float2(v0 + r0.x, v1 + r0.y);
                *reinterpret_cast<float2*>(&fo[(gr0 + 8) * N + gc]) =
                    make_float2(v2 + r1.x, v3 + r1.y);
            } else if (MODE == 1) {
                __half* bo = (__half*)out;
                *reinterpret_cast<uint32_t*>(&bo[gr0 * N + gc])       = packh2(v0, v1);
                *reinterpret_cast<uint32_t*>(&bo[(gr0 + 8) * N + gc]) = packh2(v2, v3);
            } else {
                float g[4] = { v0, v1, v2, v3 };
#pragma unroll
                for (int e = 0; e < 4; e++) {
                    float xx = g[e];
                    float tt = 0.7978845608028654f * (xx + 0.044715f * xx * xx * xx);
                    g[e] = 0.5f * xx * (1.0f + tanhf(tt));
                }
                __half* ho = (__half*)out;
                *reinterpret_cast<uint32_t*>(&ho[gr0 * N + gc])       = packh2(g[0], g[1]);
                *reinterpret_cast<uint32_t*>(&ho[(gr0 + 8) * N + gc]) = packh2(g[2], g[3]);
            }
        }
    }
}

// ---------------- flash attention: fp16, 3-stage cp.async KV pipeline ----------------
__global__ __launch_bounds__(128) void flash_kernel(
    const __half* __restrict__ Qg, const __half* __restrict__ Kg,
    const __half* __restrict__ Vg, __half* __restrict__ Ohi,
    int sq, int skv, int nk)
{
    constexpr int PD = 72;
    constexpr int STG = 2 * 64 * PD * 2;       // 18432 bytes per stage
    constexpr int VOFF = 64 * PD * 2;
    extern __shared__ __align__(16) char fsmem[];
    const uint32_t sb = smem_u32(fsmem);

    const int tid = threadIdx.x;
    const int w = tid >> 5, t = tid & 31;
    const int bh = blockIdx.y;
    const int b = bh >> 4, h = bh & 15;

    const long long qrow0 = (long long)b * 2048 + (long long)blockIdx.x * 128;
    const __half* Qb = Qg + qrow0 * sq + h * 64;
    const __half* Kb = Kg + (long long)b * nk * skv + h * 64;
    const __half* Vb = Vg + (long long)b * nk * skv + h * 64;
    __half* Obh = Ohi + qrow0 * 1024 + h * 64;

    const int qr = w * 32;
    const int tr = t >> 2, tc = (t & 3) * 2;

    uint32_t qa[2][4][4];
#pragma unroll
    for (int mt = 0; mt < 2; mt++) {
        int r0 = qr + mt * 16 + tr;
#pragma unroll
        for (int kc = 0; kc < 4; kc++) {
            int c0 = kc * 16 + tc;
            qa[mt][kc][0] = *reinterpret_cast<const uint32_t*>(&Qb[(long long)r0 * sq + c0]);
            qa[mt][kc][1] = *reinterpret_cast<const uint32_t*>(&Qb[(long long)(r0 + 8) * sq + c0]);
            qa[mt][kc][2] = *reinterpret_cast<const uint32_t*>(&Qb[(long long)r0 * sq + c0 + 8]);
            qa[mt][kc][3] = *reinterpret_cast<const uint32_t*>(&Qb[(long long)(r0 + 8) * sq + c0 + 8]);
        }
    }

    auto load_kv = [&](int kb, int s) {
        uint32_t base = sb + s * STG;
#pragma unroll
        for (int j = 0; j < 8; j++) {
            int i = tid + j * 128;
            int half_ = i >> 9, within = i & 511;
            int r = within >> 3, c = within & 7;
            const __half* g = (half_ ? Vb : Kb) +
                              (long long)(kb * 64 + r) * skv + c * 8;
            cp16(base + half_ * VOFF + (r * PD + c * 8) * 2, g);
        }
        cp_commit();
    };

    float o[2][8][4];
    float mrow[2][2], lrow[2][2];
#pragma unroll
    for (int mt = 0; mt < 2; mt++) {
        mrow[mt][0] = mrow[mt][1] = -1e30f;
        lrow[mt][0] = lrow[mt][1] = 0.f;
#pragma unroll
        for (int nb = 0; nb < 8; nb++)
#pragma unroll
            for (int e = 0; e < 4; e++) o[mt][nb][e] = 0.f;
    }

    const float CSC = 0.18033688011112042f;     // (1/8)*log2(e)
    const int niter = nk >> 6;
    const int grp = t >> 3, lrow8 = t & 7;

    load_kv(0, 0);
    load_kv(1, 1);

    for (int kb = 0; kb < niter; kb++) {
        if (kb + 1 < niter) asm volatile("cp.async.wait_group 1;" ::: "memory");
        else                asm volatile("cp.async.wait_group 0;" ::: "memory");
        __syncthreads();
        if (kb + 2 < niter) load_kv(kb + 2, (kb + 2) % 3);

        const uint32_t Kbase = sb + (kb % 3) * STG;
        const uint32_t Vbase = Kbase + VOFF;

        float s[2][8][4];
#pragma unroll
        for (int mt = 0; mt < 2; mt++)
#pragma unroll
            for (int nb = 0; nb < 8; nb++)
#pragma unroll
                for (int e = 0; e < 4; e++) s[mt][nb][e] = 0.f;

#pragma unroll
        for (int kc = 0; kc < 4; kc++) {
#pragma unroll
            for (int nbp = 0; nbp < 4; nbp++) {
                uint32_t r[4];
                uint32_t addr = Kbase +
                    ((nbp * 16 + (grp & 2) * 4 + lrow8) * PD + kc * 16 + (grp & 1) * 8) * 2;
                ldsm4_a(r, addr);
#pragma unroll
                for (int mt = 0; mt < 2; mt++) {
                    mma16816(s[mt][2 * nbp],     qa[mt][kc][0], qa[mt][kc][1],
                             qa[mt][kc][2], qa[mt][kc][3], r[0], r[1]);
                    mma16816(s[mt][2 * nbp + 1], qa[mt][kc][0], qa[mt][kc][1],
                             qa[mt][kc][2], qa[mt][kc][3], r[2], r[3]);
                }
            }
        }

#pragma unroll
        for (int mt = 0; mt < 2; mt++) {
#pragma unroll
            for (int half_ = 0; half_ < 2; half_++) {
                int e0 = 2 * half_;
                float mx = -1e30f;
#pragma unroll
                for (int nb = 0; nb < 8; nb++)
                    mx = fmaxf(mx, fmaxf(s[mt][nb][e0], s[mt][nb][e0 + 1]));
                mx = fmaxf(mx, __shfl_xor_sync(0xffffffffu, mx, 1));
                mx = fmaxf(mx, __shfl_xor_sync(0xffffffffu, mx, 2));
                float newm = fmaxf(mrow[mt][half_], mx);
                float alpha = exp2f((mrow[mt][half_] - newm) * CSC);
                float sum = 0.f;
#pragma unroll
                for (int nb = 0; nb < 8; nb++) {
                    float p0 = exp2f((s[mt][nb][e0] - newm) * CSC);
                    float p1 = exp2f((s[mt][nb][e0 + 1] - newm) * CSC);
                    s[mt][nb][e0] = p0; s[mt][nb][e0 + 1] = p1;
                    sum += p0 + p1;
                }
                sum += __shfl_xor_sync(0xffffffffu, sum, 1);
                sum += __shfl_xor_sync(0xffffffffu, sum, 2);
                lrow[mt][half_] = lrow[mt][half_] * alpha + sum;
                mrow[mt][half_] = newm;
#pragma unroll
                for (int nb = 0; nb < 8; nb++) {
                    o[mt][nb][e0]     *= alpha;
                    o[mt][nb][e0 + 1] *= alpha;
                }
            }
        }

#pragma unroll
        for (int kcP = 0; kcP < 4; kcP++) {
            uint32_t pa[2][4];
#pragma unroll
            for (int mt = 0; mt < 2; mt++) {
                pa[mt][0] = packh2(s[mt][2 * kcP][0],     s[mt][2 * kcP][1]);
                pa[mt][1] = packh2(s[mt][2 * kcP][2],     s[mt][2 * kcP][3]);
                pa[mt][2] = packh2(s[mt][2 * kcP + 1][0], s[mt][2 * kcP + 1][1]);
                pa[mt][3] = packh2(s[mt][2 * kcP + 1][2], s[mt][2 * kcP + 1][3]);
            }
#pragma unroll
            for (int nbp = 0; nbp < 4; nbp++) {
                uint32_t r[4];
                uint32_t addr = Vbase +
                    ((kcP * 16 + (grp & 1) * 8 + lrow8) * PD + nbp * 16 + (grp & 2) * 4) * 2;
                ldsm4t_a(r, addr);
#pragma unroll
                for (int mt = 0; mt < 2; mt++) {
                    mma16816(o[mt][2 * nbp],     pa[mt][0], pa[mt][1], pa[mt][2], pa[mt][3],
                             r[0], r[1]);
                    mma16816(o[mt][2 * nbp + 1], pa[mt][0], pa[mt][1], pa[mt][2], pa[mt][3],
                             r[2], r[3]);
                }
            }
        }
    }

#pragma unroll
    for (int mt = 0; mt < 2; mt++) {
        int r0 = qr + mt * 16 + tr;
        float inv0 = 1.0f / lrow[mt][0];
        float inv1 = 1.0f / lrow[mt][1];
#pragma unroll
        for (int nb = 0; nb < 8; nb++) {
            int col = nb * 8 + tc;
            *reinterpret_cast<uint32_t*>(&Obh[(long long)r0 * 1024 + col]) =
                packh2(o[mt][nb][0] * inv0, o[mt][nb][1] * inv0);
            *reinterpret_cast<uint32_t*>(&Obh[(long long)(r0 + 8) * 1024 + col]) =
                packh2(o[mt][nb][2] * inv1, o[mt][nb][3] * inv1);
        }
    }
}

// ---------------- host ----------------
static void* devptr(const void* symbol)
{
    void* p = nullptr;
    cudaGetSymbolAddress(&p, symbol);
    return p;
}

extern "C" void kernel_launch(void* const* d_in, const int* in_sizes, int n_in,
                              void* d_out, int out_size)
{
    const float* x    = (const float*)d_in[0];
    const float* ctx  = (const float*)d_in[1];
    const float* Wqkv = (const float*)d_in[2];
    const float* bqkv = (const float*)d_in[3];
    const float* Wos  = (const float*)d_in[4];
    const float* bos  = (const float*)d_in[5];
    const float* Wq   = (const float*)d_in[6];
    const float* bq   = (const float*)d_in[7];
    const float* Wkv  = (const float*)d_in[8];
    const float* bkv  = (const float*)d_in[9];
    const float* Woc  = (const float*)d_in[10];
    const float* boc  = (const float*)d_in[11];
    const float* W1   = (const float*)d_in[12];
    const float* b1   = (const float*)d_in[13];
    const float* W2   = (const float*)d_in[14];
    const float* b2   = (const float*)d_in[15];
    float* out = (float*)d_out;

    __half* wh  = (__half*)devptr(g_w_hi);
    __half* lnh = (__half*)devptr(g_lnh);
    __half* ath = (__half*)devptr(g_ath);
    __half* cxh = (__half*)devptr(g_cxh);
    __half* mdh = (__half*)devptr(g_mdh);
    __half* qkv = (__half*)devptr(g_qkv);
    __half* q   = (__half*)devptr(g_q);
    __half* kv  = (__half*)devptr(g_kv);
    float* x1 = (float*)devptr(g_x1);
    float* x2 = (float*)devptr(g_x2);

    const int SMEM  = 3 * 18944;   // gemm: 56832 bytes (2 CTAs/SM)
    const int FSMEM = 3 * 18432;   // flash: 55296 bytes
    cudaFuncSetAttribute(gemm_f16<0>, cudaFuncAttributeMaxDynamicSharedMemorySize, SMEM);
    cudaFuncSetAttribute(gemm_f16<1>, cudaFuncAttributeMaxDynamicSharedMemorySize, SMEM);
    cudaFuncSetAttribute(gemm_f16<2>, cudaFuncAttributeMaxDynamicSharedMemorySize, SMEM);
    cudaFuncSetAttribute(flash_kernel, cudaFuncAttributeMaxDynamicSharedMemorySize, FSMEM);

    // ---- conversions ----
    wsplit_all_kernel<<<W_TOTAL / 1024, 256>>>(Wqkv, Wos, Wq, Wkv, Woc, W1, W2, wh);
    conv_kernel<<<2097152 / 1024, 256>>>(ctx, cxh);

    // ---- self-attention ----
    ln_kernel<<<4096, 256>>>(x, lnh);
    gemm_f16<1><<<dim3(24, 32), 128, SMEM>>>(lnh, wh + OFF_QKV,
                                             bqkv, nullptr, qkv, 1024, 3072);
    flash_kernel<<<dim3(16, 32), 128, FSMEM>>>(qkv, qkv + 1024, qkv + 2048, ath,
                                               3072, 3072, 2048);
    gemm_f16<0><<<dim3(8, 32), 128, SMEM>>>(ath, wh + OFF_OS,
                                            bos, x, x1, 1024, 1024);

    // ---- cross-attention ----
    ln_kernel<<<4096, 256>>>(x1, lnh);
    gemm_f16<1><<<dim3(8, 32), 128, SMEM>>>(lnh, wh + OFF_Q,
                                            bq, nullptr, q, 1024, 1024);
    gemm_f16<1><<<dim3(16, 16), 128, SMEM>>>(cxh, wh + OFF_KV,
                                             bkv, nullptr, kv, 1024, 2048);
    flash_kernel<<<dim3(16, 32), 128, FSMEM>>>(q, kv, kv + 1024, ath,
                                               1024, 2048, 1024);
    gemm_f16<0><<<dim3(8, 32), 128, SMEM>>>(ath, wh + OFF_OC,
                                            boc, x1, x2, 1024, 1024);

    // ---- MLP ----
    ln_kernel<<<4096, 256>>>(x2, lnh);
    gemm_f16<2><<<dim3(32, 32), 128, SMEM>>>(lnh, wh + OFF_W1,
                                             b1, nullptr, mdh, 1024, 4096);
    gemm_f16<0><<<dim3(8, 32), 128, SMEM>>>(mdh, wh + OFF_W2,
                                            b2, x2, out, 4096, 1024);
}

// round 17
// speedup vs baseline: 3.4115x; 1.0025x over previous
#include <cuda_runtime.h>
#include <cuda_fp16.h>
#include <cstdint>

// Dims: B=2, N=2048, M=1024, C=1024, H=16, D=64, HID=4096
// TQ = 4096 (B*N), TKV = 2048 (B*M)

// ---------------- scratch ----------------
__device__ __half g_w_hi[16777216];                 // weights fp16 (B operand)
__device__ __half g_lnh[4096u * 1024u];             // LN out fp16
__device__ __half g_ath[4096u * 1024u];             // attention out fp16
__device__ __half g_cxh[2048u * 1024u];             // ctx fp16
__device__ __half g_mdh[4096u * 4096u];             // MLP mid fp16
__device__ __half g_qkv[4096u * 3072u];
__device__ __half g_q  [4096u * 1024u];
__device__ __half g_kv [2048u * 2048u];
__device__ float g_x1[4096u * 1024u];
__device__ float g_x2[4096u * 1024u];

// weight offsets (elements) — contiguous in launch order
#define OFF_QKV 0
#define OFF_OS  3145728
#define OFF_Q   4194304
#define OFF_KV  5242880
#define OFF_OC  7340032
#define OFF_W1  8388608
#define OFF_W2  12582912
#define W_TOTAL 16777216

// ---------------- helpers ----------------
__device__ __forceinline__ uint32_t smem_u32(const void* p)
{
    uint32_t a;
    asm("{ .reg .u64 t; cvta.to.shared.u64 t, %1; cvt.u32.u64 %0, t; }" : "=r"(a) : "l"(p));
    return a;
}
__device__ __forceinline__ uint32_t packh2(float lo, float hi)
{
    __half2 h = __floats2half2_rn(lo, hi);
    return *reinterpret_cast<uint32_t*>(&h);
}
__device__ __forceinline__ void cp16(uint32_t s, const void* g)
{
    asm volatile("cp.async.cg.shared.global [%0], [%1], 16;" :: "r"(s), "l"(g));
}
__device__ __forceinline__ void cp_commit() { asm volatile("cp.async.commit_group;"); }

__device__ __forceinline__ void mma16816(float c[4], uint32_t a0, uint32_t a1,
                                         uint32_t a2, uint32_t a3,
                                         uint32_t b0, uint32_t b1)
{
    asm volatile("mma.sync.aligned.m16n8k16.row.col.f32.f16.f16.f32 "
                 "{%0,%1,%2,%3}, {%4,%5,%6,%7}, {%8,%9}, {%0,%1,%2,%3};"
                 : "+f"(c[0]), "+f"(c[1]), "+f"(c[2]), "+f"(c[3])
                 : "r"(a0), "r"(a1), "r"(a2), "r"(a3), "r"(b0), "r"(b1));
}
__device__ __forceinline__ void ldsm4_a(uint32_t* r, uint32_t a)
{
    asm volatile("ldmatrix.sync.aligned.m8n8.x4.shared.b16 {%0,%1,%2,%3}, [%4];"
                 : "=r"(r[0]), "=r"(r[1]), "=r"(r[2]), "=r"(r[3]) : "r"(a));
}
__device__ __forceinline__ void ldsm4t_a(uint32_t* r, uint32_t a)
{
    asm volatile("ldmatrix.sync.aligned.m8n8.x4.trans.shared.b16 {%0,%1,%2,%3}, [%4];"
                 : "=r"(r[0]), "=r"(r[1]), "=r"(r[2]), "=r"(r[3]) : "r"(a));
}

// ---------------- LayerNorm -> fp16 ----------------
__global__ __launch_bounds__(256) void ln_kernel(const float* __restrict__ x,
                                                 __half* __restrict__ hi)
{
    long long base = (long long)blockIdx.x * 1024;
    float v4[4];
    float s = 0.f, ss = 0.f;
#pragma unroll
    for (int i = 0; i < 4; i++) {
        v4[i] = x[base + threadIdx.x + i * 256];
        s += v4[i]; ss += v4[i] * v4[i];
    }
    __shared__ float shs[32], shq[32];
    for (int o = 16; o; o >>= 1) {
        s  += __shfl_xor_sync(0xffffffffu, s,  o);
        ss += __shfl_xor_sync(0xffffffffu, ss, o);
    }
    int w = threadIdx.x >> 5, l = threadIdx.x & 31;
    if (l == 0) { shs[w] = s; shq[w] = ss; }
    __syncthreads();
    if (w == 0) {
        float a = (l < 8) ? shs[l] : 0.f;
        float b = (l < 8) ? shq[l] : 0.f;
        for (int o = 4; o; o >>= 1) {
            a += __shfl_xor_sync(0xffffffffu, a, o);
            b += __shfl_xor_sync(0xffffffffu, b, o);
        }
        if (l == 0) { shs[0] = a; shq[0] = b; }
    }
    __syncthreads();
    float mean = shs[0] * (1.0f / 1024.0f);
    float var  = shq[0] * (1.0f / 1024.0f) - mean * mean;
    float inv  = rsqrtf(var + 1e-6f);
#pragma unroll
    for (int i = 0; i < 4; i++)
        hi[base + threadIdx.x + i * 256] = __float2half_rn((v4[i] - mean) * inv);
}

// ---------------- batched weight convert: 7 fp32 sources -> contiguous fp16 ----------------
__global__ __launch_bounds__(256) void wsplit_all_kernel(
    const float* __restrict__ s0, const float* __restrict__ s1,
    const float* __restrict__ s2, const float* __restrict__ s3,
    const float* __restrict__ s4, const float* __restrict__ s5,
    const float* __restrict__ s6,
    __half* __restrict__ hi)
{
    long long e = ((long long)blockIdx.x * 256 + threadIdx.x) * 4;
    const float* src;
    long long off;
    if      (e < OFF_OS)  { src = s0; off = 0; }
    else if (e < OFF_Q)   { src = s1; off = OFF_OS; }
    else if (e < OFF_KV)  { src = s2; off = OFF_Q; }
    else if (e < OFF_OC)  { src = s3; off = OFF_KV; }
    else if (e < OFF_W1)  { src = s4; off = OFF_OC; }
    else if (e < OFF_W2)  { src = s5; off = OFF_W1; }
    else                  { src = s6; off = OFF_W2; }
    float4 v = *reinterpret_cast<const float4*>(&src[e - off]);
    uint2 uh;
    uh.x = packh2(v.x, v.y);
    uh.y = packh2(v.z, v.w);
    *reinterpret_cast<uint2*>(&hi[e]) = uh;
}

// ---------------- fp32 -> fp16 convert (ctx) ----------------
__global__ __launch_bounds__(256) void conv_kernel(const float* __restrict__ x,
                                                   __half* __restrict__ hi)
{
    long long i = ((long long)blockIdx.x * 256 + threadIdx.x) * 4;
    float4 v = *reinterpret_cast<const float4*>(&x[i]);
    uint2 uh;
    uh.x = packh2(v.x, v.y);
    uh.y = packh2(v.z, v.w);
    *reinterpret_cast<uint2*>(&hi[i]) = uh;
}

// ---------------- fp16 single-term GEMM, BK=64, 64x64 warp tiles ----------------
// C[M,N] = A @ B.  Block tile 128x128, BK=64, 3-stage cp.async,
// 128 threads (4 warps, 2x2), warp tile 64x64, 2 CTAs/SM.
// MODE 0: fp32 out = acc+bias+res; 1: fp16 out = acc+bias; 2: fp16 out = gelu(acc+bias).
template <int MODE>
__global__ __launch_bounds__(128, 2) void gemm_f16(
    const __half* __restrict__ Ah, const __half* __restrict__ Bh,
    const float* __restrict__ bias, const float* __restrict__ res,
    void* __restrict__ out, int K, int N)
{
    // per-stage smem (bytes):
    //   A: 128 rows x pitch 72 fp16 -> 18432
    //   B:  64 rows x pitch 136 fp16 -> 17408
    constexpr int STAGE = 35840;
    constexpr int BOFF  = 18432;
    extern __shared__ __align__(16) char smem[];
    const uint32_t sbase = smem_u32(smem);

    const int tid = threadIdx.x;
    const int w = tid >> 5, lane = tid & 31;
    const int grp = lane >> 3, lrow8 = lane & 7;
    const int wr = w >> 1, wc = w & 1;              // 2x2 warps; warp tile 64x64
    const int rbase = wr * 64, cbase = wc * 64;

    const __half* Abh = Ah + (long long)blockIdx.y * 128 * K;
    const __half* Bbh = Bh + blockIdx.x * 128;

    auto load_stage = [&](int kt, int s) {
        uint32_t sb = sbase + s * STAGE;
#pragma unroll
        for (int j = 0; j < 8; j++) {               // A: 1024 16B chunks
            int idx = tid + j * 128;
            int row = idx >> 3, c = idx & 7;
            const __half* g = Abh + (long long)row * K + kt * 64 + c * 8;
            cp16(sb + (row * 72 + c * 8) * 2, g);
        }
#pragma unroll
        for (int j = 0; j < 8; j++) {               // B: 1024 16B chunks
            int idx = tid + j * 128;
            int row = idx >> 4, c = idx & 15;
            const __half* g = Bbh + (long long)(kt * 64 + row) * N + c * 8;
            cp16(sb + BOFF + (row * 136 + c * 8) * 2, g);
        }
        cp_commit();
    };

    float acc[4][8][4];
#pragma unroll
    for (int i = 0; i < 4; i++)
#pragma unroll
        for (int j = 0; j < 8; j++)
#pragma unroll
            for (int e = 0; e < 4; e++) acc[i][j][e] = 0.f;

    const int KT = K >> 6;
    load_stage(0, 0);
    load_stage(1, 1);

    for (int kt = 0; kt < KT; kt++) {
        if (kt + 1 < KT) asm volatile("cp.async.wait_group 1;" ::: "memory");
        else             asm volatile("cp.async.wait_group 0;" ::: "memory");
        __syncthreads();
        if (kt + 2 < KT) load_stage(kt + 2, (kt + 2) % 3);

        const uint32_t Ab = sbase + (kt % 3) * STAGE;
        const uint32_t Bb = Ab + BOFF;
#pragma unroll
        for (int kk = 0; kk < 64; kk += 16) {
            uint32_t ah[4][4];
#pragma unroll
            for (int i = 0; i < 4; i++) {
                uint32_t addr = Ab + ((rbase + i * 16 + (grp & 1) * 8 + lrow8) * 72 +
                                      kk + (grp & 2) * 4) * 2;
                ldsm4_a(ah[i], addr);
            }
            uint32_t bh[4][4];
#pragma unroll
            for (int j = 0; j < 4; j++) {
                uint32_t addr = Bb + ((kk + (grp & 1) * 8 + lrow8) * 136 +
                                      cbase + j * 16 + (grp & 2) * 4) * 2;
                ldsm4t_a(bh[j], addr);
            }
#pragma unroll
            for (int i = 0; i < 4; i++)
#pragma unroll
                for (int jj = 0; jj < 8; jj++) {
                    uint32_t b0 = bh[jj >> 1][(jj & 1) * 2], b1 = bh[jj >> 1][(jj & 1) * 2 + 1];
                    mma16816(acc[i][jj], ah[i][0], ah[i][1], ah[i][2], ah[i][3], b0, b1);
                }
        }
    }

    // ---- epilogue straight from registers ----
    const int tr = lane >> 2, tc = (lane & 3) * 2;
#pragma unroll
    for (int i = 0; i < 4; i++) {
        long long gr0 = (long long)blockIdx.y * 128 + rbase + i * 16 + tr;
#pragma unroll
        for (int jj = 0; jj < 8; jj++) {
            int gc = blockIdx.x * 128 + cbase + jj * 8 + tc;
            float b0 = bias[gc], b1 = bias[gc + 1];
            float v0 = acc[i][jj][0] + b0, v1 = acc[i][jj][1] + b1;
            float v2 = acc[i][jj][2] + b0, v3 = acc[i][jj][3] + b1;
            if (MODE == 0) {
                float* fo = (float*)out;
                float2 r0 = *reinterpret_cast<const float2*>(&res[gr0 * N + gc]);
                float2 r1 = *reinterpret_cast<const float2*>(&res[(gr0 + 8) * N + gc]);
                *reinterpret_cast<float2*>(&fo[gr0 * N + gc]) =
                    make_float2(v0 + r0.x, v1 + r0.y);
                *reinterpret_cast<float2*>(&fo[(gr0 + 8) * N + gc]) =
                    make_float2(v2 + r1.x, v3 + r1.y);
            } else if (MODE == 1) {
                __half* bo = (__half*)out;
                *reinterpret_cast<uint32_t*>(&bo[gr0 * N + gc])       = packh2(v0, v1);
                *reinterpret_cast<uint32_t*>(&bo[(gr0 + 8) * N + gc]) = packh2(v2, v3);
            } else {
                float g[4] = { v0, v1, v2, v3 };
#pragma unroll
                for (int e = 0; e < 4; e++) {
                    float xx = g[e];
                    float tt = 0.7978845608028654f * (xx + 0.044715f * xx * xx * xx);
                    g[e] = 0.5f * xx * (1.0f + tanhf(tt));
                }
                __half* ho = (__half*)out;
                *reinterpret_cast<uint32_t*>(&ho[gr0 * N + gc])       = packh2(g[0], g[1]);
                *reinterpret_cast<uint32_t*>(&ho[(gr0 + 8) * N + gc]) = packh2(g[2], g[3]);
            }
        }
    }
}

// ---------------- flash attention: fp16, 3-stage cp.async KV pipeline ----------------
__global__ __launch_bounds__(128) void flash_kernel(
    const __half* __restrict__ Qg, const __half* __restrict__ Kg,
    const __half* __restrict__ Vg, __half* __restrict__ Ohi,
    int sq, int skv, int nk)
{
    constexpr int PD = 72;
    constexpr int STG = 2 * 64 * PD * 2;       // 18432 bytes per stage
    constexpr int VOFF = 64 * PD * 2;
    extern __shared__ __align__(16) char fsmem[];
    const uint32_t sb = smem_u32(fsmem);

    const int tid = threadIdx.x;
    const int w = tid >> 5, t = tid & 31;
    const int bh = blockIdx.y;
    const int b = bh >> 4, h = bh & 15;

    const long long qrow0 = (long long)b * 2048 + (long long)blockIdx.x * 128;
    const __half* Qb = Qg + qrow0 * sq + h * 64;
    const __half* Kb = Kg + (long long)b * nk * skv + h * 64;
    const __half* Vb = Vg + (long long)b * nk * skv + h * 64;
    __half* Obh = Ohi + qrow0 * 1024 + h * 64;

    const int qr = w * 32;
    const int tr = t >> 2, tc = (t & 3) * 2;

    uint32_t qa[2][4][4];
#pragma unroll
    for (int mt = 0; mt < 2; mt++) {
        int r0 = qr + mt * 16 + tr;
#pragma unroll
        for (int kc = 0; kc < 4; kc++) {
            int c0 = kc * 16 + tc;
            qa[mt][kc][0] = *reinterpret_cast<const uint32_t*>(&Qb[(long long)r0 * sq + c0]);
            qa[mt][kc][1] = *reinterpret_cast<const uint32_t*>(&Qb[(long long)(r0 + 8) * sq + c0]);
            qa[mt][kc][2] = *reinterpret_cast<const uint32_t*>(&Qb[(long long)r0 * sq + c0 + 8]);
            qa[mt][kc][3] = *reinterpret_cast<const uint32_t*>(&Qb[(long long)(r0 + 8) * sq + c0 + 8]);
        }
    }

    auto load_kv = [&](int kb, int s) {
        uint32_t base = sb + s * STG;
#pragma unroll
        for (int j = 0; j < 8; j++) {
            int i = tid + j * 128;
            int half_ = i >> 9, within = i & 511;
            int r = within >> 3, c = within & 7;
            const __half* g = (half_ ? Vb : Kb) +
                              (long long)(kb * 64 + r) * skv + c * 8;
            cp16(base + half_ * VOFF + (r * PD + c * 8) * 2, g);
        }
        cp_commit();
    };

    float o[2][8][4];
    float mrow[2][2], lrow[2][2];
#pragma unroll
    for (int mt = 0; mt < 2; mt++) {
        mrow[mt][0] = mrow[mt][1] = -1e30f;
        lrow[mt][0] = lrow[mt][1] = 0.f;
#pragma unroll
        for (int nb = 0; nb < 8; nb++)
#pragma unroll
            for (int e = 0; e < 4; e++) o[mt][nb][e] = 0.f;
    }

    const float CSC = 0.18033688011112042f;     // (1/8)*log2(e)
    const int niter = nk >> 6;
    const int grp = t >> 3, lrow8 = t & 7;

    load_kv(0, 0);
    load_kv(1, 1);

    for (int kb = 0; kb < niter; kb++) {
        if (kb + 1 < niter) asm volatile("cp.async.wait_group 1;" ::: "memory");
        else                asm volatile("cp.async.wait_group 0;" ::: "memory");
        __syncthreads();
        if (kb + 2 < niter) load_kv(kb + 2, (kb + 2) % 3);

        const uint32_t Kbase = sb + (kb % 3) * STG;
        const uint32_t Vbase = Kbase + VOFF;

        float s[2][8][4];
#pragma unroll
        for (int mt = 0; mt < 2; mt++)
#pragma unroll
            for (int nb = 0; nb < 8; nb++)
#pragma unroll
                for (int e = 0; e < 4; e++) s[mt][nb][e] = 0.f;

#pragma unroll
        for (int kc = 0; kc < 4; kc++) {
#pragma unroll
            for (int nbp = 0; nbp < 4; nbp++) {
                uint32_t r[4];
                uint32_t addr = Kbase +
                    ((nbp * 16 + (grp & 2) * 4 + lrow8) * PD + kc * 16 + (grp & 1) * 8) * 2;
                ldsm4_a(r, addr);
#pragma unroll
                for (int mt = 0; mt < 2; mt++) {
                    mma16816(s[mt][2 * nbp],     qa[mt][kc][0], qa[mt][kc][1],
                             qa[mt][kc][2], qa[mt][kc][3], r[0], r[1]);
                    mma16816(s[mt][2 * nbp + 1], qa[mt][kc][0], qa[mt][kc][1],
                             qa[mt][kc][2], qa[mt][kc][3], r[2], r[3]);
                }
            }
        }

#pragma unroll
        for (int mt = 0; mt < 2; mt++) {
#pragma unroll
            for (int half_ = 0; half_ < 2; half_++) {
                int e0 = 2 * half_;
                float mx = -1e30f;
#pragma unroll
                for (int nb = 0; nb < 8; nb++)
                    mx = fmaxf(mx, fmaxf(s[mt][nb][e0], s[mt][nb][e0 + 1]));
                mx = fmaxf(mx, __shfl_xor_sync(0xffffffffu, mx, 1));
                mx = fmaxf(mx, __shfl_xor_sync(0xffffffffu, mx, 2));
                float newm = fmaxf(mrow[mt][half_], mx);
                float alpha = exp2f((mrow[mt][half_] - newm) * CSC);
                float sum = 0.f;
#pragma unroll
                for (int nb = 0; nb < 8; nb++) {
                    float p0 = exp2f((s[mt][nb][e0] - newm) * CSC);
                    float p1 = exp2f((s[mt][nb][e0 + 1] - newm) * CSC);
                    s[mt][nb][e0] = p0; s[mt][nb][e0 + 1] = p1;
                    sum += p0 + p1;
                }
                sum += __shfl_xor_sync(0xffffffffu, sum, 1);
                sum += __shfl_xor_sync(0xffffffffu, sum, 2);
                lrow[mt][half_] = lrow[mt][half_] * alpha + sum;
                mrow[mt][half_] = newm;
#pragma unroll
                for (int nb = 0; nb < 8; nb++) {
                    o[mt][nb][e0]     *= alpha;
                    o[mt][nb][e0 + 1] *= alpha;
                }
            }
        }

#pragma unroll
        for (int kcP = 0; kcP < 4; kcP++) {
            uint32_t pa[2][4];
#pragma unroll
            for (int mt = 0; mt < 2; mt++) {
                pa[mt][0] = packh2(s[mt][2 * kcP][0],     s[mt][2 * kcP][1]);
                pa[mt][1] = packh2(s[mt][2 * kcP][2],     s[mt][2 * kcP][3]);
                pa[mt][2] = packh2(s[mt][2 * kcP + 1][0], s[mt][2 * kcP + 1][1]);
                pa[mt][3] = packh2(s[mt][2 * kcP + 1][2], s[mt][2 * kcP + 1][3]);
            }
#pragma unroll
            for (int nbp = 0; nbp < 4; nbp++) {
                uint32_t r[4];
                uint32_t addr = Vbase +
                    ((kcP * 16 + (grp & 1) * 8 + lrow8) * PD + nbp * 16 + (grp & 2) * 4) * 2;
                ldsm4t_a(r, addr);
#pragma unroll
                for (int mt = 0; mt < 2; mt++) {
                    mma16816(o[mt][2 * nbp],     pa[mt][0], pa[mt][1], pa[mt][2], pa[mt][3],
                             r[0], r[1]);
                    mma16816(o[mt][2 * nbp + 1], pa[mt][0], pa[mt][1], pa[mt][2], pa[mt][3],
                             r[2], r[3]);
                }
            }
        }
    }

#pragma unroll
    for (int mt = 0; mt < 2; mt++) {
        int r0 = qr + mt * 16 + tr;
        float inv0 = 1.0f / lrow[mt][0];
        float inv1 = 1.0f / lrow[mt][1];
#pragma unroll
        for (int nb = 0; nb < 8; nb++) {
            int col = nb * 8 + tc;
            *reinterpret_cast<uint32_t*>(&Obh[(long long)r0 * 1024 + col]) =
                packh2(o[mt][nb][0] * inv0, o[mt][nb][1] * inv0);
            *reinterpret_cast<uint32_t*>(&Obh[(long long)(r0 + 8) * 1024 + col]) =
                packh2(o[mt][nb][2] * inv1, o[mt][nb][3] * inv1);
        }
    }
}

// ---------------- host ----------------
static void* devptr(const void* symbol)
{
    void* p = nullptr;
    cudaGetSymbolAddress(&p, symbol);
    return p;
}

extern "C" void kernel_launch(void* const* d_in, const int* in_sizes, int n_in,
                              void* d_out, int out_size)
{
    const float* x    = (const float*)d_in[0];
    const float* ctx  = (const float*)d_in[1];
    const float* Wqkv = (const float*)d_in[2];
    const float* bqkv = (const float*)d_in[3];
    const float* Wos  = (const float*)d_in[4];
    const float* bos  = (const float*)d_in[5];
    const float* Wq   = (const float*)d_in[6];
    const float* bq   = (const float*)d_in[7];
    const float* Wkv  = (const float*)d_in[8];
    const float* bkv  = (const float*)d_in[9];
    const float* Woc  = (const float*)d_in[10];
    const float* boc  = (const float*)d_in[11];
    const float* W1   = (const float*)d_in[12];
    const float* b1   = (const float*)d_in[13];
    const float* W2   = (const float*)d_in[14];
    const float* b2   = (const float*)d_in[15];
    float* out = (float*)d_out;

    __half* wh  = (__half*)devptr(g_w_hi);
    __half* lnh = (__half*)devptr(g_lnh);
    __half* ath = (__half*)devptr(g_ath);
    __half* cxh = (__half*)devptr(g_cxh);
    __half* mdh = (__half*)devptr(g_mdh);
    __half* qkv = (__half*)devptr(g_qkv);
    __half* q   = (__half*)devptr(g_q);
    __half* kv  = (__half*)devptr(g_kv);
    float* x1 = (float*)devptr(g_x1);
    float* x2 = (float*)devptr(g_x2);

    const int SMEM  = 3 * 35840;   // gemm: 107520 bytes (2 CTAs/SM)
    const int FSMEM = 3 * 18432;   // flash: 55296 bytes
    cudaFuncSetAttribute(gemm_f16<0>, cudaFuncAttributeMaxDynamicSharedMemorySize, SMEM);
    cudaFuncSetAttribute(gemm_f16<1>, cudaFuncAttributeMaxDynamicSharedMemorySize, SMEM);
    cudaFuncSetAttribute(gemm_f16<2>, cudaFuncAttributeMaxDynamicSharedMemorySize, SMEM);
    cudaFuncSetAttribute(flash_kernel, cudaFuncAttributeMaxDynamicSharedMemorySize, FSMEM);

    // ---- conversions ----
    wsplit_all_kernel<<<W_TOTAL / 1024, 256>>>(Wqkv, Wos, Wq, Wkv, Woc, W1, W2, wh);
    conv_kernel<<<2097152 / 1024, 256>>>(ctx, cxh);

    // ---- self-attention ----
    ln_kernel<<<4096, 256>>>(x, lnh);
    gemm_f16<1><<<dim3(24, 32), 128, SMEM>>>(lnh, wh + OFF_QKV,
                                             bqkv, nullptr, qkv, 1024, 3072);
    flash_kernel<<<dim3(16, 32), 128, FSMEM>>>(qkv, qkv + 1024, qkv + 2048, ath,
                                               3072, 3072, 2048);
    gemm_f16<0><<<dim3(8, 32), 128, SMEM>>>(ath, wh + OFF_OS,
                                            bos, x, x1, 1024, 1024);

    // ---- cross-attention ----
    ln_kernel<<<4096, 256>>>(x1, lnh);
    gemm_f16<1><<<dim3(8, 32), 128, SMEM>>>(lnh, wh + OFF_Q,
                                            bq, nullptr, q, 1024, 1024);
    gemm_f16<1><<<dim3(16, 16), 128, SMEM>>>(cxh, wh + OFF_KV,
                                             bkv, nullptr, kv, 1024, 2048);
    flash_kernel<<<dim3(16, 32), 128, FSMEM>>>(q, kv, kv + 1024, ath,
                                               1024, 2048, 1024);
    gemm_f16<0><<<dim3(8, 32), 128, SMEM>>>(ath, wh + OFF_OC,
                                            boc, x1, x2, 1024, 1024);

    // ---- MLP ----
    ln_kernel<<<4096, 256>>>(x2, lnh);
    gemm_f16<2><<<dim3(32, 32), 128, SMEM>>>(lnh, wh + OFF_W1,
                                             b1, nullptr, mdh, 1024, 4096);
    gemm_f16<0><<<dim3(8, 32), 128, SMEM>>>(mdh, wh + OFF_W2,
                                            b2, x2, out, 4096, 1024);
}